// round 8
// baseline (speedup 1.0000x reference)
#include <cuda_runtime.h>
#include <math.h>
#include <stdint.h>

#define BB  256
#define NN  1024
#define C1  101
#define DD  256
#define HH  16
#define NEGV (-1000000000.0f)
#define AS  104          // att row stride (floats)
#define WS  260          // w_sh row stride (floats); 16*WS = 4160
#define WROW (HH * WS)

__device__ __align__(16) float g_u[BB * HH * DD];     // u[b][h][d]
__device__ __align__(16) float g_w[BB * HH * DD];     // weighted ce per head
__device__ __align__(16) float g_tv[BB * DD];
__device__ __align__(16) float g_M2T[DD * DD];        // M2T[e][d] = sum_c Wks[d,c]*Wo[e,c]
__device__ __align__(16) float g_part[2 * BB * 4 * DD];
__device__ int g_cnt[2 * BB * 4];

__device__ __forceinline__ bool readb(const void* p, int idx, int mode) {
    if (mode == 0) return ((const unsigned char*)p)[idx] != 0;
    if (mode == 1) return ((const int*)p)[idx] != 0;
    return ((const float*)p)[idx] != 0.0f;
}

__device__ __forceinline__ float dot4(float4 a, float4 b) {
    return a.x * b.x + a.y * b.y + a.z * b.z + a.w * b.w;
}

__device__ __forceinline__ unsigned long long pack2(float x) {
    unsigned long long r;
    asm("mov.b64 %0, {%1, %1};" : "=l"(r) : "f"(x));
    return r;
}
__device__ __forceinline__ void fma2(unsigned long long& acc, unsigned long long a,
                                     unsigned long long b) {
    asm("fma.rn.f32x2 %0, %1, %2, %0;" : "+l"(acc) : "l"(a), "l"(b));
}
union U64F2 { unsigned long long u; float2 f; };

// bool-dtype probe on first 4KB of `mask`. Call from ALL threads (sync-or).
__device__ __forceinline__ int detect_mode(const void* m, int t) {
    int f32 = 0, u8 = 0;
    if (t < 256) {
        uint4 v = ((const uint4*)m)[t];
        unsigned w[4] = {v.x, v.y, v.z, v.w};
#pragma unroll
        for (int i = 0; i < 4; i++) {
            unsigned x = w[i];
            if (((x >> 24) & 0xffu) == 0x3fu || ((x >> 16) & 0xffu) == 0x3fu ||
                ((x >> 8) & 0xffu) == 0x3fu || (x & 0xffu) == 0x3fu) f32 = 1;
            if (x & 0xffffff00u) u8 = 1;
        }
    }
    int a = __syncthreads_or(f32);
    int b = __syncthreads_or(u8);
    return a ? 2 : (b ? 0 : 1);
}

// ---------------- Kernel 0: M2T[e][d] = sum_c Wks[d,c] * Wo[e,c] -------------
// grid (8,8): tile 32d x 32e, K=256. Rows of both matrices load coalesced.
__global__ void __launch_bounds__(256) k_prep(
    const float* __restrict__ Wks, const float* __restrict__ Wo)
{
    __shared__ __align__(16) float a_sh[32 * 260];  // Wks rows (d-tile), padded
    __shared__ __align__(16) float b_sh[32 * 260];  // Wo rows (e-tile), padded

    int tj = blockIdx.x;   // d tile
    int ti = blockIdx.y;   // e tile
    int t = threadIdx.x;

    // load 32 rows x 256 cols each (float4): 2048 float4 per matrix
    for (int i = t; i < 2048; i += 256) {
        int r = i >> 6, c4 = i & 63;
        float4 av = ((const float4*)(Wks + (size_t)(tj * 32 + r) * 256))[c4];
        float4 bv = ((const float4*)(Wo  + (size_t)(ti * 32 + r) * 256))[c4];
        *(float4*)(a_sh + r * 260 + c4 * 4) = av;
        *(float4*)(b_sh + r * 260 + c4 * 4) = bv;
    }
    __syncthreads();

    int el = t >> 3;          // 0..31 e-local
    int dl = (t & 7) * 4;     // d-local base (4 outputs)
    float acc0 = 0.f, acc1 = 0.f, acc2 = 0.f, acc3 = 0.f;
    const float* br = b_sh + el * 260;
    const float* a0 = a_sh + (dl + 0) * 260;
    const float* a1 = a_sh + (dl + 1) * 260;
    const float* a2 = a_sh + (dl + 2) * 260;
    const float* a3 = a_sh + (dl + 3) * 260;
#pragma unroll 8
    for (int c = 0; c < 256; c++) {
        float bv = br[c];
        acc0 += a0[c] * bv;
        acc1 += a1[c] * bv;
        acc2 += a2[c] * bv;
        acc3 += a3[c] * bv;
    }
    float4 r4 = make_float4(acc0, acc1, acc2, acc3);
    *(float4*)(g_M2T + (size_t)(ti * 32 + el) * 256 + tj * 32 + dl) = r4;
}

// ---------------- Kernel 1: node partial sums (1024 CTAs) --------------------
__global__ void __launch_bounds__(256) k_nodes_part(
    const float* __restrict__ node, const void* __restrict__ mask,
    const void* __restrict__ cmask)
{
    __shared__ unsigned char code[256];
    __shared__ float4 part[2][4][64];

    int q = blockIdx.x, b = blockIdx.y, t = threadIdx.x;
    int mode = detect_mode(mask, t);

    int gidx = b * NN + q * 256 + t;
    bool m  = readb(mask,  gidx, mode);
    bool mc = m | readb(cmask, gidx, mode);
    code[t] = (unsigned char)((m ? 1 : 0) | (mc ? 2 : 0));
    int c0 = __syncthreads_count(!m);
    int c1 = __syncthreads_count(!mc);

    int chunk = t >> 6, d4 = t & 63;
    const float4* np4 = (const float4*)(node + (size_t)b * NN * DD);
    float4 s0 = make_float4(0.f, 0.f, 0.f, 0.f), s1 = s0;
    int n0 = chunk * 64;
#pragma unroll 8
    for (int i = 0; i < 64; i++) {
        int n = n0 + i;
        float4 v = __ldcs(&np4[(size_t)(q * 256 + n) * 64 + d4]);
        unsigned char c = code[n];
        if (!(c & 1)) { s0.x += v.x; s0.y += v.y; s0.z += v.z; s0.w += v.w; }
        if (!(c & 2)) { s1.x += v.x; s1.y += v.y; s1.z += v.z; s1.w += v.w; }
    }
    part[0][chunk][d4] = s0;
    part[1][chunk][d4] = s1;
    __syncthreads();

    if (t < 128) {
        int which = t >> 6, d = t & 63;
        float4 r = make_float4(0.f, 0.f, 0.f, 0.f);
#pragma unroll
        for (int c = 0; c < 4; c++) {
            float4 a = part[which][c][d];
            r.x += a.x; r.y += a.y; r.z += a.z; r.w += a.w;
        }
        ((float4*)g_part)[((which * BB + b) * 4 + q) * 64 + d] = r;
    }
    if (t == 0) {
        g_cnt[(0 * BB + b) * 4 + q] = c0;
        g_cnt[(1 * BB + b) * 4 + q] = c1;
    }
}

// ---------------- Kernel 2: q + u (uv reduced inline from partials) ----------
__global__ void __launch_bounds__(256) k_qu(
    const float* __restrict__ cur, const float* __restrict__ depot,
    const float* __restrict__ Wq, const float* __restrict__ Wk)
{
    __shared__ __align__(16) float ctx_s[8][768];
    __shared__ __align__(16) float qp[8][8][32];
    __shared__ __align__(16) float q_s[8][32];
    __shared__ float den_s[8];

    int cx = blockIdx.x;     // 0..7 : 32-col slice = 2 heads
    int by = blockIdx.y;     // 0..31: 8 batches
    int t = threadIdx.x, lane = t & 31, w = t >> 5;

    if (t < 8) {
        int b = by * 8 + t;
        int c = g_cnt[b * 4 + 0] + g_cnt[b * 4 + 1] + g_cnt[b * 4 + 2] + g_cnt[b * 4 + 3];
        den_s[t] = fmaxf((float)c, 1.0f);
    }
    __syncthreads();

    for (int i = t; i < 8 * 256; i += 256) {
        int bi = i >> 8, d = i & 255;
        int b = by * 8 + bi;
        float s = g_part[(size_t)(b * 4 + 0) * 256 + d] + g_part[(size_t)(b * 4 + 1) * 256 + d]
                + g_part[(size_t)(b * 4 + 2) * 256 + d] + g_part[(size_t)(b * 4 + 3) * 256 + d];
        ctx_s[bi][d]       = s / den_s[bi];
        ctx_s[bi][256 + d] = cur[(size_t)b * DD + d];
        ctx_s[bi][512 + d] = depot[(size_t)b * DD + d];
    }
    __syncthreads();

    {
        int c = cx * 32 + lane;
        float acc[8];
#pragma unroll
        for (int bi = 0; bi < 8; bi++) acc[bi] = 0.f;
        int k0 = w * 96;
        for (int k = k0; k < k0 + 96; k += 4) {
            float w0 = Wq[(size_t)(k + 0) * 256 + c];
            float w1 = Wq[(size_t)(k + 1) * 256 + c];
            float w2 = Wq[(size_t)(k + 2) * 256 + c];
            float w3 = Wq[(size_t)(k + 3) * 256 + c];
#pragma unroll
            for (int bi = 0; bi < 8; bi++) {
                acc[bi] += w0 * ctx_s[bi][k] + w1 * ctx_s[bi][k + 1]
                         + w2 * ctx_s[bi][k + 2] + w3 * ctx_s[bi][k + 3];
            }
        }
#pragma unroll
        for (int bi = 0; bi < 8; bi++) qp[w][bi][lane] = acc[bi];
    }
    __syncthreads();

    {
        int bi = w;
        float s = 0.f;
#pragma unroll
        for (int ww = 0; ww < 8; ww++) s += qp[ww][bi][lane];
        q_s[bi][lane] = s;
    }
    __syncthreads();

    int d = t;
    const float4* wk = (const float4*)(Wk + (size_t)d * 256 + cx * 32);
#pragma unroll
    for (int hl = 0; hl < 2; hl++) {
        float4 w0 = wk[hl * 4], w1 = wk[hl * 4 + 1], w2 = wk[hl * 4 + 2], w3 = wk[hl * 4 + 3];
#pragma unroll
        for (int bi = 0; bi < 8; bi++) {
            const float4* qv = (const float4*)(&q_s[bi][hl * 16]);
            float s = dot4(w0, qv[0]) + dot4(w1, qv[1]) + dot4(w2, qv[2]) + dot4(w3, qv[3]);
            g_u[(size_t)(by * 8 + bi) * (HH * DD) + (cx * 2 + hl) * 256 + d] = s;
        }
    }
}

// ---------------- Kernel 3: attention per batch; w -> gmem -------------------
#define OFF_CE   0
#define OFF_ATT  (C1 * DD * 4)                  // 103424
#define OFF_VMI  (OFF_ATT + HH * AS * 4)        // +6656
#define SMEM_A_BYTES (OFF_VMI + 104 * 4 + 16)   // ~110.5KB -> occ 2

__global__ void __launch_bounds__(512, 2) k_attn(
    const float* __restrict__ clus, const void* __restrict__ vmask,
    const void* __restrict__ mask)
{
    extern __shared__ __align__(16) char smraw[];
    float* ce  = (float*)(smraw + OFF_CE);
    float* att = (float*)(smraw + OFF_ATT);
    int*   vmi = (int*)(smraw + OFF_VMI);

    int b = blockIdx.x, t = threadIdx.x;
    int lane = t & 31, warp = t >> 5;

    int mode = detect_mode(mask, t);

    {
        const float4* cg = (const float4*)(clus + (size_t)b * C1 * DD);
        float4* d4 = (float4*)ce;
        for (int i = t; i < C1 * DD / 4; i += 512) d4[i] = cg[i];
    }
    if (t < C1) vmi[t] = readb(vmask, b * C1 + t, mode) ? 1 : 0;
    __syncthreads();
    if (t == 0) {
        int all = 1;
        for (int j = 1; j < C1; j++) all &= vmi[j];
        vmi[0] = !all;
    }
    __syncthreads();

    const float4* ce4 = (const float4*)ce;
    int hg = warp & 3;       // head group: heads hg*4 .. hg*4+3
    int qq = warp >> 2;      // quarter index 0..3

    // ---- scores: warp = (hg, j-quarter); 2 passes of 2 heads ---------------
    {
        int jbeg = qq * 26;
        int jend = (qq == 3) ? C1 : jbeg + 26;
        const float4* up = (const float4*)(g_u + (size_t)b * (HH * DD));
#pragma unroll
        for (int pp = 0; pp < 2; pp++) {
            int ha = hg * 4 + pp * 2, hb = ha + 1;
            float4 ua0 = up[ha * 64 + lane * 2], ub0 = up[ha * 64 + lane * 2 + 1];
            float4 ua1 = up[hb * 64 + lane * 2], ub1 = up[hb * 64 + lane * 2 + 1];
            for (int j = jbeg; j < jend; j++) {
                float4 c0 = ce4[j * 64 + lane * 2], c1 = ce4[j * 64 + lane * 2 + 1];
                float p0 = dot4(ua0, c0) + dot4(ub0, c1);
                float p1 = dot4(ua1, c0) + dot4(ub1, c1);
#pragma unroll
                for (int o = 16; o; o >>= 1) {
                    p0 += __shfl_xor_sync(0xffffffffu, p0, o);
                    p1 += __shfl_xor_sync(0xffffffffu, p1, o);
                }
                if (lane == 0) {
                    int msk = vmi[j];
                    att[ha * AS + j] = msk ? NEGV : p0 * 0.25f;
                    att[hb * AS + j] = msk ? NEGV : p1 * 0.25f;
                }
            }
        }
    }
    __syncthreads();

    // ---- softmax: warp = head ----------------------------------------------
    {
        int h = warp;
        float v[4];
#pragma unroll
        for (int k = 0; k < 4; k++) {
            int j = lane + 32 * k;
            v[k] = (j < C1) ? att[h * AS + j] : -3.0e38f;
        }
        float m = fmaxf(fmaxf(v[0], v[1]), fmaxf(v[2], v[3]));
#pragma unroll
        for (int o = 16; o; o >>= 1) m = fmaxf(m, __shfl_xor_sync(0xffffffffu, m, o));
        float e[4], s = 0.f;
#pragma unroll
        for (int k = 0; k < 4; k++) {
            int j = lane + 32 * k;
            e[k] = (j < C1) ? expf(v[k] - m) : 0.f;
            s += e[k];
        }
#pragma unroll
        for (int o = 16; o; o >>= 1) s += __shfl_xor_sync(0xffffffffu, s, o);
        float inv = 1.0f / s;
#pragma unroll
        for (int k = 0; k < 4; k++) {
            int j = lane + 32 * k;
            if (j < C1) att[h * AS + j] = e[k] * inv;
        }
    }
    __syncthreads();

    // ---- wsum: warp = (hg, d-quarter); regs -> g_w directly ------------------
    {
        unsigned long long A0 = 0ull, A1 = 0ull, A2 = 0ull, A3 = 0ull;
        const unsigned long long* ce2 = (const unsigned long long*)ce;
        const float* a0 = att + (hg * 4 + 0) * AS;
        const float* a1 = att + (hg * 4 + 1) * AS;
        const float* a2 = att + (hg * 4 + 2) * AS;
        const float* a3 = att + (hg * 4 + 3) * AS;
        int idx = qq * 32 + lane;
        for (int j = 0; j < C1; j++) {
            unsigned long long c = ce2[j * 128 + idx];
            fma2(A0, pack2(a0[j]), c);
            fma2(A1, pack2(a1[j]), c);
            fma2(A2, pack2(a2[j]), c);
            fma2(A3, pack2(a3[j]), c);
        }
        int dbase = qq * 64 + lane * 2;
        float* gw = g_w + (size_t)b * (HH * DD);
        U64F2 u0, u1, u2, u3;
        u0.u = A0; u1.u = A1; u2.u = A2; u3.u = A3;
        *(float2*)(gw + (hg * 4 + 0) * 256 + dbase) = u0.f;
        *(float2*)(gw + (hg * 4 + 1) * 256 + dbase) = u1.f;
        *(float2*)(gw + (hg * 4 + 2) * 256 + dbase) = u2.f;
        *(float2*)(gw + (hg * 4 + 3) * 256 + dbase) = u3.f;
    }
}

// ---------------- Kernel 4: gl + tv (M2-fused; 2 batches/CTA) ----------------
#define G_W    0
#define G_SCR  (G_W + 2 * WROW * 4)             // 33280
#define G_GL   (G_SCR + 2 * 8 * 256 * 4)        // +16384
#define SMEM_G_BYTES (G_GL + 2048)

__global__ void __launch_bounds__(512) k_gltv(
    const float* __restrict__ Wv)
{
    extern __shared__ __align__(16) char smg[];
    float* w_sh = (float*)(smg + G_W);
    float* scr  = (float*)(smg + G_SCR);
    float* gl   = (float*)(smg + G_GL);

    int b0 = blockIdx.x * 2, t = threadIdx.x;

    // load w for both batches
    {
        const float4* gw4 = (const float4*)(g_w + (size_t)b0 * (HH * DD));
        for (int i = t; i < 2048; i += 512) {
            int bi = i >> 10, rem = i & 1023;
            int h = rem >> 6, d4 = rem & 63;
            ((float4*)(w_sh + bi * WROW + h * WS))[d4] = gw4[i];
        }
    }
    __syncthreads();

    int c4 = t & 63, g = t >> 6;   // cols 4c4..4c4+3, d-group g (8x32)
    int h4 = c4 >> 2;

    // ---- gl: Wv loaded once, applied to both batches -------------------------
    {
        const float4* wv4 = (const float4*)Wv;
        const float* w0r = w_sh + 0 * WROW + h4 * WS;
        const float* w1r = w_sh + 1 * WROW + h4 * WS;
        float4 a0 = make_float4(0.f, 0.f, 0.f, 0.f), a1 = a0;
        int d0 = g * 32;
#pragma unroll 8
        for (int i = 0; i < 32; i++) {
            int d = d0 + i;
            float4 wv = wv4[(size_t)d * 64 + c4];
            float f0 = w0r[d], f1 = w1r[d];
            a0.x += wv.x * f0; a0.y += wv.y * f0; a0.z += wv.z * f0; a0.w += wv.w * f0;
            a1.x += wv.x * f1; a1.y += wv.y * f1; a1.z += wv.z * f1; a1.w += wv.w * f1;
        }
        ((float4*)scr)[(0 * 8 + g) * 64 + c4] = a0;
        ((float4*)scr)[(1 * 8 + g) * 64 + c4] = a1;
    }
    __syncthreads();
    {
        int bi = t >> 8, c = t & 255;
        float s = 0.f;
#pragma unroll
        for (int gg = 0; gg < 8; gg++) s += scr[(bi * 8 + gg) * 256 + c];
        gl[bi * 256 + c] = s;
    }
    __syncthreads();

    // ---- tv[d] = sum_e M2T[e][d] * gl[e]  (rows of M2T coalesced) ------------
    {
        const float4* m4 = (const float4*)g_M2T;
        float4 a0 = make_float4(0.f, 0.f, 0.f, 0.f), a1 = a0;
        int e0 = g * 32;
#pragma unroll 8
        for (int i = 0; i < 32; i++) {
            int e = e0 + i;
            float4 wv = m4[(size_t)e * 64 + c4];
            float f0 = gl[e], f1 = gl[256 + e];
            a0.x += wv.x * f0; a0.y += wv.y * f0; a0.z += wv.z * f0; a0.w += wv.w * f0;
            a1.x += wv.x * f1; a1.y += wv.y * f1; a1.z += wv.z * f1; a1.w += wv.w * f1;
        }
        ((float4*)scr)[(0 * 8 + g) * 64 + c4] = a0;
        ((float4*)scr)[(1 * 8 + g) * 64 + c4] = a1;
    }
    __syncthreads();
    {
        int bi = t >> 8, c = t & 255;
        float s = 0.f;
#pragma unroll
        for (int gg = 0; gg < 8; gg++) s += scr[(bi * 8 + gg) * 256 + c];
        g_tv[(size_t)(b0 + bi) * DD + c] = s;
    }
}

// ---------------- Kernel 5: logits + log_softmax + argmax + outputs ----------
__global__ void __launch_bounds__(256) k_out(
    const float* __restrict__ depot, const float* __restrict__ clus,
    const float* __restrict__ cur,   const void*  __restrict__ vmask,
    const void*  __restrict__ mask,  float* __restrict__ out)
{
    __shared__ float lg[C1 + 3];
    __shared__ float red[4];
    __shared__ int vmi[C1 + 3];
    __shared__ int seli[1];

    int b = blockIdx.x, t = threadIdx.x;
    int lane = t & 31, warp = t >> 5;

    int mode = detect_mode(mask, t);
    if (t < C1) vmi[t] = readb(vmask, b * C1 + t, mode) ? 1 : 0;
    __syncthreads();
    if (t == 0) {
        int all = 1;
        for (int j = 1; j < C1; j++) all &= vmi[j];
        vmi[0] = !all;
    }
    __syncthreads();

    const float4* cg = (const float4*)(clus + (size_t)b * C1 * DD);
    const float4* tv4 = (const float4*)(g_tv + (size_t)b * DD);
    float4 t0 = tv4[lane * 2], t1 = tv4[lane * 2 + 1];

    for (int j = warp; j < C1; j += 8) {
        float4 c0 = cg[j * 64 + lane * 2], c1 = cg[j * 64 + lane * 2 + 1];
        float s = dot4(t0, c0) + dot4(t1, c1);
#pragma unroll
        for (int o = 16; o; o >>= 1) s += __shfl_xor_sync(0xffffffffu, s, o);
        if (lane == 0) {
            float l = tanhf(s * (1.0f / 16.0f)) * 10.0f;
            lg[j] = vmi[j] ? NEGV : l;
        }
    }
    __syncthreads();

    if (warp == 0) {
        float m = -3.0e38f; int mi = 0x7fffffff;
        for (int j = lane; j < C1; j += 32) {
            float v = lg[j];
            if (v > m) { m = v; mi = j; }
        }
#pragma unroll
        for (int o = 16; o; o >>= 1) {
            float om = __shfl_xor_sync(0xffffffffu, m, o);
            int   oi = __shfl_xor_sync(0xffffffffu, mi, o);
            if (om > m || (om == m && oi < mi)) { m = om; mi = oi; }
        }
        float s = 0.f;
        for (int j = lane; j < C1; j += 32) s += expf(lg[j] - m);
#pragma unroll
        for (int o = 16; o; o >>= 1) s += __shfl_xor_sync(0xffffffffu, s, o);
        if (lane == 0) { red[0] = m + logf(s); seli[0] = mi; }
    }
    __syncthreads();

    int sel = seli[0];
    float lse = red[0];
    float se = clus[(size_t)b * C1 * DD + (size_t)sel * 256 + t];
    int cb = (BB + b) * 4;
    float s = g_part[(size_t)(cb + 0) * 256 + t] + g_part[(size_t)(cb + 1) * 256 + t]
            + g_part[(size_t)(cb + 2) * 256 + t] + g_part[(size_t)(cb + 3) * 256 + t];
    float den = fmaxf((float)(g_cnt[cb] + g_cnt[cb + 1] + g_cnt[cb + 2] + g_cnt[cb + 3]), 1.0f);
    size_t oa = (size_t)b * 1024;
    out[oa + t]       = s / den;
    out[oa + 256 + t] = cur[(size_t)b * DD + t];
    out[oa + 512 + t] = se;
    out[oa + 768 + t] = depot[(size_t)b * DD + t];
    out[262144 + (size_t)b * 256 + t] = se;
    if (t == 0) out[327680 + b] = (float)sel;
    if (t < C1) out[327936 + (size_t)b * C1 + t] = lg[t] - lse;
}

extern "C" void kernel_launch(void* const* d_in, const int* in_sizes, int n_in,
                              void* d_out, int out_size) {
    const float* depot = (const float*)d_in[0];
    const float* clus  = (const float*)d_in[1];
    const float* cur   = (const float*)d_in[2];
    const float* node  = (const float*)d_in[3];
    const void*  mask  = d_in[4];
    const void*  cmask = d_in[5];
    const void*  vmask = d_in[6];
    const float* Wq    = (const float*)d_in[7];
    const float* Wk    = (const float*)d_in[8];
    const float* Wv    = (const float*)d_in[9];
    const float* Wks   = (const float*)d_in[10];
    const float* Wo    = (const float*)d_in[11];
    float* out = (float*)d_out;

    cudaFuncSetAttribute(k_attn, cudaFuncAttributeMaxDynamicSharedMemorySize, SMEM_A_BYTES);
    cudaFuncSetAttribute(k_gltv, cudaFuncAttributeMaxDynamicSharedMemorySize, SMEM_G_BYTES);

    k_prep<<<dim3(8, 8), 256>>>(Wks, Wo);
    k_nodes_part<<<dim3(4, BB), 256>>>(node, mask, cmask);
    k_qu<<<dim3(8, 32), 256>>>(cur, depot, Wq, Wk);
    k_attn<<<BB, 512, SMEM_A_BYTES>>>(clus, vmask, mask);
    k_gltv<<<BB / 2, 512, SMEM_G_BYTES>>>(Wv);
    k_out<<<BB, 256>>>(depot, clus, cur, vmask, mask, out);
}

// round 9
// speedup vs baseline: 1.0819x; 1.0819x over previous
#include <cuda_runtime.h>
#include <math.h>
#include <stdint.h>

#define BB  256
#define NN  1024
#define C1  101
#define DD  256
#define HH  16
#define NEGV (-1000000000.0f)
#define AS  104          // att row stride (floats)
#define WS  260          // w_s row stride (floats)

__device__ __align__(16) float g_u[BB * HH * DD];     // u[b][h][d]
__device__ __align__(16) float g_M2T[DD * DD];        // M2T[e][d] = sum_c Wks[d,c]*Wo[e,c]
__device__ __align__(16) float g_part[2 * BB * 4 * DD];
__device__ int g_cnt[2 * BB * 4];

__device__ __forceinline__ bool readb(const void* p, int idx, int mode) {
    if (mode == 0) return ((const unsigned char*)p)[idx] != 0;
    if (mode == 1) return ((const int*)p)[idx] != 0;
    return ((const float*)p)[idx] != 0.0f;
}

__device__ __forceinline__ float dot4(float4 a, float4 b) {
    return a.x * b.x + a.y * b.y + a.z * b.z + a.w * b.w;
}

__device__ __forceinline__ unsigned long long pack2(float x) {
    unsigned long long r;
    asm("mov.b64 %0, {%1, %1};" : "=l"(r) : "f"(x));
    return r;
}
__device__ __forceinline__ void fma2(unsigned long long& acc, unsigned long long a,
                                     unsigned long long b) {
    asm("fma.rn.f32x2 %0, %1, %2, %0;" : "+l"(acc) : "l"(a), "l"(b));
}
union U64F2 { unsigned long long u; float2 f; };

// bool-dtype probe on first 4KB of `mask`. Call from ALL threads (sync-or).
__device__ __forceinline__ int detect_mode(const void* m, int t) {
    int f32 = 0, u8 = 0;
    if (t < 256) {
        uint4 v = ((const uint4*)m)[t];
        unsigned w[4] = {v.x, v.y, v.z, v.w};
#pragma unroll
        for (int i = 0; i < 4; i++) {
            unsigned x = w[i];
            if (((x >> 24) & 0xffu) == 0x3fu || ((x >> 16) & 0xffu) == 0x3fu ||
                ((x >> 8) & 0xffu) == 0x3fu || (x & 0xffu) == 0x3fu) f32 = 1;
            if (x & 0xffffff00u) u8 = 1;
        }
    }
    int a = __syncthreads_or(f32);
    int b = __syncthreads_or(u8);
    return a ? 2 : (b ? 0 : 1);
}

// ---------------- Kernel 0: M2T[e][d] = sum_c Wks[d,c] * Wo[e,c] -------------
__global__ void __launch_bounds__(256) k_prep(
    const float* __restrict__ Wks, const float* __restrict__ Wo)
{
    __shared__ __align__(16) float a_sh[32 * 260];
    __shared__ __align__(16) float b_sh[32 * 260];

    int tj = blockIdx.x;   // d tile
    int ti = blockIdx.y;   // e tile
    int t = threadIdx.x;

    for (int i = t; i < 2048; i += 256) {
        int r = i >> 6, c4 = i & 63;
        float4 av = ((const float4*)(Wks + (size_t)(tj * 32 + r) * 256))[c4];
        float4 bv = ((const float4*)(Wo  + (size_t)(ti * 32 + r) * 256))[c4];
        *(float4*)(a_sh + r * 260 + c4 * 4) = av;
        *(float4*)(b_sh + r * 260 + c4 * 4) = bv;
    }
    __syncthreads();

    int el = t >> 3;
    int dl = (t & 7) * 4;
    float acc0 = 0.f, acc1 = 0.f, acc2 = 0.f, acc3 = 0.f;
    const float* br = b_sh + el * 260;
    const float* a0 = a_sh + (dl + 0) * 260;
    const float* a1 = a_sh + (dl + 1) * 260;
    const float* a2 = a_sh + (dl + 2) * 260;
    const float* a3 = a_sh + (dl + 3) * 260;
#pragma unroll 8
    for (int c = 0; c < 256; c++) {
        float bv = br[c];
        acc0 += a0[c] * bv;
        acc1 += a1[c] * bv;
        acc2 += a2[c] * bv;
        acc3 += a3[c] * bv;
    }
    *(float4*)(g_M2T + (size_t)(ti * 32 + el) * 256 + tj * 32 + dl) =
        make_float4(acc0, acc1, acc2, acc3);
}

// ---------------- Kernel 1: node partial sums (1024 CTAs) --------------------
__global__ void __launch_bounds__(256) k_nodes_part(
    const float* __restrict__ node, const void* __restrict__ mask,
    const void* __restrict__ cmask)
{
    __shared__ unsigned char code[256];
    __shared__ float4 part[2][4][64];

    int q = blockIdx.x, b = blockIdx.y, t = threadIdx.x;
    int mode = detect_mode(mask, t);

    int gidx = b * NN + q * 256 + t;
    bool m  = readb(mask,  gidx, mode);
    bool mc = m | readb(cmask, gidx, mode);
    code[t] = (unsigned char)((m ? 1 : 0) | (mc ? 2 : 0));
    int c0 = __syncthreads_count(!m);
    int c1 = __syncthreads_count(!mc);

    int chunk = t >> 6, d4 = t & 63;
    const float4* np4 = (const float4*)(node + (size_t)b * NN * DD);
    float4 s0 = make_float4(0.f, 0.f, 0.f, 0.f), s1 = s0;
    int n0 = chunk * 64;
#pragma unroll 8
    for (int i = 0; i < 64; i++) {
        int n = n0 + i;
        float4 v = __ldcs(&np4[(size_t)(q * 256 + n) * 64 + d4]);
        unsigned char c = code[n];
        if (!(c & 1)) { s0.x += v.x; s0.y += v.y; s0.z += v.z; s0.w += v.w; }
        if (!(c & 2)) { s1.x += v.x; s1.y += v.y; s1.z += v.z; s1.w += v.w; }
    }
    part[0][chunk][d4] = s0;
    part[1][chunk][d4] = s1;
    __syncthreads();

    if (t < 128) {
        int which = t >> 6, d = t & 63;
        float4 r = make_float4(0.f, 0.f, 0.f, 0.f);
#pragma unroll
        for (int c = 0; c < 4; c++) {
            float4 a = part[which][c][d];
            r.x += a.x; r.y += a.y; r.z += a.z; r.w += a.w;
        }
        ((float4*)g_part)[((which * BB + b) * 4 + q) * 64 + d] = r;
    }
    if (t == 0) {
        g_cnt[(0 * BB + b) * 4 + q] = c0;
        g_cnt[(1 * BB + b) * 4 + q] = c1;
    }
}

// ---------------- Kernel 2: q + u (uv reduced inline from partials) ----------
__global__ void __launch_bounds__(256) k_qu(
    const float* __restrict__ cur, const float* __restrict__ depot,
    const float* __restrict__ Wq, const float* __restrict__ Wk)
{
    __shared__ __align__(16) float ctx_s[8][768];
    __shared__ __align__(16) float qp[8][8][32];
    __shared__ __align__(16) float q_s[8][32];
    __shared__ float den_s[8];

    int cx = blockIdx.x;     // 0..7 : 32-col slice = 2 heads
    int by = blockIdx.y;     // 0..31: 8 batches
    int t = threadIdx.x, lane = t & 31, w = t >> 5;

    if (t < 8) {
        int b = by * 8 + t;
        int c = g_cnt[b * 4 + 0] + g_cnt[b * 4 + 1] + g_cnt[b * 4 + 2] + g_cnt[b * 4 + 3];
        den_s[t] = fmaxf((float)c, 1.0f);
    }
    __syncthreads();

    for (int i = t; i < 8 * 256; i += 256) {
        int bi = i >> 8, d = i & 255;
        int b = by * 8 + bi;
        float s = g_part[(size_t)(b * 4 + 0) * 256 + d] + g_part[(size_t)(b * 4 + 1) * 256 + d]
                + g_part[(size_t)(b * 4 + 2) * 256 + d] + g_part[(size_t)(b * 4 + 3) * 256 + d];
        ctx_s[bi][d]       = s / den_s[bi];
        ctx_s[bi][256 + d] = cur[(size_t)b * DD + d];
        ctx_s[bi][512 + d] = depot[(size_t)b * DD + d];
    }
    __syncthreads();

    {
        int c = cx * 32 + lane;
        float acc[8];
#pragma unroll
        for (int bi = 0; bi < 8; bi++) acc[bi] = 0.f;
        int k0 = w * 96;
        for (int k = k0; k < k0 + 96; k += 4) {
            float w0 = Wq[(size_t)(k + 0) * 256 + c];
            float w1 = Wq[(size_t)(k + 1) * 256 + c];
            float w2 = Wq[(size_t)(k + 2) * 256 + c];
            float w3 = Wq[(size_t)(k + 3) * 256 + c];
#pragma unroll
            for (int bi = 0; bi < 8; bi++) {
                acc[bi] += w0 * ctx_s[bi][k] + w1 * ctx_s[bi][k + 1]
                         + w2 * ctx_s[bi][k + 2] + w3 * ctx_s[bi][k + 3];
            }
        }
#pragma unroll
        for (int bi = 0; bi < 8; bi++) qp[w][bi][lane] = acc[bi];
    }
    __syncthreads();

    {
        int bi = w;
        float s = 0.f;
#pragma unroll
        for (int ww = 0; ww < 8; ww++) s += qp[ww][bi][lane];
        q_s[bi][lane] = s;
    }
    __syncthreads();

    int d = t;
    const float4* wk = (const float4*)(Wk + (size_t)d * 256 + cx * 32);
#pragma unroll
    for (int hl = 0; hl < 2; hl++) {
        float4 w0 = wk[hl * 4], w1 = wk[hl * 4 + 1], w2 = wk[hl * 4 + 2], w3 = wk[hl * 4 + 3];
#pragma unroll
        for (int bi = 0; bi < 8; bi++) {
            const float4* qv = (const float4*)(&q_s[bi][hl * 16]);
            float s = dot4(w0, qv[0]) + dot4(w1, qv[1]) + dot4(w2, qv[2]) + dot4(w3, qv[3]);
            g_u[(size_t)(by * 8 + bi) * (HH * DD) + (cx * 2 + hl) * 256 + d] = s;
        }
    }
}

// SMEM layout (bytes). Region A holds ce; reused after wsum for w/gl/tv/scr.
#define OFF_A    0
#define A_BYTES  (C1 * DD * 4)                  // 103424
#define A_W      0                              // 16 * 260 * 4 = 16640
#define A_GL     16640
#define A_TV     (A_GL + 1024)
#define A_SCR    (A_TV + 1024)                  // 8 * 256 * 4 = 8192
#define OFF_ATT  A_BYTES                        // 16 * 104 * 4 = 6656
#define OFF_LG   (OFF_ATT + HH * AS * 4)
#define OFF_RED  (OFF_LG + 104 * 4)
#define OFF_VMI  (OFF_RED + 16)
#define OFF_SEL  (OFF_VMI + 104 * 4)
#define SMEM_BYTES (OFF_SEL + 16)               // 110944

// ---------------- Kernel 3: fused per-batch chain, occ 2 ---------------------
__global__ void __launch_bounds__(512, 2) k_main(
    const float* __restrict__ depot, const float* __restrict__ clus,
    const float* __restrict__ cur,   const void*  __restrict__ vmask,
    const void*  __restrict__ mask,
    const float* __restrict__ Wv,    float* __restrict__ out)
{
    extern __shared__ __align__(16) char smraw[];
    float* ce   = (float*)(smraw + OFF_A);
    float* w_s  = (float*)(smraw + A_W);
    float* gl   = (float*)(smraw + A_GL);
    float* tv   = (float*)(smraw + A_TV);
    float* scr  = (float*)(smraw + A_SCR);
    float* att  = (float*)(smraw + OFF_ATT);
    float* lg   = (float*)(smraw + OFF_LG);
    float* red  = (float*)(smraw + OFF_RED);
    int*   vmi  = (int*)(smraw + OFF_VMI);
    int*   seli = (int*)(smraw + OFF_SEL);

    int b = blockIdx.x, t = threadIdx.x;
    int lane = t & 31, warp = t >> 5;

    int mode = detect_mode(mask, t);

    // ce -> SMEM
    {
        const float4* cg = (const float4*)(clus + (size_t)b * C1 * DD);
        float4* d4 = (float4*)ce;
        for (int i = t; i < C1 * DD / 4; i += 512) d4[i] = cg[i];
    }
    if (t < C1) vmi[t] = readb(vmask, b * C1 + t, mode) ? 1 : 0;
    __syncthreads();
    if (t == 0) {
        int all = 1;
        for (int j = 1; j < C1; j++) all &= vmi[j];
        vmi[0] = !all;
    }
    __syncthreads();

    const float4* ce4 = (const float4*)ce;
    int hg = warp & 3;       // head group: heads hg*4 .. hg*4+3
    int qq = warp >> 2;      // quarter index 0..3

    // ---- scores: warp = (hg, j-quarter); 4 heads in ONE pass -----------------
    {
        int jbeg = qq * 26;
        int jend = (qq == 3) ? C1 : jbeg + 26;
        const float4* up = (const float4*)(g_u + (size_t)b * (HH * DD));
        float4 ua[4], ub[4];
#pragma unroll
        for (int h = 0; h < 4; h++) {
            ua[h] = up[(hg * 4 + h) * 64 + lane * 2];
            ub[h] = up[(hg * 4 + h) * 64 + lane * 2 + 1];
        }
        for (int j = jbeg; j < jend; j++) {
            float4 c0 = ce4[j * 64 + lane * 2], c1 = ce4[j * 64 + lane * 2 + 1];
            float p0 = dot4(ua[0], c0) + dot4(ub[0], c1);
            float p1 = dot4(ua[1], c0) + dot4(ub[1], c1);
            float p2 = dot4(ua[2], c0) + dot4(ub[2], c1);
            float p3 = dot4(ua[3], c0) + dot4(ub[3], c1);
#pragma unroll
            for (int o = 16; o; o >>= 1) {
                p0 += __shfl_xor_sync(0xffffffffu, p0, o);
                p1 += __shfl_xor_sync(0xffffffffu, p1, o);
                p2 += __shfl_xor_sync(0xffffffffu, p2, o);
                p3 += __shfl_xor_sync(0xffffffffu, p3, o);
            }
            if (lane == 0) {
                int msk = vmi[j];
                att[(hg * 4 + 0) * AS + j] = msk ? NEGV : p0 * 0.25f;
                att[(hg * 4 + 1) * AS + j] = msk ? NEGV : p1 * 0.25f;
                att[(hg * 4 + 2) * AS + j] = msk ? NEGV : p2 * 0.25f;
                att[(hg * 4 + 3) * AS + j] = msk ? NEGV : p3 * 0.25f;
            }
        }
    }
    __syncthreads();

    // ---- softmax: warp = head ------------------------------------------------
    {
        int h = warp;
        float v[4];
#pragma unroll
        for (int k = 0; k < 4; k++) {
            int j = lane + 32 * k;
            v[k] = (j < C1) ? att[h * AS + j] : -3.0e38f;
        }
        float m = fmaxf(fmaxf(v[0], v[1]), fmaxf(v[2], v[3]));
#pragma unroll
        for (int o = 16; o; o >>= 1) m = fmaxf(m, __shfl_xor_sync(0xffffffffu, m, o));
        float e[4], s = 0.f;
#pragma unroll
        for (int k = 0; k < 4; k++) {
            int j = lane + 32 * k;
            e[k] = (j < C1) ? expf(v[k] - m) : 0.f;
            s += e[k];
        }
#pragma unroll
        for (int o = 16; o; o >>= 1) s += __shfl_xor_sync(0xffffffffu, s, o);
        float inv = 1.0f / s;
#pragma unroll
        for (int k = 0; k < 4; k++) {
            int j = lane + 32 * k;
            if (j < C1) att[h * AS + j] = e[k] * inv;
        }
    }
    __syncthreads();

    // ---- wsum: warp = (hg, d-quarter); accumulators in regs -------------------
    unsigned long long A0 = 0ull, A1 = 0ull, A2 = 0ull, A3 = 0ull;
    {
        const unsigned long long* ce2 = (const unsigned long long*)ce;
        const float* a0 = att + (hg * 4 + 0) * AS;
        const float* a1 = att + (hg * 4 + 1) * AS;
        const float* a2 = att + (hg * 4 + 2) * AS;
        const float* a3 = att + (hg * 4 + 3) * AS;
        int idx = qq * 32 + lane;
        for (int j = 0; j < C1; j++) {
            unsigned long long c = ce2[j * 128 + idx];
            fma2(A0, pack2(a0[j]), c);
            fma2(A1, pack2(a1[j]), c);
            fma2(A2, pack2(a2[j]), c);
            fma2(A3, pack2(a3[j]), c);
        }
    }
    __syncthreads();   // ce reads done; region A reusable

    {
        int dbase = qq * 64 + lane * 2;
        U64F2 u0, u1, u2, u3;
        u0.u = A0; u1.u = A1; u2.u = A2; u3.u = A3;
        *(float2*)(w_s + (hg * 4 + 0) * WS + dbase) = u0.f;
        *(float2*)(w_s + (hg * 4 + 1) * WS + dbase) = u1.f;
        *(float2*)(w_s + (hg * 4 + 2) * WS + dbase) = u2.f;
        *(float2*)(w_s + (hg * 4 + 3) * WS + dbase) = u3.f;
    }
    __syncthreads();

    int c4 = t & 63, g = t >> 6;      // thread owns cols 4c4..4c4+3, d-group g
    int h4 = c4 >> 2;                 // head of those 4 columns

    // ---- gl[c] = sum_d Wv[d,c] * w[h(c)][d]  (coalesced float4 row loads) ----
    {
        const float4* wv4 = (const float4*)Wv;
        float4 acc = make_float4(0.f, 0.f, 0.f, 0.f);
        const float* wrow = w_s + h4 * WS;
        int d0 = g * 32;
#pragma unroll 8
        for (int i = 0; i < 32; i++) {
            int d = d0 + i;
            float4 wv = wv4[(size_t)d * 64 + c4];
            float wd = wrow[d];
            acc.x += wv.x * wd; acc.y += wv.y * wd;
            acc.z += wv.z * wd; acc.w += wv.w * wd;
        }
        ((float4*)scr)[g * 64 + c4] = acc;
    }
    __syncthreads();
    if (t < 256) {
        float s = 0.f;
#pragma unroll
        for (int gg = 0; gg < 8; gg++) s += scr[gg * 256 + t];
        gl[t] = s;
    }
    __syncthreads();

    // ---- tv[d] = sum_e M2T[e][d] * gl[e]  (go phase fused away) ---------------
    {
        const float4* m4 = (const float4*)g_M2T;
        float4 acc = make_float4(0.f, 0.f, 0.f, 0.f);
        int e0 = g * 32;
#pragma unroll 8
        for (int i = 0; i < 32; i++) {
            int e = e0 + i;
            float4 wv = m4[(size_t)e * 64 + c4];
            float ge = gl[e];
            acc.x += wv.x * ge; acc.y += wv.y * ge;
            acc.z += wv.z * ge; acc.w += wv.w * ge;
        }
        ((float4*)scr)[g * 64 + c4] = acc;
    }
    __syncthreads();
    if (t < 256) {
        float s = 0.f;
#pragma unroll
        for (int gg = 0; gg < 8; gg++) s += scr[gg * 256 + t];
        tv[t] = s;
    }
    __syncthreads();

    // ---- logits: ce re-read from gmem (L2) ------------------------------------
    {
        const float4* cg = (const float4*)(clus + (size_t)b * C1 * DD);
        const float4* tv4 = (const float4*)tv;
        float4 t0 = tv4[lane * 2], t1 = tv4[lane * 2 + 1];
        for (int j = warp; j < C1; j += 16) {
            float4 c0 = cg[j * 64 + lane * 2], c1 = cg[j * 64 + lane * 2 + 1];
            float s = dot4(t0, c0) + dot4(t1, c1);
#pragma unroll
            for (int o = 16; o; o >>= 1) s += __shfl_xor_sync(0xffffffffu, s, o);
            if (lane == 0) {
                float l = tanhf(s * (1.0f / 16.0f)) * 10.0f;
                lg[j] = vmi[j] ? NEGV : l;
            }
        }
    }
    __syncthreads();

    // ---- log_softmax + argmax (warp 0) ----------------------------------------
    if (warp == 0) {
        float m = -3.0e38f; int mi = 0x7fffffff;
        for (int j = lane; j < C1; j += 32) {
            float v = lg[j];
            if (v > m) { m = v; mi = j; }
        }
#pragma unroll
        for (int o = 16; o; o >>= 1) {
            float om = __shfl_xor_sync(0xffffffffu, m, o);
            int   oi = __shfl_xor_sync(0xffffffffu, mi, o);
            if (om > m || (om == m && oi < mi)) { m = om; mi = oi; }
        }
        float s = 0.f;
        for (int j = lane; j < C1; j += 32) s += expf(lg[j] - m);
#pragma unroll
        for (int o = 16; o; o >>= 1) s += __shfl_xor_sync(0xffffffffu, s, o);
        if (lane == 0) { red[0] = m + logf(s); seli[0] = mi; }
    }
    __syncthreads();

    // ---- outputs (uvc reduced inline from node partials) ----------------------
    int sel = seli[0];
    float lse = red[0];
    size_t oa = (size_t)b * 1024;
    if (t < 256) {
        float se = clus[(size_t)b * C1 * DD + (size_t)sel * 256 + t];
        int cb = (BB + b) * 4;
        float s = g_part[(size_t)(cb + 0) * 256 + t] + g_part[(size_t)(cb + 1) * 256 + t]
                + g_part[(size_t)(cb + 2) * 256 + t] + g_part[(size_t)(cb + 3) * 256 + t];
        float den = fmaxf((float)(g_cnt[cb] + g_cnt[cb + 1] + g_cnt[cb + 2] + g_cnt[cb + 3]), 1.0f);
        out[oa + t]       = s / den;
        out[oa + 512 + t] = se;
        out[262144 + (size_t)b * 256 + t] = se;
    } else {
        int d = t - 256;
        out[oa + 256 + d] = cur[(size_t)b * DD + d];
        out[oa + 768 + d] = depot[(size_t)b * DD + d];
    }
    if (t == 0) out[327680 + b] = (float)sel;
    if (t < C1) out[327936 + (size_t)b * C1 + t] = lg[t] - lse;
}

extern "C" void kernel_launch(void* const* d_in, const int* in_sizes, int n_in,
                              void* d_out, int out_size) {
    const float* depot = (const float*)d_in[0];
    const float* clus  = (const float*)d_in[1];
    const float* cur   = (const float*)d_in[2];
    const float* node  = (const float*)d_in[3];
    const void*  mask  = d_in[4];
    const void*  cmask = d_in[5];
    const void*  vmask = d_in[6];
    const float* Wq    = (const float*)d_in[7];
    const float* Wk    = (const float*)d_in[8];
    const float* Wv    = (const float*)d_in[9];
    const float* Wks   = (const float*)d_in[10];
    const float* Wo    = (const float*)d_in[11];
    float* out = (float*)d_out;

    cudaFuncSetAttribute(k_main, cudaFuncAttributeMaxDynamicSharedMemorySize, SMEM_BYTES);

    k_prep<<<dim3(8, 8), 256>>>(Wks, Wo);
    k_nodes_part<<<dim3(4, BB), 256>>>(node, mask, cmask);
    k_qu<<<dim3(8, 32), 256>>>(cur, depot, Wq, Wk);
    k_main<<<BB, 512, SMEM_BYTES>>>(depot, clus, cur, vmask, mask, Wv, out);
}

// round 10
// speedup vs baseline: 1.1152x; 1.0308x over previous
#include <cuda_runtime.h>
#include <math.h>
#include <stdint.h>

#define BB  256
#define NN  1024
#define C1  101
#define DD  256
#define HH  16
#define NEGV (-1000000000.0f)
#define AS  104          // att row stride (floats)
#define WS  260          // w_s row stride (floats)

__device__ __align__(16) float g_u[BB * HH * DD];     // u[b][h][d]
__device__ __align__(16) float g_M2T[DD * DD];        // M2T[e][d] = sum_c Wks[d,c]*Wo[e,c]
__device__ __align__(16) float g_part[2 * BB * 4 * DD];
__device__ int g_cnt[2 * BB * 4];

__device__ __forceinline__ bool readb(const void* p, int idx, int mode) {
    if (mode == 0) return ((const unsigned char*)p)[idx] != 0;
    if (mode == 1) return ((const int*)p)[idx] != 0;
    return ((const float*)p)[idx] != 0.0f;
}

__device__ __forceinline__ float dot4(float4 a, float4 b) {
    return a.x * b.x + a.y * b.y + a.z * b.z + a.w * b.w;
}

__device__ __forceinline__ unsigned long long pack2(float x) {
    unsigned long long r;
    asm("mov.b64 %0, {%1, %1};" : "=l"(r) : "f"(x));
    return r;
}
__device__ __forceinline__ void fma2(unsigned long long& acc, unsigned long long a,
                                     unsigned long long b) {
    asm("fma.rn.f32x2 %0, %1, %2, %0;" : "+l"(acc) : "l"(a), "l"(b));
}
union U64F2 { unsigned long long u; float2 f; };

// bool-dtype probe on first 4KB of `mask`. Call from ALL threads (sync-or).
__device__ __forceinline__ int detect_mode(const void* m, int t) {
    int f32 = 0, u8 = 0;
    if (t < 256) {
        uint4 v = ((const uint4*)m)[t];
        unsigned w[4] = {v.x, v.y, v.z, v.w};
#pragma unroll
        for (int i = 0; i < 4; i++) {
            unsigned x = w[i];
            if (((x >> 24) & 0xffu) == 0x3fu || ((x >> 16) & 0xffu) == 0x3fu ||
                ((x >> 8) & 0xffu) == 0x3fu || (x & 0xffu) == 0x3fu) f32 = 1;
            if (x & 0xffffff00u) u8 = 1;
        }
    }
    int a = __syncthreads_or(f32);
    int b = __syncthreads_or(u8);
    return a ? 2 : (b ? 0 : 1);
}

// ---------------- Kernel 1: node partial sums (1024 CTAs), pipelined ---------
__global__ void __launch_bounds__(256) k_nodes_part(
    const float* __restrict__ node, const void* __restrict__ mask,
    const void* __restrict__ cmask)
{
    __shared__ unsigned char code[256];
    __shared__ float4 part[2][4][64];

    int q = blockIdx.x, b = blockIdx.y, t = threadIdx.x;
    int mode = detect_mode(mask, t);

    int gidx = b * NN + q * 256 + t;
    bool m  = readb(mask,  gidx, mode);
    bool mc = m | readb(cmask, gidx, mode);
    code[t] = (unsigned char)((m ? 1 : 0) | (mc ? 2 : 0));
    int c0 = __syncthreads_count(!m);
    int c1 = __syncthreads_count(!mc);

    int chunk = t >> 6, d4 = t & 63;
    const float4* np4 = (const float4*)(node + (size_t)b * NN * DD);
    int n0 = chunk * 64;
    const float4* basep = np4 + (size_t)(q * 256 + n0) * 64 + d4;

    float4 s0 = make_float4(0.f, 0.f, 0.f, 0.f), s1 = s0;

    // depth-4 software pipeline: keep 4 independent LDG.128 in flight
    float4 buf[4];
#pragma unroll
    for (int j = 0; j < 4; j++) buf[j] = __ldcs(basep + j * 64);

#pragma unroll
    for (int i = 0; i < 64; i += 4) {
        float4 curv[4];
#pragma unroll
        for (int j = 0; j < 4; j++) curv[j] = buf[j];
        if (i + 4 < 64) {
#pragma unroll
            for (int j = 0; j < 4; j++) buf[j] = __ldcs(basep + (i + 4 + j) * 64);
        }
#pragma unroll
        for (int j = 0; j < 4; j++) {
            unsigned char c = code[n0 + i + j];
            float4 v = curv[j];
            if (!(c & 1)) { s0.x += v.x; s0.y += v.y; s0.z += v.z; s0.w += v.w; }
            if (!(c & 2)) { s1.x += v.x; s1.y += v.y; s1.z += v.z; s1.w += v.w; }
        }
    }
    part[0][chunk][d4] = s0;
    part[1][chunk][d4] = s1;
    __syncthreads();

    if (t < 128) {
        int which = t >> 6, d = t & 63;
        float4 r = make_float4(0.f, 0.f, 0.f, 0.f);
#pragma unroll
        for (int c = 0; c < 4; c++) {
            float4 a = part[which][c][d];
            r.x += a.x; r.y += a.y; r.z += a.z; r.w += a.w;
        }
        ((float4*)g_part)[((which * BB + b) * 4 + q) * 64 + d] = r;
    }
    if (t == 0) {
        g_cnt[(0 * BB + b) * 4 + q] = c0;
        g_cnt[(1 * BB + b) * 4 + q] = c1;
    }
}

// ---------------- Kernel 2: q + u (CTAs 0..255)  +  M2T prep (CTAs 256..319) -
// Dynamic SMEM union: qu role ~33.8KB, prep role 65KB.
#define QU_SMEM_BYTES 66560

__global__ void __launch_bounds__(256) k_qu_prep(
    const float* __restrict__ cur, const float* __restrict__ depot,
    const float* __restrict__ Wq,  const float* __restrict__ Wk,
    const float* __restrict__ Wks, const float* __restrict__ Wo)
{
    extern __shared__ __align__(16) float sm[];
    int bx = blockIdx.x;
    int t = threadIdx.x;

    if (bx >= 256) {
        // ---- prep role: M2T[e][d] = sum_c Wks[d,c] * Wo[e,c] ---------------
        float* a_sh = sm;            // 32 * 260
        float* b_sh = sm + 8320;     // 32 * 260
        int tile = bx - 256;
        int tj = tile & 7;   // d tile
        int ti = tile >> 3;  // e tile

        for (int i = t; i < 2048; i += 256) {
            int r = i >> 6, c4 = i & 63;
            float4 av = ((const float4*)(Wks + (size_t)(tj * 32 + r) * 256))[c4];
            float4 bv = ((const float4*)(Wo  + (size_t)(ti * 32 + r) * 256))[c4];
            *(float4*)(a_sh + r * 260 + c4 * 4) = av;
            *(float4*)(b_sh + r * 260 + c4 * 4) = bv;
        }
        __syncthreads();

        int el = t >> 3;
        int dl = (t & 7) * 4;
        float acc0 = 0.f, acc1 = 0.f, acc2 = 0.f, acc3 = 0.f;
        const float* br = b_sh + el * 260;
        const float* a0 = a_sh + (dl + 0) * 260;
        const float* a1 = a_sh + (dl + 1) * 260;
        const float* a2 = a_sh + (dl + 2) * 260;
        const float* a3 = a_sh + (dl + 3) * 260;
#pragma unroll 8
        for (int c = 0; c < 256; c++) {
            float bv = br[c];
            acc0 += a0[c] * bv;
            acc1 += a1[c] * bv;
            acc2 += a2[c] * bv;
            acc3 += a3[c] * bv;
        }
        *(float4*)(g_M2T + (size_t)(ti * 32 + el) * 256 + tj * 32 + dl) =
            make_float4(acc0, acc1, acc2, acc3);
        return;
    }

    // ---- qu role ------------------------------------------------------------
    float* ctx_base = sm;                       // 8 x 768
    float* qp_base  = sm + 6144;                // 8 x 8 x 32
    float* q_base   = sm + 6144 + 2048;         // 8 x 32
    float* den_s    = sm + 6144 + 2048 + 256;   // 8

    int cx = bx & 7;        // 0..7 : 32-col slice = 2 heads
    int by = bx >> 3;       // 0..31: 8 batches
    int lane = t & 31, w = t >> 5;

    if (t < 8) {
        int b = by * 8 + t;
        int c = g_cnt[b * 4 + 0] + g_cnt[b * 4 + 1] + g_cnt[b * 4 + 2] + g_cnt[b * 4 + 3];
        den_s[t] = fmaxf((float)c, 1.0f);
    }
    __syncthreads();

    for (int i = t; i < 8 * 256; i += 256) {
        int bi = i >> 8, d = i & 255;
        int b = by * 8 + bi;
        float s = g_part[(size_t)(b * 4 + 0) * 256 + d] + g_part[(size_t)(b * 4 + 1) * 256 + d]
                + g_part[(size_t)(b * 4 + 2) * 256 + d] + g_part[(size_t)(b * 4 + 3) * 256 + d];
        ctx_base[bi * 768 + d]       = s / den_s[bi];
        ctx_base[bi * 768 + 256 + d] = cur[(size_t)b * DD + d];
        ctx_base[bi * 768 + 512 + d] = depot[(size_t)b * DD + d];
    }
    __syncthreads();

    {
        int c = cx * 32 + lane;
        float acc[8];
#pragma unroll
        for (int bi = 0; bi < 8; bi++) acc[bi] = 0.f;
        int k0 = w * 96;
        for (int k = k0; k < k0 + 96; k += 4) {
            float w0 = Wq[(size_t)(k + 0) * 256 + c];
            float w1 = Wq[(size_t)(k + 1) * 256 + c];
            float w2 = Wq[(size_t)(k + 2) * 256 + c];
            float w3 = Wq[(size_t)(k + 3) * 256 + c];
#pragma unroll
            for (int bi = 0; bi < 8; bi++) {
                const float* cb = ctx_base + bi * 768;
                acc[bi] += w0 * cb[k] + w1 * cb[k + 1]
                         + w2 * cb[k + 2] + w3 * cb[k + 3];
            }
        }
#pragma unroll
        for (int bi = 0; bi < 8; bi++) qp_base[(w * 8 + bi) * 32 + lane] = acc[bi];
    }
    __syncthreads();

    {
        int bi = w;
        float s = 0.f;
#pragma unroll
        for (int ww = 0; ww < 8; ww++) s += qp_base[(ww * 8 + bi) * 32 + lane];
        q_base[bi * 32 + lane] = s;
    }
    __syncthreads();

    int d = t;
    const float4* wk = (const float4*)(Wk + (size_t)d * 256 + cx * 32);
#pragma unroll
    for (int hl = 0; hl < 2; hl++) {
        float4 w0 = wk[hl * 4], w1 = wk[hl * 4 + 1], w2 = wk[hl * 4 + 2], w3 = wk[hl * 4 + 3];
#pragma unroll
        for (int bi = 0; bi < 8; bi++) {
            const float4* qv = (const float4*)(q_base + bi * 32 + hl * 16);
            float s = dot4(w0, qv[0]) + dot4(w1, qv[1]) + dot4(w2, qv[2]) + dot4(w3, qv[3]);
            g_u[(size_t)(by * 8 + bi) * (HH * DD) + (cx * 2 + hl) * 256 + d] = s;
        }
    }
}

// SMEM layout (bytes). Region A holds ce; reused after wsum for w/gl/tv/scr.
#define OFF_A    0
#define A_BYTES  (C1 * DD * 4)                  // 103424
#define A_W      0                              // 16 * 260 * 4 = 16640
#define A_GL     16640
#define A_TV     (A_GL + 1024)
#define A_SCR    (A_TV + 1024)                  // 8 * 256 * 4 = 8192
#define OFF_ATT  A_BYTES                        // 16 * 104 * 4 = 6656
#define OFF_LG   (OFF_ATT + HH * AS * 4)
#define OFF_RED  (OFF_LG + 104 * 4)
#define OFF_VMI  (OFF_RED + 16)
#define OFF_SEL  (OFF_VMI + 104 * 4)
#define SMEM_BYTES (OFF_SEL + 16)               // 110944

// ---------------- Kernel 3: fused per-batch chain, occ 2 ---------------------
__global__ void __launch_bounds__(512, 2) k_main(
    const float* __restrict__ depot, const float* __restrict__ clus,
    const float* __restrict__ cur,   const void*  __restrict__ vmask,
    const void*  __restrict__ mask,
    const float* __restrict__ Wv,    float* __restrict__ out)
{
    extern __shared__ __align__(16) char smraw[];
    float* ce   = (float*)(smraw + OFF_A);
    float* w_s  = (float*)(smraw + A_W);
    float* gl   = (float*)(smraw + A_GL);
    float* tv   = (float*)(smraw + A_TV);
    float* scr  = (float*)(smraw + A_SCR);
    float* att  = (float*)(smraw + OFF_ATT);
    float* lg   = (float*)(smraw + OFF_LG);
    float* red  = (float*)(smraw + OFF_RED);
    int*   vmi  = (int*)(smraw + OFF_VMI);
    int*   seli = (int*)(smraw + OFF_SEL);

    int b = blockIdx.x, t = threadIdx.x;
    int lane = t & 31, warp = t >> 5;

    int mode = detect_mode(mask, t);

    // ce -> SMEM
    {
        const float4* cg = (const float4*)(clus + (size_t)b * C1 * DD);
        float4* d4 = (float4*)ce;
        for (int i = t; i < C1 * DD / 4; i += 512) d4[i] = cg[i];
    }
    if (t < C1) vmi[t] = readb(vmask, b * C1 + t, mode) ? 1 : 0;
    __syncthreads();
    if (t == 0) {
        int all = 1;
        for (int j = 1; j < C1; j++) all &= vmi[j];
        vmi[0] = !all;
    }
    __syncthreads();

    const float4* ce4 = (const float4*)ce;
    int hg = warp & 3;       // head group: heads hg*4 .. hg*4+3
    int qq = warp >> 2;      // quarter index 0..3

    // ---- scores: warp = (hg, j-quarter); 4 heads in ONE pass -----------------
    {
        int jbeg = qq * 26;
        int jend = (qq == 3) ? C1 : jbeg + 26;
        const float4* up = (const float4*)(g_u + (size_t)b * (HH * DD));
        float4 ua[4], ub[4];
#pragma unroll
        for (int h = 0; h < 4; h++) {
            ua[h] = up[(hg * 4 + h) * 64 + lane * 2];
            ub[h] = up[(hg * 4 + h) * 64 + lane * 2 + 1];
        }
        for (int j = jbeg; j < jend; j++) {
            float4 c0 = ce4[j * 64 + lane * 2], c1 = ce4[j * 64 + lane * 2 + 1];
            float p0 = dot4(ua[0], c0) + dot4(ub[0], c1);
            float p1 = dot4(ua[1], c0) + dot4(ub[1], c1);
            float p2 = dot4(ua[2], c0) + dot4(ub[2], c1);
            float p3 = dot4(ua[3], c0) + dot4(ub[3], c1);
#pragma unroll
            for (int o = 16; o; o >>= 1) {
                p0 += __shfl_xor_sync(0xffffffffu, p0, o);
                p1 += __shfl_xor_sync(0xffffffffu, p1, o);
                p2 += __shfl_xor_sync(0xffffffffu, p2, o);
                p3 += __shfl_xor_sync(0xffffffffu, p3, o);
            }
            if (lane == 0) {
                int msk = vmi[j];
                att[(hg * 4 + 0) * AS + j] = msk ? NEGV : p0 * 0.25f;
                att[(hg * 4 + 1) * AS + j] = msk ? NEGV : p1 * 0.25f;
                att[(hg * 4 + 2) * AS + j] = msk ? NEGV : p2 * 0.25f;
                att[(hg * 4 + 3) * AS + j] = msk ? NEGV : p3 * 0.25f;
            }
        }
    }
    __syncthreads();

    // ---- softmax: warp = head ------------------------------------------------
    {
        int h = warp;
        float v[4];
#pragma unroll
        for (int k = 0; k < 4; k++) {
            int j = lane + 32 * k;
            v[k] = (j < C1) ? att[h * AS + j] : -3.0e38f;
        }
        float m = fmaxf(fmaxf(v[0], v[1]), fmaxf(v[2], v[3]));
#pragma unroll
        for (int o = 16; o; o >>= 1) m = fmaxf(m, __shfl_xor_sync(0xffffffffu, m, o));
        float e[4], s = 0.f;
#pragma unroll
        for (int k = 0; k < 4; k++) {
            int j = lane + 32 * k;
            e[k] = (j < C1) ? expf(v[k] - m) : 0.f;
            s += e[k];
        }
#pragma unroll
        for (int o = 16; o; o >>= 1) s += __shfl_xor_sync(0xffffffffu, s, o);
        float inv = 1.0f / s;
#pragma unroll
        for (int k = 0; k < 4; k++) {
            int j = lane + 32 * k;
            if (j < C1) att[h * AS + j] = e[k] * inv;
        }
    }
    __syncthreads();

    // ---- wsum: warp = (hg, d-quarter); accumulators in regs -------------------
    unsigned long long A0 = 0ull, A1 = 0ull, A2 = 0ull, A3 = 0ull;
    {
        const unsigned long long* ce2 = (const unsigned long long*)ce;
        const float* a0 = att + (hg * 4 + 0) * AS;
        const float* a1 = att + (hg * 4 + 1) * AS;
        const float* a2 = att + (hg * 4 + 2) * AS;
        const float* a3 = att + (hg * 4 + 3) * AS;
        int idx = qq * 32 + lane;
        for (int j = 0; j < C1; j++) {
            unsigned long long c = ce2[j * 128 + idx];
            fma2(A0, pack2(a0[j]), c);
            fma2(A1, pack2(a1[j]), c);
            fma2(A2, pack2(a2[j]), c);
            fma2(A3, pack2(a3[j]), c);
        }
    }
    __syncthreads();   // ce reads done; region A reusable

    {
        int dbase = qq * 64 + lane * 2;
        U64F2 u0, u1, u2, u3;
        u0.u = A0; u1.u = A1; u2.u = A2; u3.u = A3;
        *(float2*)(w_s + (hg * 4 + 0) * WS + dbase) = u0.f;
        *(float2*)(w_s + (hg * 4 + 1) * WS + dbase) = u1.f;
        *(float2*)(w_s + (hg * 4 + 2) * WS + dbase) = u2.f;
        *(float2*)(w_s + (hg * 4 + 3) * WS + dbase) = u3.f;
    }
    __syncthreads();

    int c4 = t & 63, g = t >> 6;      // thread owns cols 4c4..4c4+3, d-group g
    int h4 = c4 >> 2;                 // head of those 4 columns

    // ---- gl[c] = sum_d Wv[d,c] * w[h(c)][d]  (coalesced float4 row loads) ----
    {
        const float4* wv4 = (const float4*)Wv;
        float4 acc = make_float4(0.f, 0.f, 0.f, 0.f);
        const float* wrow = w_s + h4 * WS;
        int d0 = g * 32;
#pragma unroll 8
        for (int i = 0; i < 32; i++) {
            int d = d0 + i;
            float4 wv = wv4[(size_t)d * 64 + c4];
            float wd = wrow[d];
            acc.x += wv.x * wd; acc.y += wv.y * wd;
            acc.z += wv.z * wd; acc.w += wv.w * wd;
        }
        ((float4*)scr)[g * 64 + c4] = acc;
    }
    __syncthreads();
    if (t < 256) {
        float s = 0.f;
#pragma unroll
        for (int gg = 0; gg < 8; gg++) s += scr[gg * 256 + t];
        gl[t] = s;
    }
    __syncthreads();

    // ---- tv[d] = sum_e M2T[e][d] * gl[e]  (go phase fused away) ---------------
    {
        const float4* m4 = (const float4*)g_M2T;
        float4 acc = make_float4(0.f, 0.f, 0.f, 0.f);
        int e0 = g * 32;
#pragma unroll 8
        for (int i = 0; i < 32; i++) {
            int e = e0 + i;
            float4 wv = m4[(size_t)e * 64 + c4];
            float ge = gl[e];
            acc.x += wv.x * ge; acc.y += wv.y * ge;
            acc.z += wv.z * ge; acc.w += wv.w * ge;
        }
        ((float4*)scr)[g * 64 + c4] = acc;
    }
    __syncthreads();
    if (t < 256) {
        float s = 0.f;
#pragma unroll
        for (int gg = 0; gg < 8; gg++) s += scr[gg * 256 + t];
        tv[t] = s;
    }
    __syncthreads();

    // ---- logits: ce re-read from gmem (L2) ------------------------------------
    {
        const float4* cg = (const float4*)(clus + (size_t)b * C1 * DD);
        const float4* tv4 = (const float4*)tv;
        float4 t0 = tv4[lane * 2], t1 = tv4[lane * 2 + 1];
        for (int j = warp; j < C1; j += 16) {
            float4 c0 = cg[j * 64 + lane * 2], c1 = cg[j * 64 + lane * 2 + 1];
            float s = dot4(t0, c0) + dot4(t1, c1);
#pragma unroll
            for (int o = 16; o; o >>= 1) s += __shfl_xor_sync(0xffffffffu, s, o);
            if (lane == 0) {
                float l = tanhf(s * (1.0f / 16.0f)) * 10.0f;
                lg[j] = vmi[j] ? NEGV : l;
            }
        }
    }
    __syncthreads();

    // ---- log_softmax + argmax (warp 0) ----------------------------------------
    if (warp == 0) {
        float m = -3.0e38f; int mi = 0x7fffffff;
        for (int j = lane; j < C1; j += 32) {
            float v = lg[j];
            if (v > m) { m = v; mi = j; }
        }
#pragma unroll
        for (int o = 16; o; o >>= 1) {
            float om = __shfl_xor_sync(0xffffffffu, m, o);
            int   oi = __shfl_xor_sync(0xffffffffu, mi, o);
            if (om > m || (om == m && oi < mi)) { m = om; mi = oi; }
        }
        float s = 0.f;
        for (int j = lane; j < C1; j += 32) s += expf(lg[j] - m);
#pragma unroll
        for (int o = 16; o; o >>= 1) s += __shfl_xor_sync(0xffffffffu, s, o);
        if (lane == 0) { red[0] = m + logf(s); seli[0] = mi; }
    }
    __syncthreads();

    // ---- outputs (uvc reduced inline from node partials) ----------------------
    int sel = seli[0];
    float lse = red[0];
    size_t oa = (size_t)b * 1024;
    if (t < 256) {
        float se = clus[(size_t)b * C1 * DD + (size_t)sel * 256 + t];
        int cb = (BB + b) * 4;
        float s = g_part[(size_t)(cb + 0) * 256 + t] + g_part[(size_t)(cb + 1) * 256 + t]
                + g_part[(size_t)(cb + 2) * 256 + t] + g_part[(size_t)(cb + 3) * 256 + t];
        float den = fmaxf((float)(g_cnt[cb] + g_cnt[cb + 1] + g_cnt[cb + 2] + g_cnt[cb + 3]), 1.0f);
        out[oa + t]       = s / den;
        out[oa + 512 + t] = se;
        out[262144 + (size_t)b * 256 + t] = se;
    } else {
        int d = t - 256;
        out[oa + 256 + d] = cur[(size_t)b * DD + d];
        out[oa + 768 + d] = depot[(size_t)b * DD + d];
    }
    if (t == 0) out[327680 + b] = (float)sel;
    if (t < C1) out[327936 + (size_t)b * C1 + t] = lg[t] - lse;
}

extern "C" void kernel_launch(void* const* d_in, const int* in_sizes, int n_in,
                              void* d_out, int out_size) {
    const float* depot = (const float*)d_in[0];
    const float* clus  = (const float*)d_in[1];
    const float* cur   = (const float*)d_in[2];
    const float* node  = (const float*)d_in[3];
    const void*  mask  = d_in[4];
    const void*  cmask = d_in[5];
    const void*  vmask = d_in[6];
    const float* Wq    = (const float*)d_in[7];
    const float* Wk    = (const float*)d_in[8];
    const float* Wv    = (const float*)d_in[9];
    const float* Wks   = (const float*)d_in[10];
    const float* Wo    = (const float*)d_in[11];
    float* out = (float*)d_out;

    cudaFuncSetAttribute(k_qu_prep, cudaFuncAttributeMaxDynamicSharedMemorySize, QU_SMEM_BYTES);
    cudaFuncSetAttribute(k_main, cudaFuncAttributeMaxDynamicSharedMemorySize, SMEM_BYTES);

    k_nodes_part<<<dim3(4, BB), 256>>>(node, mask, cmask);
    k_qu_prep<<<320, 256, QU_SMEM_BYTES>>>(cur, depot, Wq, Wk, Wks, Wo);
    k_main<<<BB, 512, SMEM_BYTES>>>(depot, clus, cur, vmask, mask, Wv, out);
}

// round 11
// speedup vs baseline: 1.1668x; 1.0462x over previous
#include <cuda_runtime.h>
#include <math.h>
#include <stdint.h>

#define BB  256
#define NN  1024
#define C1  101
#define DD  256
#define HH  16
#define NEGV (-1000000000.0f)
#define AS  104          // att row stride (floats)
#define WS  260          // w_s row stride (floats)

__device__ __align__(16) float g_u[BB * HH * DD];     // u[b][h][d]
__device__ __align__(16) float g_M2T[DD * DD];        // M2T[e][d] = sum_c Wks[d,c]*Wo[e,c]
__device__ __align__(16) float g_part[2 * BB * 4 * DD];
__device__ int g_cnt[2 * BB * 4];

__device__ __forceinline__ bool readb(const void* p, int idx, int mode) {
    if (mode == 0) return ((const unsigned char*)p)[idx] != 0;
    if (mode == 1) return ((const int*)p)[idx] != 0;
    return ((const float*)p)[idx] != 0.0f;
}

__device__ __forceinline__ float dot4(float4 a, float4 b) {
    return a.x * b.x + a.y * b.y + a.z * b.z + a.w * b.w;
}

__device__ __forceinline__ unsigned long long pack2(float x) {
    unsigned long long r;
    asm("mov.b64 %0, {%1, %1};" : "=l"(r) : "f"(x));
    return r;
}
__device__ __forceinline__ void fma2(unsigned long long& acc, unsigned long long a,
                                     unsigned long long b) {
    asm("fma.rn.f32x2 %0, %1, %2, %0;" : "+l"(acc) : "l"(a), "l"(b));
}
union U64F2 { unsigned long long u; float2 f; };

// bool-dtype probe on first 4KB of `mask`. Call from ALL threads (sync-or).
__device__ __forceinline__ int detect_mode(const void* m, int t) {
    int f32 = 0, u8 = 0;
    if (t < 256) {
        uint4 v = ((const uint4*)m)[t];
        unsigned w[4] = {v.x, v.y, v.z, v.w};
#pragma unroll
        for (int i = 0; i < 4; i++) {
            unsigned x = w[i];
            if (((x >> 24) & 0xffu) == 0x3fu || ((x >> 16) & 0xffu) == 0x3fu ||
                ((x >> 8) & 0xffu) == 0x3fu || (x & 0xffu) == 0x3fu) f32 = 1;
            if (x & 0xffffff00u) u8 = 1;
        }
    }
    int a = __syncthreads_or(f32);
    int b = __syncthreads_or(u8);
    return a ? 2 : (b ? 0 : 1);
}

// ---------------- Kernel 1: node partial sums (1024 CTAs) --------------------
// Rows with mask=1 contribute to NEITHER mean (mc = m|c superset) -> skip the
// 1KB row load entirely (warp-uniform branch, ~20% DRAM traffic removed).
__global__ void __launch_bounds__(256) k_nodes_part(
    const float* __restrict__ node, const void* __restrict__ mask,
    const void* __restrict__ cmask)
{
    __shared__ unsigned char code[256];
    __shared__ float4 part[2][4][64];

    int q = blockIdx.x, b = blockIdx.y, t = threadIdx.x;
    int mode = detect_mode(mask, t);

    int gidx = b * NN + q * 256 + t;
    bool m  = readb(mask,  gidx, mode);
    bool mc = m | readb(cmask, gidx, mode);
    code[t] = (unsigned char)((m ? 1 : 0) | (mc ? 2 : 0));
    int c0 = __syncthreads_count(!m);
    int c1 = __syncthreads_count(!mc);

    int chunk = t >> 6, d4 = t & 63;
    const float4* np4 = (const float4*)(node + (size_t)b * NN * DD);
    float4 s0 = make_float4(0.f, 0.f, 0.f, 0.f), s1 = s0;
    int n0 = chunk * 64;
#pragma unroll 8
    for (int i = 0; i < 64; i++) {
        int n = n0 + i;
        unsigned char c = code[n];
        if (c & 1) continue;   // masked: in neither mean; skip the row load
        float4 v = __ldcs(&np4[(size_t)(q * 256 + n) * 64 + d4]);
        s0.x += v.x; s0.y += v.y; s0.z += v.z; s0.w += v.w;
        if (!(c & 2)) { s1.x += v.x; s1.y += v.y; s1.z += v.z; s1.w += v.w; }
    }
    part[0][chunk][d4] = s0;
    part[1][chunk][d4] = s1;
    __syncthreads();

    if (t < 128) {
        int which = t >> 6, d = t & 63;
        float4 r = make_float4(0.f, 0.f, 0.f, 0.f);
#pragma unroll
        for (int c = 0; c < 4; c++) {
            float4 a = part[which][c][d];
            r.x += a.x; r.y += a.y; r.z += a.z; r.w += a.w;
        }
        ((float4*)g_part)[((which * BB + b) * 4 + q) * 64 + d] = r;
    }
    if (t == 0) {
        g_cnt[(0 * BB + b) * 4 + q] = c0;
        g_cnt[(1 * BB + b) * 4 + q] = c1;
    }
}

// ---------------- Kernel 2: q + u (CTAs 0..255)  +  M2T prep (CTAs 256..319) -
#define QU_SMEM_BYTES 66560

__global__ void __launch_bounds__(256) k_qu_prep(
    const float* __restrict__ cur, const float* __restrict__ depot,
    const float* __restrict__ Wq,  const float* __restrict__ Wk,
    const float* __restrict__ Wks, const float* __restrict__ Wo)
{
    extern __shared__ __align__(16) float sm[];
    int bx = blockIdx.x;
    int t = threadIdx.x;

    if (bx >= 256) {
        // ---- prep role: M2T[e][d] = sum_c Wks[d,c] * Wo[e,c] ---------------
        float* a_sh = sm;            // 32 * 260
        float* b_sh = sm + 8320;     // 32 * 260
        int tile = bx - 256;
        int tj = tile & 7;   // d tile
        int ti = tile >> 3;  // e tile

        for (int i = t; i < 2048; i += 256) {
            int r = i >> 6, c4 = i & 63;
            float4 av = ((const float4*)(Wks + (size_t)(tj * 32 + r) * 256))[c4];
            float4 bv = ((const float4*)(Wo  + (size_t)(ti * 32 + r) * 256))[c4];
            *(float4*)(a_sh + r * 260 + c4 * 4) = av;
            *(float4*)(b_sh + r * 260 + c4 * 4) = bv;
        }
        __syncthreads();

        int el = t >> 3;
        int dl = (t & 7) * 4;
        float acc0 = 0.f, acc1 = 0.f, acc2 = 0.f, acc3 = 0.f;
        const float* br = b_sh + el * 260;
        const float* a0 = a_sh + (dl + 0) * 260;
        const float* a1 = a_sh + (dl + 1) * 260;
        const float* a2 = a_sh + (dl + 2) * 260;
        const float* a3 = a_sh + (dl + 3) * 260;
#pragma unroll 8
        for (int c = 0; c < 256; c++) {
            float bv = br[c];
            acc0 += a0[c] * bv;
            acc1 += a1[c] * bv;
            acc2 += a2[c] * bv;
            acc3 += a3[c] * bv;
        }
        *(float4*)(g_M2T + (size_t)(ti * 32 + el) * 256 + tj * 32 + dl) =
            make_float4(acc0, acc1, acc2, acc3);
        return;
    }

    // ---- qu role ------------------------------------------------------------
    float* ctx_base = sm;                       // 8 x 768
    float* qp_base  = sm + 6144;                // 8 x 8 x 32
    float* q_base   = sm + 6144 + 2048;         // 8 x 32
    float* den_s    = sm + 6144 + 2048 + 256;   // 8

    int cx = bx & 7;        // 0..7 : 32-col slice = 2 heads
    int by = bx >> 3;       // 0..31: 8 batches
    int lane = t & 31, w = t >> 5;

    if (t < 8) {
        int b = by * 8 + t;
        int c = g_cnt[b * 4 + 0] + g_cnt[b * 4 + 1] + g_cnt[b * 4 + 2] + g_cnt[b * 4 + 3];
        den_s[t] = fmaxf((float)c, 1.0f);
    }
    __syncthreads();

    for (int i = t; i < 8 * 256; i += 256) {
        int bi = i >> 8, d = i & 255;
        int b = by * 8 + bi;
        float s = g_part[(size_t)(b * 4 + 0) * 256 + d] + g_part[(size_t)(b * 4 + 1) * 256 + d]
                + g_part[(size_t)(b * 4 + 2) * 256 + d] + g_part[(size_t)(b * 4 + 3) * 256 + d];
        ctx_base[bi * 768 + d]       = s / den_s[bi];
        ctx_base[bi * 768 + 256 + d] = cur[(size_t)b * DD + d];
        ctx_base[bi * 768 + 512 + d] = depot[(size_t)b * DD + d];
    }
    __syncthreads();

    {
        int c = cx * 32 + lane;
        float acc[8];
#pragma unroll
        for (int bi = 0; bi < 8; bi++) acc[bi] = 0.f;
        int k0 = w * 96;
        for (int k = k0; k < k0 + 96; k += 4) {
            float w0 = Wq[(size_t)(k + 0) * 256 + c];
            float w1 = Wq[(size_t)(k + 1) * 256 + c];
            float w2 = Wq[(size_t)(k + 2) * 256 + c];
            float w3 = Wq[(size_t)(k + 3) * 256 + c];
#pragma unroll
            for (int bi = 0; bi < 8; bi++) {
                const float* cb = ctx_base + bi * 768;
                acc[bi] += w0 * cb[k] + w1 * cb[k + 1]
                         + w2 * cb[k + 2] + w3 * cb[k + 3];
            }
        }
#pragma unroll
        for (int bi = 0; bi < 8; bi++) qp_base[(w * 8 + bi) * 32 + lane] = acc[bi];
    }
    __syncthreads();

    {
        int bi = w;
        float s = 0.f;
#pragma unroll
        for (int ww = 0; ww < 8; ww++) s += qp_base[(ww * 8 + bi) * 32 + lane];
        q_base[bi * 32 + lane] = s;
    }
    __syncthreads();

    int d = t;
    const float4* wk = (const float4*)(Wk + (size_t)d * 256 + cx * 32);
#pragma unroll
    for (int hl = 0; hl < 2; hl++) {
        float4 w0 = wk[hl * 4], w1 = wk[hl * 4 + 1], w2 = wk[hl * 4 + 2], w3 = wk[hl * 4 + 3];
#pragma unroll
        for (int bi = 0; bi < 8; bi++) {
            const float4* qv = (const float4*)(q_base + bi * 32 + hl * 16);
            float s = dot4(w0, qv[0]) + dot4(w1, qv[1]) + dot4(w2, qv[2]) + dot4(w3, qv[3]);
            g_u[(size_t)(by * 8 + bi) * (HH * DD) + (cx * 2 + hl) * 256 + d] = s;
        }
    }
}

// SMEM layout (bytes). Region A holds ce; reused after wsum for w/gl/tv/scr.
#define OFF_A    0
#define A_BYTES  (C1 * DD * 4)                  // 103424
#define A_W      0                              // 16 * 260 * 4 = 16640
#define A_GL     16640
#define A_TV     (A_GL + 1024)
#define A_SCR    (A_TV + 1024)                  // 8 * 256 * 4 = 8192
#define OFF_ATT  A_BYTES                        // 16 * 104 * 4 = 6656
#define OFF_LG   (OFF_ATT + HH * AS * 4)
#define OFF_RED  (OFF_LG + 104 * 4)
#define OFF_VMI  (OFF_RED + 16)
#define OFF_SEL  (OFF_VMI + 104 * 4)
#define SMEM_BYTES (OFF_SEL + 16)               // 110944

// ---------------- Kernel 3: fused per-batch chain, occ 2 ---------------------
__global__ void __launch_bounds__(512, 2) k_main(
    const float* __restrict__ depot, const float* __restrict__ clus,
    const float* __restrict__ cur,   const void*  __restrict__ vmask,
    const void*  __restrict__ mask,
    const float* __restrict__ Wv,    float* __restrict__ out)
{
    extern __shared__ __align__(16) char smraw[];
    float* ce   = (float*)(smraw + OFF_A);
    float* w_s  = (float*)(smraw + A_W);
    float* gl   = (float*)(smraw + A_GL);
    float* tv   = (float*)(smraw + A_TV);
    float* scr  = (float*)(smraw + A_SCR);
    float* att  = (float*)(smraw + OFF_ATT);
    float* lg   = (float*)(smraw + OFF_LG);
    float* red  = (float*)(smraw + OFF_RED);
    int*   vmi  = (int*)(smraw + OFF_VMI);
    int*   seli = (int*)(smraw + OFF_SEL);

    int b = blockIdx.x, t = threadIdx.x;
    int lane = t & 31, warp = t >> 5;

    int mode = detect_mode(mask, t);

    // ce -> SMEM
    {
        const float4* cg = (const float4*)(clus + (size_t)b * C1 * DD);
        float4* d4 = (float4*)ce;
        for (int i = t; i < C1 * DD / 4; i += 512) d4[i] = cg[i];
    }
    if (t < C1) vmi[t] = readb(vmask, b * C1 + t, mode) ? 1 : 0;
    __syncthreads();
    if (t == 0) {
        int all = 1;
        for (int j = 1; j < C1; j++) all &= vmi[j];
        vmi[0] = !all;
    }
    __syncthreads();

    const float4* ce4 = (const float4*)ce;
    int hg = warp & 3;       // head group: heads hg*4 .. hg*4+3
    int qq = warp >> 2;      // quarter index 0..3

    // ---- scores: warp = (hg, j-quarter); 4 heads in ONE pass -----------------
    {
        int jbeg = qq * 26;
        int jend = (qq == 3) ? C1 : jbeg + 26;
        const float4* up = (const float4*)(g_u + (size_t)b * (HH * DD));
        float4 ua[4], ub[4];
#pragma unroll
        for (int h = 0; h < 4; h++) {
            ua[h] = up[(hg * 4 + h) * 64 + lane * 2];
            ub[h] = up[(hg * 4 + h) * 64 + lane * 2 + 1];
        }
        for (int j = jbeg; j < jend; j++) {
            float4 c0 = ce4[j * 64 + lane * 2], c1 = ce4[j * 64 + lane * 2 + 1];
            float p0 = dot4(ua[0], c0) + dot4(ub[0], c1);
            float p1 = dot4(ua[1], c0) + dot4(ub[1], c1);
            float p2 = dot4(ua[2], c0) + dot4(ub[2], c1);
            float p3 = dot4(ua[3], c0) + dot4(ub[3], c1);
#pragma unroll
            for (int o = 16; o; o >>= 1) {
                p0 += __shfl_xor_sync(0xffffffffu, p0, o);
                p1 += __shfl_xor_sync(0xffffffffu, p1, o);
                p2 += __shfl_xor_sync(0xffffffffu, p2, o);
                p3 += __shfl_xor_sync(0xffffffffu, p3, o);
            }
            if (lane == 0) {
                int msk = vmi[j];
                att[(hg * 4 + 0) * AS + j] = msk ? NEGV : p0 * 0.25f;
                att[(hg * 4 + 1) * AS + j] = msk ? NEGV : p1 * 0.25f;
                att[(hg * 4 + 2) * AS + j] = msk ? NEGV : p2 * 0.25f;
                att[(hg * 4 + 3) * AS + j] = msk ? NEGV : p3 * 0.25f;
            }
        }
    }
    __syncthreads();

    // ---- softmax: warp = head ------------------------------------------------
    {
        int h = warp;
        float v[4];
#pragma unroll
        for (int k = 0; k < 4; k++) {
            int j = lane + 32 * k;
            v[k] = (j < C1) ? att[h * AS + j] : -3.0e38f;
        }
        float m = fmaxf(fmaxf(v[0], v[1]), fmaxf(v[2], v[3]));
#pragma unroll
        for (int o = 16; o; o >>= 1) m = fmaxf(m, __shfl_xor_sync(0xffffffffu, m, o));
        float e[4], s = 0.f;
#pragma unroll
        for (int k = 0; k < 4; k++) {
            int j = lane + 32 * k;
            e[k] = (j < C1) ? expf(v[k] - m) : 0.f;
            s += e[k];
        }
#pragma unroll
        for (int o = 16; o; o >>= 1) s += __shfl_xor_sync(0xffffffffu, s, o);
        float inv = 1.0f / s;
#pragma unroll
        for (int k = 0; k < 4; k++) {
            int j = lane + 32 * k;
            if (j < C1) att[h * AS + j] = e[k] * inv;
        }
    }
    __syncthreads();

    // ---- wsum: warp = (hg, d-quarter); accumulators in regs -------------------
    unsigned long long A0 = 0ull, A1 = 0ull, A2 = 0ull, A3 = 0ull;
    {
        const unsigned long long* ce2 = (const unsigned long long*)ce;
        const float* a0 = att + (hg * 4 + 0) * AS;
        const float* a1 = att + (hg * 4 + 1) * AS;
        const float* a2 = att + (hg * 4 + 2) * AS;
        const float* a3 = att + (hg * 4 + 3) * AS;
        int idx = qq * 32 + lane;
        for (int j = 0; j < C1; j++) {
            unsigned long long c = ce2[j * 128 + idx];
            fma2(A0, pack2(a0[j]), c);
            fma2(A1, pack2(a1[j]), c);
            fma2(A2, pack2(a2[j]), c);
            fma2(A3, pack2(a3[j]), c);
        }
    }
    __syncthreads();   // ce reads done; region A reusable

    {
        int dbase = qq * 64 + lane * 2;
        U64F2 u0, u1, u2, u3;
        u0.u = A0; u1.u = A1; u2.u = A2; u3.u = A3;
        *(float2*)(w_s + (hg * 4 + 0) * WS + dbase) = u0.f;
        *(float2*)(w_s + (hg * 4 + 1) * WS + dbase) = u1.f;
        *(float2*)(w_s + (hg * 4 + 2) * WS + dbase) = u2.f;
        *(float2*)(w_s + (hg * 4 + 3) * WS + dbase) = u3.f;
    }
    __syncthreads();

    int c4 = t & 63, g = t >> 6;      // thread owns cols 4c4..4c4+3, d-group g
    int h4 = c4 >> 2;                 // head of those 4 columns

    // ---- gl[c] = sum_d Wv[d,c] * w[h(c)][d]  (coalesced float4 row loads) ----
    {
        const float4* wv4 = (const float4*)Wv;
        float4 acc = make_float4(0.f, 0.f, 0.f, 0.f);
        const float* wrow = w_s + h4 * WS;
        int d0 = g * 32;
#pragma unroll 8
        for (int i = 0; i < 32; i++) {
            int d = d0 + i;
            float4 wv = wv4[(size_t)d * 64 + c4];
            float wd = wrow[d];
            acc.x += wv.x * wd; acc.y += wv.y * wd;
            acc.z += wv.z * wd; acc.w += wv.w * wd;
        }
        ((float4*)scr)[g * 64 + c4] = acc;
    }
    __syncthreads();
    if (t < 256) {
        float s = 0.f;
#pragma unroll
        for (int gg = 0; gg < 8; gg++) s += scr[gg * 256 + t];
        gl[t] = s;
    }
    __syncthreads();

    // ---- tv[d] = sum_e M2T[e][d] * gl[e]  (go phase fused away) ---------------
    {
        const float4* m4 = (const float4*)g_M2T;
        float4 acc = make_float4(0.f, 0.f, 0.f, 0.f);
        int e0 = g * 32;
#pragma unroll 8
        for (int i = 0; i < 32; i++) {
            int e = e0 + i;
            float4 wv = m4[(size_t)e * 64 + c4];
            float ge = gl[e];
            acc.x += wv.x * ge; acc.y += wv.y * ge;
            acc.z += wv.z * ge; acc.w += wv.w * ge;
        }
        ((float4*)scr)[g * 64 + c4] = acc;
    }
    __syncthreads();
    if (t < 256) {
        float s = 0.f;
#pragma unroll
        for (int gg = 0; gg < 8; gg++) s += scr[gg * 256 + t];
        tv[t] = s;
    }
    __syncthreads();

    // ---- logits: ce re-read from gmem (L2) ------------------------------------
    {
        const float4* cg = (const float4*)(clus + (size_t)b * C1 * DD);
        const float4* tv4 = (const float4*)tv;
        float4 t0 = tv4[lane * 2], t1 = tv4[lane * 2 + 1];
        for (int j = warp; j < C1; j += 16) {
            float4 c0 = cg[j * 64 + lane * 2], c1 = cg[j * 64 + lane * 2 + 1];
            float s = dot4(t0, c0) + dot4(t1, c1);
#pragma unroll
            for (int o = 16; o; o >>= 1) s += __shfl_xor_sync(0xffffffffu, s, o);
            if (lane == 0) {
                float l = tanhf(s * (1.0f / 16.0f)) * 10.0f;
                lg[j] = vmi[j] ? NEGV : l;
            }
        }
    }
    __syncthreads();

    // ---- log_softmax + argmax (warp 0) ----------------------------------------
    if (warp == 0) {
        float m = -3.0e38f; int mi = 0x7fffffff;
        for (int j = lane; j < C1; j += 32) {
            float v = lg[j];
            if (v > m) { m = v; mi = j; }
        }
#pragma unroll
        for (int o = 16; o; o >>= 1) {
            float om = __shfl_xor_sync(0xffffffffu, m, o);
            int   oi = __shfl_xor_sync(0xffffffffu, mi, o);
            if (om > m || (om == m && oi < mi)) { m = om; mi = oi; }
        }
        float s = 0.f;
        for (int j = lane; j < C1; j += 32) s += expf(lg[j] - m);
#pragma unroll
        for (int o = 16; o; o >>= 1) s += __shfl_xor_sync(0xffffffffu, s, o);
        if (lane == 0) { red[0] = m + logf(s); seli[0] = mi; }
    }
    __syncthreads();

    // ---- outputs (uvc reduced inline from node partials) ----------------------
    int sel = seli[0];
    float lse = red[0];
    size_t oa = (size_t)b * 1024;
    if (t < 256) {
        float se = clus[(size_t)b * C1 * DD + (size_t)sel * 256 + t];
        int cb = (BB + b) * 4;
        float s = g_part[(size_t)(cb + 0) * 256 + t] + g_part[(size_t)(cb + 1) * 256 + t]
                + g_part[(size_t)(cb + 2) * 256 + t] + g_part[(size_t)(cb + 3) * 256 + t];
        float den = fmaxf((float)(g_cnt[cb] + g_cnt[cb + 1] + g_cnt[cb + 2] + g_cnt[cb + 3]), 1.0f);
        out[oa + t]       = s / den;
        out[oa + 512 + t] = se;
        out[262144 + (size_t)b * 256 + t] = se;
    } else {
        int d = t - 256;
        out[oa + 256 + d] = cur[(size_t)b * DD + d];
        out[oa + 768 + d] = depot[(size_t)b * DD + d];
    }
    if (t == 0) out[327680 + b] = (float)sel;
    if (t < C1) out[327936 + (size_t)b * C1 + t] = lg[t] - lse;
}

extern "C" void kernel_launch(void* const* d_in, const int* in_sizes, int n_in,
                              void* d_out, int out_size) {
    const float* depot = (const float*)d_in[0];
    const float* clus  = (const float*)d_in[1];
    const float* cur   = (const float*)d_in[2];
    const float* node  = (const float*)d_in[3];
    const void*  mask  = d_in[4];
    const void*  cmask = d_in[5];
    const void*  vmask = d_in[6];
    const float* Wq    = (const float*)d_in[7];
    const float* Wk    = (const float*)d_in[8];
    const float* Wv    = (const float*)d_in[9];
    const float* Wks   = (const float*)d_in[10];
    const float* Wo    = (const float*)d_in[11];
    float* out = (float*)d_out;

    cudaFuncSetAttribute(k_qu_prep, cudaFuncAttributeMaxDynamicSharedMemorySize, QU_SMEM_BYTES);
    cudaFuncSetAttribute(k_main, cudaFuncAttributeMaxDynamicSharedMemorySize, SMEM_BYTES);

    k_nodes_part<<<dim3(4, BB), 256>>>(node, mask, cmask);
    k_qu_prep<<<320, 256, QU_SMEM_BYTES>>>(cur, depot, Wq, Wk, Wks, Wo);
    k_main<<<BB, 512, SMEM_BYTES>>>(depot, clus, cur, vmask, mask, Wv, out);
}

// round 12
// speedup vs baseline: 1.1927x; 1.0222x over previous
#include <cuda_runtime.h>
#include <math.h>
#include <stdint.h>

#define BB  256
#define NN  1024
#define C1  101
#define DD  256
#define HH  16
#define NEGV (-1000000000.0f)
#define AS  104          // att row stride (floats)
#define WS  260          // w_s row stride (floats)

__device__ __align__(16) float g_u[BB * HH * DD];     // u[b][h][d]
__device__ __align__(16) float g_M2T[DD * DD];        // M2T[e][d] = sum_c Wks[d,c]*Wo[e,c]
__device__ __align__(16) float g_part[2 * BB * 4 * DD];
__device__ int g_cnt[2 * BB * 4];

__device__ __forceinline__ bool readb(const void* p, int idx, int mode) {
    if (mode == 0) return ((const unsigned char*)p)[idx] != 0;
    if (mode == 1) return ((const int*)p)[idx] != 0;
    return ((const float*)p)[idx] != 0.0f;
}

__device__ __forceinline__ float dot4(float4 a, float4 b) {
    return a.x * b.x + a.y * b.y + a.z * b.z + a.w * b.w;
}

__device__ __forceinline__ unsigned long long pack2(float x) {
    unsigned long long r;
    asm("mov.b64 %0, {%1, %1};" : "=l"(r) : "f"(x));
    return r;
}
__device__ __forceinline__ void fma2(unsigned long long& acc, unsigned long long a,
                                     unsigned long long b) {
    asm("fma.rn.f32x2 %0, %1, %2, %0;" : "+l"(acc) : "l"(a), "l"(b));
}
union U64F2 { unsigned long long u; float2 f; };

// bool-dtype probe on first 4KB of `mask`. Call from ALL threads (sync-or).
__device__ __forceinline__ int detect_mode(const void* m, int t) {
    int f32 = 0, u8 = 0;
    if (t < 256) {
        uint4 v = ((const uint4*)m)[t];
        unsigned w[4] = {v.x, v.y, v.z, v.w};
#pragma unroll
        for (int i = 0; i < 4; i++) {
            unsigned x = w[i];
            if (((x >> 24) & 0xffu) == 0x3fu || ((x >> 16) & 0xffu) == 0x3fu ||
                ((x >> 8) & 0xffu) == 0x3fu || (x & 0xffu) == 0x3fu) f32 = 1;
            if (x & 0xffffff00u) u8 = 1;
        }
    }
    int a = __syncthreads_or(f32);
    int b = __syncthreads_or(u8);
    return a ? 2 : (b ? 0 : 1);
}

// ---------------- Kernel 1: node partial sums (1024 CTAs) --------------------
// Rows with mask=1 are in neither mean. Compact surviving row indices into a
// dense SMEM list, then run a branch-free unroll-4 load loop (MLP >= 4).
__global__ void __launch_bounds__(256) k_nodes_part(
    const float* __restrict__ node, const void* __restrict__ mask,
    const void* __restrict__ cmask)
{
    __shared__ int list0[256];    // n | (uvc-flag << 8)
    __shared__ int lcnt;
    __shared__ float4 part[2][4][64];

    int q = blockIdx.x, b = blockIdx.y, t = threadIdx.x;
    int mode = detect_mode(mask, t);

    if (t == 0) lcnt = 0;
    __syncthreads();

    int gidx = b * NN + q * 256 + t;
    bool m  = readb(mask,  gidx, mode);
    bool mc = m | readb(cmask, gidx, mode);
    if (!m) {
        int pos = atomicAdd(&lcnt, 1);
        list0[pos] = t | ((mc ? 0 : 1) << 8);
    }
    int c0 = __syncthreads_count(!m);
    int c1 = __syncthreads_count(!mc);

    int chunk = t >> 6, d4 = t & 63;
    const float4* np4 = (const float4*)(node + (size_t)(b * NN + q * 256) * DD);
    float4 s0 = make_float4(0.f, 0.f, 0.f, 0.f), s1 = s0;

    int cnt = c0;                      // == lcnt after sync
    int len4 = (cnt + 3) >> 2;
    int begin = chunk * len4;
    int end = begin + len4; if (end > cnt) end = cnt;

    int i = begin;
    for (; i + 4 <= end; i += 4) {
        int e0 = list0[i], e1 = list0[i + 1], e2 = list0[i + 2], e3 = list0[i + 3];
        float4 v0 = __ldcs(&np4[(size_t)(e0 & 255) * 64 + d4]);
        float4 v1 = __ldcs(&np4[(size_t)(e1 & 255) * 64 + d4]);
        float4 v2 = __ldcs(&np4[(size_t)(e2 & 255) * 64 + d4]);
        float4 v3 = __ldcs(&np4[(size_t)(e3 & 255) * 64 + d4]);
        s0.x += v0.x; s0.y += v0.y; s0.z += v0.z; s0.w += v0.w;
        if (e0 & 256) { s1.x += v0.x; s1.y += v0.y; s1.z += v0.z; s1.w += v0.w; }
        s0.x += v1.x; s0.y += v1.y; s0.z += v1.z; s0.w += v1.w;
        if (e1 & 256) { s1.x += v1.x; s1.y += v1.y; s1.z += v1.z; s1.w += v1.w; }
        s0.x += v2.x; s0.y += v2.y; s0.z += v2.z; s0.w += v2.w;
        if (e2 & 256) { s1.x += v2.x; s1.y += v2.y; s1.z += v2.z; s1.w += v2.w; }
        s0.x += v3.x; s0.y += v3.y; s0.z += v3.z; s0.w += v3.w;
        if (e3 & 256) { s1.x += v3.x; s1.y += v3.y; s1.z += v3.z; s1.w += v3.w; }
    }
    for (; i < end; i++) {
        int e = list0[i];
        float4 v = __ldcs(&np4[(size_t)(e & 255) * 64 + d4]);
        s0.x += v.x; s0.y += v.y; s0.z += v.z; s0.w += v.w;
        if (e & 256) { s1.x += v.x; s1.y += v.y; s1.z += v.z; s1.w += v.w; }
    }

    part[0][chunk][d4] = s0;
    part[1][chunk][d4] = s1;
    __syncthreads();

    if (t < 128) {
        int which = t >> 6, d = t & 63;
        float4 r = make_float4(0.f, 0.f, 0.f, 0.f);
#pragma unroll
        for (int c = 0; c < 4; c++) {
            float4 a = part[which][c][d];
            r.x += a.x; r.y += a.y; r.z += a.z; r.w += a.w;
        }
        ((float4*)g_part)[((which * BB + b) * 4 + q) * 64 + d] = r;
    }
    if (t == 0) {
        g_cnt[(0 * BB + b) * 4 + q] = c0;
        g_cnt[(1 * BB + b) * 4 + q] = c1;
    }
}

// ---------------- Kernel 2: q + u (CTAs 0..255)  +  M2T prep (CTAs 256..319) -
#define QU_SMEM_BYTES 66560

__global__ void __launch_bounds__(256) k_qu_prep(
    const float* __restrict__ cur, const float* __restrict__ depot,
    const float* __restrict__ Wq,  const float* __restrict__ Wk,
    const float* __restrict__ Wks, const float* __restrict__ Wo)
{
    extern __shared__ __align__(16) float sm[];
    int bx = blockIdx.x;
    int t = threadIdx.x;

    if (bx >= 256) {
        // ---- prep role: M2T[e][d] = sum_c Wks[d,c] * Wo[e,c] ---------------
        float* a_sh = sm;            // 32 * 260
        float* b_sh = sm + 8320;     // 32 * 260
        int tile = bx - 256;
        int tj = tile & 7;   // d tile
        int ti = tile >> 3;  // e tile

        for (int i = t; i < 2048; i += 256) {
            int r = i >> 6, c4 = i & 63;
            float4 av = ((const float4*)(Wks + (size_t)(tj * 32 + r) * 256))[c4];
            float4 bv = ((const float4*)(Wo  + (size_t)(ti * 32 + r) * 256))[c4];
            *(float4*)(a_sh + r * 260 + c4 * 4) = av;
            *(float4*)(b_sh + r * 260 + c4 * 4) = bv;
        }
        __syncthreads();

        int el = t >> 3;
        int dl = (t & 7) * 4;
        float acc0 = 0.f, acc1 = 0.f, acc2 = 0.f, acc3 = 0.f;
        const float* br = b_sh + el * 260;
        const float* a0 = a_sh + (dl + 0) * 260;
        const float* a1 = a_sh + (dl + 1) * 260;
        const float* a2 = a_sh + (dl + 2) * 260;
        const float* a3 = a_sh + (dl + 3) * 260;
#pragma unroll 8
        for (int c = 0; c < 256; c++) {
            float bv = br[c];
            acc0 += a0[c] * bv;
            acc1 += a1[c] * bv;
            acc2 += a2[c] * bv;
            acc3 += a3[c] * bv;
        }
        *(float4*)(g_M2T + (size_t)(ti * 32 + el) * 256 + tj * 32 + dl) =
            make_float4(acc0, acc1, acc2, acc3);
        return;
    }

    // ---- qu role ------------------------------------------------------------
    float* ctx_base = sm;                       // 8 x 768
    float* qp_base  = sm + 6144;                // 8 x 8 x 32
    float* q_base   = sm + 6144 + 2048;         // 8 x 32
    float* den_s    = sm + 6144 + 2048 + 256;   // 8

    int cx = bx & 7;        // 0..7 : 32-col slice = 2 heads
    int by = bx >> 3;       // 0..31: 8 batches
    int lane = t & 31, w = t >> 5;

    if (t < 8) {
        int b = by * 8 + t;
        int c = g_cnt[b * 4 + 0] + g_cnt[b * 4 + 1] + g_cnt[b * 4 + 2] + g_cnt[b * 4 + 3];
        den_s[t] = fmaxf((float)c, 1.0f);
    }
    __syncthreads();

    for (int i = t; i < 8 * 256; i += 256) {
        int bi = i >> 8, d = i & 255;
        int b = by * 8 + bi;
        float s = g_part[(size_t)(b * 4 + 0) * 256 + d] + g_part[(size_t)(b * 4 + 1) * 256 + d]
                + g_part[(size_t)(b * 4 + 2) * 256 + d] + g_part[(size_t)(b * 4 + 3) * 256 + d];
        ctx_base[bi * 768 + d]       = s / den_s[bi];
        ctx_base[bi * 768 + 256 + d] = cur[(size_t)b * DD + d];
        ctx_base[bi * 768 + 512 + d] = depot[(size_t)b * DD + d];
    }
    __syncthreads();

    {
        int c = cx * 32 + lane;
        float acc[8];
#pragma unroll
        for (int bi = 0; bi < 8; bi++) acc[bi] = 0.f;
        int k0 = w * 96;
        for (int k = k0; k < k0 + 96; k += 4) {
            float w0 = Wq[(size_t)(k + 0) * 256 + c];
            float w1 = Wq[(size_t)(k + 1) * 256 + c];
            float w2 = Wq[(size_t)(k + 2) * 256 + c];
            float w3 = Wq[(size_t)(k + 3) * 256 + c];
#pragma unroll
            for (int bi = 0; bi < 8; bi++) {
                const float* cb = ctx_base + bi * 768;
                acc[bi] += w0 * cb[k] + w1 * cb[k + 1]
                         + w2 * cb[k + 2] + w3 * cb[k + 3];
            }
        }
#pragma unroll
        for (int bi = 0; bi < 8; bi++) qp_base[(w * 8 + bi) * 32 + lane] = acc[bi];
    }
    __syncthreads();

    {
        int bi = w;
        float s = 0.f;
#pragma unroll
        for (int ww = 0; ww < 8; ww++) s += qp_base[(ww * 8 + bi) * 32 + lane];
        q_base[bi * 32 + lane] = s;
    }
    __syncthreads();

    int d = t;
    const float4* wk = (const float4*)(Wk + (size_t)d * 256 + cx * 32);
#pragma unroll
    for (int hl = 0; hl < 2; hl++) {
        float4 w0 = wk[hl * 4], w1 = wk[hl * 4 + 1], w2 = wk[hl * 4 + 2], w3 = wk[hl * 4 + 3];
#pragma unroll
        for (int bi = 0; bi < 8; bi++) {
            const float4* qv = (const float4*)(q_base + bi * 32 + hl * 16);
            float s = dot4(w0, qv[0]) + dot4(w1, qv[1]) + dot4(w2, qv[2]) + dot4(w3, qv[3]);
            g_u[(size_t)(by * 8 + bi) * (HH * DD) + (cx * 2 + hl) * 256 + d] = s;
        }
    }
}

// SMEM layout (bytes). Region A holds ce; reused after wsum for w/gl/tv/scr.
#define OFF_A    0
#define A_BYTES  (C1 * DD * 4)                  // 103424
#define A_W      0                              // 16 * 260 * 4 = 16640
#define A_GL     16640
#define A_TV     (A_GL + 1024)
#define A_SCR    (A_TV + 1024)                  // 8 * 256 * 4 = 8192
#define OFF_ATT  A_BYTES                        // 16 * 104 * 4 = 6656
#define OFF_LG   (OFF_ATT + HH * AS * 4)
#define OFF_RED  (OFF_LG + 104 * 4)
#define OFF_VMI  (OFF_RED + 16)
#define OFF_SEL  (OFF_VMI + 104 * 4)
#define SMEM_BYTES (OFF_SEL + 16)               // 110944

// ---------------- Kernel 3: fused per-batch chain, occ 2 ---------------------
__global__ void __launch_bounds__(512, 2) k_main(
    const float* __restrict__ depot, const float* __restrict__ clus,
    const float* __restrict__ cur,   const void*  __restrict__ vmask,
    const void*  __restrict__ mask,
    const float* __restrict__ Wv,    float* __restrict__ out)
{
    extern __shared__ __align__(16) char smraw[];
    float* ce   = (float*)(smraw + OFF_A);
    float* w_s  = (float*)(smraw + A_W);
    float* gl   = (float*)(smraw + A_GL);
    float* tv   = (float*)(smraw + A_TV);
    float* scr  = (float*)(smraw + A_SCR);
    float* att  = (float*)(smraw + OFF_ATT);
    float* lg   = (float*)(smraw + OFF_LG);
    float* red  = (float*)(smraw + OFF_RED);
    int*   vmi  = (int*)(smraw + OFF_VMI);
    int*   seli = (int*)(smraw + OFF_SEL);

    int b = blockIdx.x, t = threadIdx.x;
    int lane = t & 31, warp = t >> 5;

    int mode = detect_mode(mask, t);

    // ce -> SMEM
    {
        const float4* cg = (const float4*)(clus + (size_t)b * C1 * DD);
        float4* d4 = (float4*)ce;
        for (int i = t; i < C1 * DD / 4; i += 512) d4[i] = cg[i];
    }
    if (t < C1) vmi[t] = readb(vmask, b * C1 + t, mode) ? 1 : 0;
    __syncthreads();
    if (t == 0) {
        int all = 1;
        for (int j = 1; j < C1; j++) all &= vmi[j];
        vmi[0] = !all;
    }
    __syncthreads();

    const float4* ce4 = (const float4*)ce;
    int hg = warp & 3;       // head group: heads hg*4 .. hg*4+3
    int qq = warp >> 2;      // quarter index 0..3

    // ---- scores: warp = (hg, j-quarter); 4 heads in ONE pass -----------------
    {
        int jbeg = qq * 26;
        int jend = (qq == 3) ? C1 : jbeg + 26;
        const float4* up = (const float4*)(g_u + (size_t)b * (HH * DD));
        float4 ua[4], ub[4];
#pragma unroll
        for (int h = 0; h < 4; h++) {
            ua[h] = up[(hg * 4 + h) * 64 + lane * 2];
            ub[h] = up[(hg * 4 + h) * 64 + lane * 2 + 1];
        }
        for (int j = jbeg; j < jend; j++) {
            float4 c0 = ce4[j * 64 + lane * 2], c1 = ce4[j * 64 + lane * 2 + 1];
            float p0 = dot4(ua[0], c0) + dot4(ub[0], c1);
            float p1 = dot4(ua[1], c0) + dot4(ub[1], c1);
            float p2 = dot4(ua[2], c0) + dot4(ub[2], c1);
            float p3 = dot4(ua[3], c0) + dot4(ub[3], c1);
#pragma unroll
            for (int o = 16; o; o >>= 1) {
                p0 += __shfl_xor_sync(0xffffffffu, p0, o);
                p1 += __shfl_xor_sync(0xffffffffu, p1, o);
                p2 += __shfl_xor_sync(0xffffffffu, p2, o);
                p3 += __shfl_xor_sync(0xffffffffu, p3, o);
            }
            if (lane == 0) {
                int msk = vmi[j];
                att[(hg * 4 + 0) * AS + j] = msk ? NEGV : p0 * 0.25f;
                att[(hg * 4 + 1) * AS + j] = msk ? NEGV : p1 * 0.25f;
                att[(hg * 4 + 2) * AS + j] = msk ? NEGV : p2 * 0.25f;
                att[(hg * 4 + 3) * AS + j] = msk ? NEGV : p3 * 0.25f;
            }
        }
    }
    __syncthreads();

    // ---- softmax: warp = head ------------------------------------------------
    {
        int h = warp;
        float v[4];
#pragma unroll
        for (int k = 0; k < 4; k++) {
            int j = lane + 32 * k;
            v[k] = (j < C1) ? att[h * AS + j] : -3.0e38f;
        }
        float m = fmaxf(fmaxf(v[0], v[1]), fmaxf(v[2], v[3]));
#pragma unroll
        for (int o = 16; o; o >>= 1) m = fmaxf(m, __shfl_xor_sync(0xffffffffu, m, o));
        float e[4], s = 0.f;
#pragma unroll
        for (int k = 0; k < 4; k++) {
            int j = lane + 32 * k;
            e[k] = (j < C1) ? expf(v[k] - m) : 0.f;
            s += e[k];
        }
#pragma unroll
        for (int o = 16; o; o >>= 1) s += __shfl_xor_sync(0xffffffffu, s, o);
        float inv = 1.0f / s;
#pragma unroll
        for (int k = 0; k < 4; k++) {
            int j = lane + 32 * k;
            if (j < C1) att[h * AS + j] = e[k] * inv;
        }
    }
    __syncthreads();

    // ---- wsum: warp = (hg, d-quarter); accumulators in regs -------------------
    unsigned long long A0 = 0ull, A1 = 0ull, A2 = 0ull, A3 = 0ull;
    {
        const unsigned long long* ce2 = (const unsigned long long*)ce;
        const float* a0 = att + (hg * 4 + 0) * AS;
        const float* a1 = att + (hg * 4 + 1) * AS;
        const float* a2 = att + (hg * 4 + 2) * AS;
        const float* a3 = att + (hg * 4 + 3) * AS;
        int idx = qq * 32 + lane;
        for (int j = 0; j < C1; j++) {
            unsigned long long c = ce2[j * 128 + idx];
            fma2(A0, pack2(a0[j]), c);
            fma2(A1, pack2(a1[j]), c);
            fma2(A2, pack2(a2[j]), c);
            fma2(A3, pack2(a3[j]), c);
        }
    }
    __syncthreads();   // ce reads done; region A reusable

    {
        int dbase = qq * 64 + lane * 2;
        U64F2 u0, u1, u2, u3;
        u0.u = A0; u1.u = A1; u2.u = A2; u3.u = A3;
        *(float2*)(w_s + (hg * 4 + 0) * WS + dbase) = u0.f;
        *(float2*)(w_s + (hg * 4 + 1) * WS + dbase) = u1.f;
        *(float2*)(w_s + (hg * 4 + 2) * WS + dbase) = u2.f;
        *(float2*)(w_s + (hg * 4 + 3) * WS + dbase) = u3.f;
    }
    __syncthreads();

    int c4 = t & 63, g = t >> 6;      // thread owns cols 4c4..4c4+3, d-group g
    int h4 = c4 >> 2;                 // head of those 4 columns

    // ---- gl[c] = sum_d Wv[d,c] * w[h(c)][d]  (coalesced float4 row loads) ----
    {
        const float4* wv4 = (const float4*)Wv;
        float4 acc = make_float4(0.f, 0.f, 0.f, 0.f);
        const float* wrow = w_s + h4 * WS;
        int d0 = g * 32;
#pragma unroll 8
        for (int i = 0; i < 32; i++) {
            int d = d0 + i;
            float4 wv = wv4[(size_t)d * 64 + c4];
            float wd = wrow[d];
            acc.x += wv.x * wd; acc.y += wv.y * wd;
            acc.z += wv.z * wd; acc.w += wv.w * wd;
        }
        ((float4*)scr)[g * 64 + c4] = acc;
    }
    __syncthreads();
    if (t < 256) {
        float s = 0.f;
#pragma unroll
        for (int gg = 0; gg < 8; gg++) s += scr[gg * 256 + t];
        gl[t] = s;
    }
    __syncthreads();

    // ---- tv[d] = sum_e M2T[e][d] * gl[e]  (go phase fused away) ---------------
    {
        const float4* m4 = (const float4*)g_M2T;
        float4 acc = make_float4(0.f, 0.f, 0.f, 0.f);
        int e0 = g * 32;
#pragma unroll 8
        for (int i = 0; i < 32; i++) {
            int e = e0 + i;
            float4 wv = m4[(size_t)e * 64 + c4];
            float ge = gl[e];
            acc.x += wv.x * ge; acc.y += wv.y * ge;
            acc.z += wv.z * ge; acc.w += wv.w * ge;
        }
        ((float4*)scr)[g * 64 + c4] = acc;
    }
    __syncthreads();
    if (t < 256) {
        float s = 0.f;
#pragma unroll
        for (int gg = 0; gg < 8; gg++) s += scr[gg * 256 + t];
        tv[t] = s;
    }
    __syncthreads();

    // ---- logits: ce re-read from gmem (L2) ------------------------------------
    {
        const float4* cg = (const float4*)(clus + (size_t)b * C1 * DD);
        const float4* tv4 = (const float4*)tv;
        float4 t0 = tv4[lane * 2], t1 = tv4[lane * 2 + 1];
        for (int j = warp; j < C1; j += 16) {
            float4 c0 = cg[j * 64 + lane * 2], c1 = cg[j * 64 + lane * 2 + 1];
            float s = dot4(t0, c0) + dot4(t1, c1);
#pragma unroll
            for (int o = 16; o; o >>= 1) s += __shfl_xor_sync(0xffffffffu, s, o);
            if (lane == 0) {
                float l = tanhf(s * (1.0f / 16.0f)) * 10.0f;
                lg[j] = vmi[j] ? NEGV : l;
            }
        }
    }
    __syncthreads();

    // ---- log_softmax + argmax (warp 0) ----------------------------------------
    if (warp == 0) {
        float m = -3.0e38f; int mi = 0x7fffffff;
        for (int j = lane; j < C1; j += 32) {
            float v = lg[j];
            if (v > m) { m = v; mi = j; }
        }
#pragma unroll
        for (int o = 16; o; o >>= 1) {
            float om = __shfl_xor_sync(0xffffffffu, m, o);
            int   oi = __shfl_xor_sync(0xffffffffu, mi, o);
            if (om > m || (om == m && oi < mi)) { m = om; mi = oi; }
        }
        float s = 0.f;
        for (int j = lane; j < C1; j += 32) s += expf(lg[j] - m);
#pragma unroll
        for (int o = 16; o; o >>= 1) s += __shfl_xor_sync(0xffffffffu, s, o);
        if (lane == 0) { red[0] = m + logf(s); seli[0] = mi; }
    }
    __syncthreads();

    // ---- outputs (uvc reduced inline from node partials) ----------------------
    int sel = seli[0];
    float lse = red[0];
    size_t oa = (size_t)b * 1024;
    if (t < 256) {
        float se = clus[(size_t)b * C1 * DD + (size_t)sel * 256 + t];
        int cb = (BB + b) * 4;
        float s = g_part[(size_t)(cb + 0) * 256 + t] + g_part[(size_t)(cb + 1) * 256 + t]
                + g_part[(size_t)(cb + 2) * 256 + t] + g_part[(size_t)(cb + 3) * 256 + t];
        float den = fmaxf((float)(g_cnt[cb] + g_cnt[cb + 1] + g_cnt[cb + 2] + g_cnt[cb + 3]), 1.0f);
        out[oa + t]       = s / den;
        out[oa + 512 + t] = se;
        out[262144 + (size_t)b * 256 + t] = se;
    } else {
        int d = t - 256;
        out[oa + 256 + d] = cur[(size_t)b * DD + d];
        out[oa + 768 + d] = depot[(size_t)b * DD + d];
    }
    if (t == 0) out[327680 + b] = (float)sel;
    if (t < C1) out[327936 + (size_t)b * C1 + t] = lg[t] - lse;
}

extern "C" void kernel_launch(void* const* d_in, const int* in_sizes, int n_in,
                              void* d_out, int out_size) {
    const float* depot = (const float*)d_in[0];
    const float* clus  = (const float*)d_in[1];
    const float* cur   = (const float*)d_in[2];
    const float* node  = (const float*)d_in[3];
    const void*  mask  = d_in[4];
    const void*  cmask = d_in[5];
    const void*  vmask = d_in[6];
    const float* Wq    = (const float*)d_in[7];
    const float* Wk    = (const float*)d_in[8];
    const float* Wv    = (const float*)d_in[9];
    const float* Wks   = (const float*)d_in[10];
    const float* Wo    = (const float*)d_in[11];
    float* out = (float*)d_out;

    cudaFuncSetAttribute(k_qu_prep, cudaFuncAttributeMaxDynamicSharedMemorySize, QU_SMEM_BYTES);
    cudaFuncSetAttribute(k_main, cudaFuncAttributeMaxDynamicSharedMemorySize, SMEM_BYTES);

    k_nodes_part<<<dim3(4, BB), 256>>>(node, mask, cmask);
    k_qu_prep<<<320, 256, QU_SMEM_BYTES>>>(cur, depot, Wq, Wk, Wks, Wo);
    k_main<<<BB, 512, SMEM_BYTES>>>(depot, clus, cur, vmask, mask, Wv, out);
}

// round 13
// speedup vs baseline: 1.2283x; 1.0298x over previous
#include <cuda_runtime.h>
#include <math.h>
#include <stdint.h>

#define BB  256
#define NN  1024
#define C1  101
#define DD  256
#define HH  16
#define NEGV (-1000000000.0f)
#define AS  104          // att row stride (floats)
#define WS  260          // w_s row stride (floats)

__device__ __align__(16) float g_u[BB * HH * DD];     // u[b][h][d]
__device__ __align__(16) float g_M2T[DD * DD];        // M2T[e][d] = sum_c Wks[d,c]*Wo[e,c]
__device__ __align__(16) float g_part[2 * BB * 4 * DD];
__device__ int g_cnt[2 * BB * 4];

__device__ __forceinline__ bool readb(const void* p, int idx, int mode) {
    if (mode == 0) return ((const unsigned char*)p)[idx] != 0;
    if (mode == 1) return ((const int*)p)[idx] != 0;
    return ((const float*)p)[idx] != 0.0f;
}

__device__ __forceinline__ float dot4(float4 a, float4 b) {
    return a.x * b.x + a.y * b.y + a.z * b.z + a.w * b.w;
}

__device__ __forceinline__ unsigned long long pack2(float x) {
    unsigned long long r;
    asm("mov.b64 %0, {%1, %1};" : "=l"(r) : "f"(x));
    return r;
}
__device__ __forceinline__ void fma2(unsigned long long& acc, unsigned long long a,
                                     unsigned long long b) {
    asm("fma.rn.f32x2 %0, %1, %2, %0;" : "+l"(acc) : "l"(a), "l"(b));
}
union U64F2 { unsigned long long u; float2 f; };

// bool-dtype probe on first 4KB of `mask`. Call from ALL threads (sync-or).
__device__ __forceinline__ int detect_mode(const void* m, int t) {
    int f32 = 0, u8 = 0;
    if (t < 256) {
        uint4 v = ((const uint4*)m)[t];
        unsigned w[4] = {v.x, v.y, v.z, v.w};
#pragma unroll
        for (int i = 0; i < 4; i++) {
            unsigned x = w[i];
            if (((x >> 24) & 0xffu) == 0x3fu || ((x >> 16) & 0xffu) == 0x3fu ||
                ((x >> 8) & 0xffu) == 0x3fu || (x & 0xffu) == 0x3fu) f32 = 1;
            if (x & 0xffffff00u) u8 = 1;
        }
    }
    int a = __syncthreads_or(f32);
    int b = __syncthreads_or(u8);
    return a ? 2 : (b ? 0 : 1);
}

// ---------------- Kernel 1: node partial sums (1024 CTAs) --------------------
// Compacted surviving-row list + unroll-8 loads (MLP ~8 per thread).
__global__ void __launch_bounds__(256) k_nodes_part(
    const float* __restrict__ node, const void* __restrict__ mask,
    const void* __restrict__ cmask)
{
    __shared__ int list0[256];    // n | (uvc-flag << 8)
    __shared__ int lcnt;
    __shared__ float4 part[2][4][64];

    int q = blockIdx.x, b = blockIdx.y, t = threadIdx.x;
    int mode = detect_mode(mask, t);

    if (t == 0) lcnt = 0;
    __syncthreads();

    int gidx = b * NN + q * 256 + t;
    bool m  = readb(mask,  gidx, mode);
    bool mc = m | readb(cmask, gidx, mode);
    if (!m) {
        int pos = atomicAdd(&lcnt, 1);
        list0[pos] = t | ((mc ? 0 : 1) << 8);
    }
    int c0 = __syncthreads_count(!m);
    int c1 = __syncthreads_count(!mc);

    int chunk = t >> 6, d4 = t & 63;
    const float4* np4 = (const float4*)(node + (size_t)(b * NN + q * 256) * DD);
    float4 s0 = make_float4(0.f, 0.f, 0.f, 0.f), s1 = s0;

    int cnt = c0;
    int len4 = (cnt + 3) >> 2;
    int begin = chunk * len4;
    int end = begin + len4; if (end > cnt) end = cnt;

    int i = begin;
    for (; i + 8 <= end; i += 8) {
        int e[8];
        float4 v[8];
#pragma unroll
        for (int k = 0; k < 8; k++) e[k] = list0[i + k];
#pragma unroll
        for (int k = 0; k < 8; k++) v[k] = __ldcs(&np4[(size_t)(e[k] & 255) * 64 + d4]);
#pragma unroll
        for (int k = 0; k < 8; k++) {
            s0.x += v[k].x; s0.y += v[k].y; s0.z += v[k].z; s0.w += v[k].w;
            if (e[k] & 256) {
                s1.x += v[k].x; s1.y += v[k].y; s1.z += v[k].z; s1.w += v[k].w;
            }
        }
    }
    for (; i < end; i++) {
        int e = list0[i];
        float4 v = __ldcs(&np4[(size_t)(e & 255) * 64 + d4]);
        s0.x += v.x; s0.y += v.y; s0.z += v.z; s0.w += v.w;
        if (e & 256) { s1.x += v.x; s1.y += v.y; s1.z += v.z; s1.w += v.w; }
    }

    part[0][chunk][d4] = s0;
    part[1][chunk][d4] = s1;
    __syncthreads();

    if (t < 128) {
        int which = t >> 6, d = t & 63;
        float4 r = make_float4(0.f, 0.f, 0.f, 0.f);
#pragma unroll
        for (int c = 0; c < 4; c++) {
            float4 a = part[which][c][d];
            r.x += a.x; r.y += a.y; r.z += a.z; r.w += a.w;
        }
        ((float4*)g_part)[((which * BB + b) * 4 + q) * 64 + d] = r;
    }
    if (t == 0) {
        g_cnt[(0 * BB + b) * 4 + q] = c0;
        g_cnt[(1 * BB + b) * 4 + q] = c1;
    }
}

// ---------------- Kernel 2: q + u (CTAs 0..255)  +  M2T prep (CTAs 256..319) -
#define QU_SMEM_BYTES 66560

__global__ void __launch_bounds__(256) k_qu_prep(
    const float* __restrict__ cur, const float* __restrict__ depot,
    const float* __restrict__ Wq,  const float* __restrict__ Wk,
    const float* __restrict__ Wks, const float* __restrict__ Wo)
{
    extern __shared__ __align__(16) float sm[];
    int bx = blockIdx.x;
    int t = threadIdx.x;

    if (bx >= 256) {
        // ---- prep role: M2T[e][d] = sum_c Wks[d,c] * Wo[e,c] ---------------
        float* a_sh = sm;            // 32 * 260
        float* b_sh = sm + 8320;     // 32 * 260
        int tile = bx - 256;
        int tj = tile & 7;   // d tile
        int ti = tile >> 3;  // e tile

        for (int i = t; i < 2048; i += 256) {
            int r = i >> 6, c4 = i & 63;
            float4 av = ((const float4*)(Wks + (size_t)(tj * 32 + r) * 256))[c4];
            float4 bv = ((const float4*)(Wo  + (size_t)(ti * 32 + r) * 256))[c4];
            *(float4*)(a_sh + r * 260 + c4 * 4) = av;
            *(float4*)(b_sh + r * 260 + c4 * 4) = bv;
        }
        __syncthreads();

        int el = t >> 3;
        int dl = (t & 7) * 4;
        float acc0 = 0.f, acc1 = 0.f, acc2 = 0.f, acc3 = 0.f;
        const float* br = b_sh + el * 260;
        const float* a0 = a_sh + (dl + 0) * 260;
        const float* a1 = a_sh + (dl + 1) * 260;
        const float* a2 = a_sh + (dl + 2) * 260;
        const float* a3 = a_sh + (dl + 3) * 260;
#pragma unroll 8
        for (int c = 0; c < 256; c++) {
            float bv = br[c];
            acc0 += a0[c] * bv;
            acc1 += a1[c] * bv;
            acc2 += a2[c] * bv;
            acc3 += a3[c] * bv;
        }
        *(float4*)(g_M2T + (size_t)(ti * 32 + el) * 256 + tj * 32 + dl) =
            make_float4(acc0, acc1, acc2, acc3);
        return;
    }

    // ---- qu role ------------------------------------------------------------
    float* ctx_base = sm;                       // 8 x 768
    float* qp_base  = sm + 6144;                // 8 x 8 x 32
    float* q_base   = sm + 6144 + 2048;         // 8 x 32
    float* den_s    = sm + 6144 + 2048 + 256;   // 8

    int cx = bx & 7;        // 0..7 : 32-col slice = 2 heads
    int by = bx >> 3;       // 0..31: 8 batches
    int lane = t & 31, w = t >> 5;

    if (t < 8) {
        int b = by * 8 + t;
        int c = g_cnt[b * 4 + 0] + g_cnt[b * 4 + 1] + g_cnt[b * 4 + 2] + g_cnt[b * 4 + 3];
        den_s[t] = fmaxf((float)c, 1.0f);
    }
    __syncthreads();

    for (int i = t; i < 8 * 256; i += 256) {
        int bi = i >> 8, d = i & 255;
        int b = by * 8 + bi;
        float s = g_part[(size_t)(b * 4 + 0) * 256 + d] + g_part[(size_t)(b * 4 + 1) * 256 + d]
                + g_part[(size_t)(b * 4 + 2) * 256 + d] + g_part[(size_t)(b * 4 + 3) * 256 + d];
        ctx_base[bi * 768 + d]       = s / den_s[bi];
        ctx_base[bi * 768 + 256 + d] = cur[(size_t)b * DD + d];
        ctx_base[bi * 768 + 512 + d] = depot[(size_t)b * DD + d];
    }
    __syncthreads();

    {
        int c = cx * 32 + lane;
        float acc[8];
#pragma unroll
        for (int bi = 0; bi < 8; bi++) acc[bi] = 0.f;
        int k0 = w * 96;
        for (int k = k0; k < k0 + 96; k += 4) {
            float w0 = Wq[(size_t)(k + 0) * 256 + c];
            float w1 = Wq[(size_t)(k + 1) * 256 + c];
            float w2 = Wq[(size_t)(k + 2) * 256 + c];
            float w3 = Wq[(size_t)(k + 3) * 256 + c];
#pragma unroll
            for (int bi = 0; bi < 8; bi++) {
                const float* cb = ctx_base + bi * 768;
                acc[bi] += w0 * cb[k] + w1 * cb[k + 1]
                         + w2 * cb[k + 2] + w3 * cb[k + 3];
            }
        }
#pragma unroll
        for (int bi = 0; bi < 8; bi++) qp_base[(w * 8 + bi) * 32 + lane] = acc[bi];
    }
    __syncthreads();

    {
        int bi = w;
        float s = 0.f;
#pragma unroll
        for (int ww = 0; ww < 8; ww++) s += qp_base[(ww * 8 + bi) * 32 + lane];
        q_base[bi * 32 + lane] = s;
    }
    __syncthreads();

    int d = t;
    const float4* wk = (const float4*)(Wk + (size_t)d * 256 + cx * 32);
#pragma unroll
    for (int hl = 0; hl < 2; hl++) {
        float4 w0 = wk[hl * 4], w1 = wk[hl * 4 + 1], w2 = wk[hl * 4 + 2], w3 = wk[hl * 4 + 3];
#pragma unroll
        for (int bi = 0; bi < 8; bi++) {
            const float4* qv = (const float4*)(q_base + bi * 32 + hl * 16);
            float s = dot4(w0, qv[0]) + dot4(w1, qv[1]) + dot4(w2, qv[2]) + dot4(w3, qv[3]);
            g_u[(size_t)(by * 8 + bi) * (HH * DD) + (cx * 2 + hl) * 256 + d] = s;
        }
    }
}

// SMEM layout (bytes). Region A holds ce; its TAIL is reused after wsum for
// w/gl/tv/scr, preserving ce rows 0..73 for the logits phase.
#define OFF_A    0
#define A_BYTES  (C1 * DD * 4)                  // 103424
#define A_W      76544                          // 16 * 260 * 4 = 16640
#define A_GL     (A_W + 16640)                  // 93184
#define A_TV     (A_GL + 1024)                  // 94208
#define A_SCR    (A_TV + 1024)                  // 95232 (+8192 = 103424)
#define SM_J_LIM 74                             // ce rows [0,74) intact
#define OFF_ATT  A_BYTES                        // 16 * 104 * 4 = 6656
#define OFF_LG   (OFF_ATT + HH * AS * 4)
#define OFF_RED  (OFF_LG + 104 * 4)
#define OFF_VMI  (OFF_RED + 16)
#define OFF_SEL  (OFF_VMI + 104 * 4)
#define SMEM_BYTES (OFF_SEL + 16)               // 110944

// ---------------- Kernel 3: fused per-batch chain, occ 2 ---------------------
__global__ void __launch_bounds__(512, 2) k_main(
    const float* __restrict__ depot, const float* __restrict__ clus,
    const float* __restrict__ cur,   const void*  __restrict__ vmask,
    const void*  __restrict__ mask,
    const float* __restrict__ Wv,    float* __restrict__ out)
{
    extern __shared__ __align__(16) char smraw[];
    float* ce   = (float*)(smraw + OFF_A);
    float* w_s  = (float*)(smraw + A_W);
    float* gl   = (float*)(smraw + A_GL);
    float* tv   = (float*)(smraw + A_TV);
    float* scr  = (float*)(smraw + A_SCR);
    float* att  = (float*)(smraw + OFF_ATT);
    float* lg   = (float*)(smraw + OFF_LG);
    float* red  = (float*)(smraw + OFF_RED);
    int*   vmi  = (int*)(smraw + OFF_VMI);
    int*   seli = (int*)(smraw + OFF_SEL);

    int b = blockIdx.x, t = threadIdx.x;
    int lane = t & 31, warp = t >> 5;

    int mode = detect_mode(mask, t);

    // ce -> SMEM
    {
        const float4* cg = (const float4*)(clus + (size_t)b * C1 * DD);
        float4* d4 = (float4*)ce;
        for (int i = t; i < C1 * DD / 4; i += 512) d4[i] = cg[i];
    }
    if (t < C1) vmi[t] = readb(vmask, b * C1 + t, mode) ? 1 : 0;
    __syncthreads();
    if (t == 0) {
        int all = 1;
        for (int j = 1; j < C1; j++) all &= vmi[j];
        vmi[0] = !all;
    }
    __syncthreads();

    const float4* ce4 = (const float4*)ce;
    int hg = warp & 3;       // head group: heads hg*4 .. hg*4+3
    int qq = warp >> 2;      // quarter index 0..3

    // ---- scores: warp = (hg, j-quarter); 4 heads in ONE pass -----------------
    {
        int jbeg = qq * 26;
        int jend = (qq == 3) ? C1 : jbeg + 26;
        const float4* up = (const float4*)(g_u + (size_t)b * (HH * DD));
        float4 ua[4], ub[4];
#pragma unroll
        for (int h = 0; h < 4; h++) {
            ua[h] = up[(hg * 4 + h) * 64 + lane * 2];
            ub[h] = up[(hg * 4 + h) * 64 + lane * 2 + 1];
        }
        for (int j = jbeg; j < jend; j++) {
            float4 c0 = ce4[j * 64 + lane * 2], c1 = ce4[j * 64 + lane * 2 + 1];
            float p0 = dot4(ua[0], c0) + dot4(ub[0], c1);
            float p1 = dot4(ua[1], c0) + dot4(ub[1], c1);
            float p2 = dot4(ua[2], c0) + dot4(ub[2], c1);
            float p3 = dot4(ua[3], c0) + dot4(ub[3], c1);
#pragma unroll
            for (int o = 16; o; o >>= 1) {
                p0 += __shfl_xor_sync(0xffffffffu, p0, o);
                p1 += __shfl_xor_sync(0xffffffffu, p1, o);
                p2 += __shfl_xor_sync(0xffffffffu, p2, o);
                p3 += __shfl_xor_sync(0xffffffffu, p3, o);
            }
            if (lane == 0) {
                int msk = vmi[j];
                att[(hg * 4 + 0) * AS + j] = msk ? NEGV : p0 * 0.25f;
                att[(hg * 4 + 1) * AS + j] = msk ? NEGV : p1 * 0.25f;
                att[(hg * 4 + 2) * AS + j] = msk ? NEGV : p2 * 0.25f;
                att[(hg * 4 + 3) * AS + j] = msk ? NEGV : p3 * 0.25f;
            }
        }
    }
    __syncthreads();

    // ---- softmax: warp = head ------------------------------------------------
    {
        int h = warp;
        float v[4];
#pragma unroll
        for (int k = 0; k < 4; k++) {
            int j = lane + 32 * k;
            v[k] = (j < C1) ? att[h * AS + j] : -3.0e38f;
        }
        float m = fmaxf(fmaxf(v[0], v[1]), fmaxf(v[2], v[3]));
#pragma unroll
        for (int o = 16; o; o >>= 1) m = fmaxf(m, __shfl_xor_sync(0xffffffffu, m, o));
        float e[4], s = 0.f;
#pragma unroll
        for (int k = 0; k < 4; k++) {
            int j = lane + 32 * k;
            e[k] = (j < C1) ? expf(v[k] - m) : 0.f;
            s += e[k];
        }
#pragma unroll
        for (int o = 16; o; o >>= 1) s += __shfl_xor_sync(0xffffffffu, s, o);
        float inv = 1.0f / s;
#pragma unroll
        for (int k = 0; k < 4; k++) {
            int j = lane + 32 * k;
            if (j < C1) att[h * AS + j] = e[k] * inv;
        }
    }
    __syncthreads();

    // ---- wsum: warp = (hg, d-quarter); accumulators in regs -------------------
    unsigned long long A0 = 0ull, A1 = 0ull, A2 = 0ull, A3 = 0ull;
    {
        const unsigned long long* ce2 = (const unsigned long long*)ce;
        const float* a0 = att + (hg * 4 + 0) * AS;
        const float* a1 = att + (hg * 4 + 1) * AS;
        const float* a2 = att + (hg * 4 + 2) * AS;
        const float* a3 = att + (hg * 4 + 3) * AS;
        int idx = qq * 32 + lane;
        for (int j = 0; j < C1; j++) {
            unsigned long long c = ce2[j * 128 + idx];
            fma2(A0, pack2(a0[j]), c);
            fma2(A1, pack2(a1[j]), c);
            fma2(A2, pack2(a2[j]), c);
            fma2(A3, pack2(a3[j]), c);
        }
    }
    __syncthreads();   // ce reads done; TAIL of region A reusable

    {
        int dbase = qq * 64 + lane * 2;
        U64F2 u0, u1, u2, u3;
        u0.u = A0; u1.u = A1; u2.u = A2; u3.u = A3;
        *(float2*)(w_s + (hg * 4 + 0) * WS + dbase) = u0.f;
        *(float2*)(w_s + (hg * 4 + 1) * WS + dbase) = u1.f;
        *(float2*)(w_s + (hg * 4 + 2) * WS + dbase) = u2.f;
        *(float2*)(w_s + (hg * 4 + 3) * WS + dbase) = u3.f;
    }
    __syncthreads();

    int c4 = t & 63, g = t >> 6;      // thread owns cols 4c4..4c4+3, d-group g
    int h4 = c4 >> 2;                 // head of those 4 columns

    // ---- gl[c] = sum_d Wv[d,c] * w[h(c)][d]  (coalesced float4 row loads) ----
    {
        const float4* wv4 = (const float4*)Wv;
        float4 acc = make_float4(0.f, 0.f, 0.f, 0.f);
        const float* wrow = w_s + h4 * WS;
        int d0 = g * 32;
#pragma unroll 8
        for (int i = 0; i < 32; i++) {
            int d = d0 + i;
            float4 wv = wv4[(size_t)d * 64 + c4];
            float wd = wrow[d];
            acc.x += wv.x * wd; acc.y += wv.y * wd;
            acc.z += wv.z * wd; acc.w += wv.w * wd;
        }
        ((float4*)scr)[g * 64 + c4] = acc;
    }
    __syncthreads();
    if (t < 256) {
        float s = 0.f;
#pragma unroll
        for (int gg = 0; gg < 8; gg++) s += scr[gg * 256 + t];
        gl[t] = s;
    }
    __syncthreads();

    // ---- tv[d] = sum_e M2T[e][d] * gl[e] ---------------------------------------
    {
        const float4* m4 = (const float4*)g_M2T;
        float4 acc = make_float4(0.f, 0.f, 0.f, 0.f);
        int e0 = g * 32;
#pragma unroll 8
        for (int i = 0; i < 32; i++) {
            int e = e0 + i;
            float4 wv = m4[(size_t)e * 64 + c4];
            float ge = gl[e];
            acc.x += wv.x * ge; acc.y += wv.y * ge;
            acc.z += wv.z * ge; acc.w += wv.w * ge;
        }
        ((float4*)scr)[g * 64 + c4] = acc;
    }
    __syncthreads();
    if (t < 256) {
        float s = 0.f;
#pragma unroll
        for (int gg = 0; gg < 8; gg++) s += scr[gg * 256 + t];
        tv[t] = s;
    }
    __syncthreads();

    // ---- logits: j<74 from SMEM ce, rest from gmem (L2) ------------------------
    {
        const float4* cg = (const float4*)(clus + (size_t)b * C1 * DD);
        const float4* tv4 = (const float4*)tv;
        float4 t0 = tv4[lane * 2], t1 = tv4[lane * 2 + 1];
        for (int j = warp; j < C1; j += 16) {
            const float4* src = (j < SM_J_LIM) ? ce4 : cg;
            float4 c0 = src[j * 64 + lane * 2], c1 = src[j * 64 + lane * 2 + 1];
            float s = dot4(t0, c0) + dot4(t1, c1);
#pragma unroll
            for (int o = 16; o; o >>= 1) s += __shfl_xor_sync(0xffffffffu, s, o);
            if (lane == 0) {
                float l = tanhf(s * (1.0f / 16.0f)) * 10.0f;
                lg[j] = vmi[j] ? NEGV : l;
            }
        }
    }
    __syncthreads();

    // ---- log_softmax + argmax (warp 0) ----------------------------------------
    if (warp == 0) {
        float m = -3.0e38f; int mi = 0x7fffffff;
        for (int j = lane; j < C1; j += 32) {
            float v = lg[j];
            if (v > m) { m = v; mi = j; }
        }
#pragma unroll
        for (int o = 16; o; o >>= 1) {
            float om = __shfl_xor_sync(0xffffffffu, m, o);
            int   oi = __shfl_xor_sync(0xffffffffu, mi, o);
            if (om > m || (om == m && oi < mi)) { m = om; mi = oi; }
        }
        float s = 0.f;
        for (int j = lane; j < C1; j += 32) s += expf(lg[j] - m);
#pragma unroll
        for (int o = 16; o; o >>= 1) s += __shfl_xor_sync(0xffffffffu, s, o);
        if (lane == 0) { red[0] = m + logf(s); seli[0] = mi; }
    }
    __syncthreads();

    // ---- outputs (uvc reduced inline from node partials) ----------------------
    int sel = seli[0];
    float lse = red[0];
    size_t oa = (size_t)b * 1024;
    if (t < 256) {
        float se = clus[(size_t)b * C1 * DD + (size_t)sel * 256 + t];
        int cb = (BB + b) * 4;
        float s = g_part[(size_t)(cb + 0) * 256 + t] + g_part[(size_t)(cb + 1) * 256 + t]
                + g_part[(size_t)(cb + 2) * 256 + t] + g_part[(size_t)(cb + 3) * 256 + t];
        float den = fmaxf((float)(g_cnt[cb] + g_cnt[cb + 1] + g_cnt[cb + 2] + g_cnt[cb + 3]), 1.0f);
        out[oa + t]       = s / den;
        out[oa + 512 + t] = se;
        out[262144 + (size_t)b * 256 + t] = se;
    } else {
        int d = t - 256;
        out[oa + 256 + d] = cur[(size_t)b * DD + d];
        out[oa + 768 + d] = depot[(size_t)b * DD + d];
    }
    if (t == 0) out[327680 + b] = (float)sel;
    if (t < C1) out[327936 + (size_t)b * C1 + t] = lg[t] - lse;
}

extern "C" void kernel_launch(void* const* d_in, const int* in_sizes, int n_in,
                              void* d_out, int out_size) {
    const float* depot = (const float*)d_in[0];
    const float* clus  = (const float*)d_in[1];
    const float* cur   = (const float*)d_in[2];
    const float* node  = (const float*)d_in[3];
    const void*  mask  = d_in[4];
    const void*  cmask = d_in[5];
    const void*  vmask = d_in[6];
    const float* Wq    = (const float*)d_in[7];
    const float* Wk    = (const float*)d_in[8];
    const float* Wv    = (const float*)d_in[9];
    const float* Wks   = (const float*)d_in[10];
    const float* Wo    = (const float*)d_in[11];
    float* out = (float*)d_out;

    cudaFuncSetAttribute(k_qu_prep, cudaFuncAttributeMaxDynamicSharedMemorySize, QU_SMEM_BYTES);
    cudaFuncSetAttribute(k_main, cudaFuncAttributeMaxDynamicSharedMemorySize, SMEM_BYTES);

    k_nodes_part<<<dim3(4, BB), 256>>>(node, mask, cmask);
    k_qu_prep<<<320, 256, QU_SMEM_BYTES>>>(cur, depot, Wq, Wk, Wks, Wo);
    k_main<<<BB, 512, SMEM_BYTES>>>(depot, clus, cur, vmask, mask, Wv, out);
}

// round 14
// speedup vs baseline: 1.2441x; 1.0129x over previous
#include <cuda_runtime.h>
#include <math.h>
#include <stdint.h>

#define BB  256
#define NN  1024
#define C1  101
#define DD  256
#define HH  16
#define NEGV (-1000000000.0f)
#define AS  104          // att row stride (floats)
#define WS  260          // w_s row stride (floats)

__device__ __align__(16) float g_u[BB * HH * DD];     // u[b][h][d]
__device__ __align__(16) float g_M2T[DD * DD];        // M2T[e][d] = sum_c Wks[d,c]*Wo[e,c]
__device__ __align__(16) float g_part[2 * BB * 4 * DD];
__device__ int g_cnt[2 * BB * 4];

__device__ __forceinline__ bool readb(const void* p, int idx, int mode) {
    if (mode == 0) return ((const unsigned char*)p)[idx] != 0;
    if (mode == 1) return ((const int*)p)[idx] != 0;
    return ((const float*)p)[idx] != 0.0f;
}

__device__ __forceinline__ float dot4(float4 a, float4 b) {
    return a.x * b.x + a.y * b.y + a.z * b.z + a.w * b.w;
}

__device__ __forceinline__ unsigned long long pack2(float x) {
    unsigned long long r;
    asm("mov.b64 %0, {%1, %1};" : "=l"(r) : "f"(x));
    return r;
}
__device__ __forceinline__ void fma2(unsigned long long& acc, unsigned long long a,
                                     unsigned long long b) {
    asm("fma.rn.f32x2 %0, %1, %2, %0;" : "+l"(acc) : "l"(a), "l"(b));
}
union U64F2 { unsigned long long u; float2 f; };

// bool-dtype probe on first 4KB of `mask`. Call from ALL threads (sync-or).
__device__ __forceinline__ int detect_mode(const void* m, int t) {
    int f32 = 0, u8 = 0;
    if (t < 256) {
        uint4 v = ((const uint4*)m)[t];
        unsigned w[4] = {v.x, v.y, v.z, v.w};
#pragma unroll
        for (int i = 0; i < 4; i++) {
            unsigned x = w[i];
            if (((x >> 24) & 0xffu) == 0x3fu || ((x >> 16) & 0xffu) == 0x3fu ||
                ((x >> 8) & 0xffu) == 0x3fu || (x & 0xffu) == 0x3fu) f32 = 1;
            if (x & 0xffffff00u) u8 = 1;
        }
    }
    int a = __syncthreads_or(f32);
    int b = __syncthreads_or(u8);
    return a ? 2 : (b ? 0 : 1);
}

// ---------------- Kernel 1: node partial sums (1024 CTAs) --------------------
__global__ void __launch_bounds__(256) k_nodes_part(
    const float* __restrict__ node, const void* __restrict__ mask,
    const void* __restrict__ cmask)
{
    __shared__ int list0[256];    // n | (uvc-flag << 8)
    __shared__ int lcnt;
    __shared__ float4 part[2][4][64];

    int q = blockIdx.x, b = blockIdx.y, t = threadIdx.x;
    int mode = detect_mode(mask, t);

    if (t == 0) lcnt = 0;
    __syncthreads();

    int gidx = b * NN + q * 256 + t;
    bool m  = readb(mask,  gidx, mode);
    bool mc = m | readb(cmask, gidx, mode);
    if (!m) {
        int pos = atomicAdd(&lcnt, 1);
        list0[pos] = t | ((mc ? 0 : 1) << 8);
    }
    int c0 = __syncthreads_count(!m);
    int c1 = __syncthreads_count(!mc);

    int chunk = t >> 6, d4 = t & 63;
    const float4* np4 = (const float4*)(node + (size_t)(b * NN + q * 256) * DD);
    float4 s0 = make_float4(0.f, 0.f, 0.f, 0.f), s1 = s0;

    int cnt = c0;
    int len4 = (cnt + 3) >> 2;
    int begin = chunk * len4;
    int end = begin + len4; if (end > cnt) end = cnt;

    int i = begin;
    for (; i + 8 <= end; i += 8) {
        int e[8];
        float4 v[8];
#pragma unroll
        for (int k = 0; k < 8; k++) e[k] = list0[i + k];
#pragma unroll
        for (int k = 0; k < 8; k++) v[k] = __ldcs(&np4[(size_t)(e[k] & 255) * 64 + d4]);
#pragma unroll
        for (int k = 0; k < 8; k++) {
            s0.x += v[k].x; s0.y += v[k].y; s0.z += v[k].z; s0.w += v[k].w;
            if (e[k] & 256) {
                s1.x += v[k].x; s1.y += v[k].y; s1.z += v[k].z; s1.w += v[k].w;
            }
        }
    }
    for (; i < end; i++) {
        int e = list0[i];
        float4 v = __ldcs(&np4[(size_t)(e & 255) * 64 + d4]);
        s0.x += v.x; s0.y += v.y; s0.z += v.z; s0.w += v.w;
        if (e & 256) { s1.x += v.x; s1.y += v.y; s1.z += v.z; s1.w += v.w; }
    }

    part[0][chunk][d4] = s0;
    part[1][chunk][d4] = s1;
    __syncthreads();

    if (t < 128) {
        int which = t >> 6, d = t & 63;
        float4 r = make_float4(0.f, 0.f, 0.f, 0.f);
#pragma unroll
        for (int c = 0; c < 4; c++) {
            float4 a = part[which][c][d];
            r.x += a.x; r.y += a.y; r.z += a.z; r.w += a.w;
        }
        ((float4*)g_part)[((which * BB + b) * 4 + q) * 64 + d] = r;
    }
    if (t == 0) {
        g_cnt[(0 * BB + b) * 4 + q] = c0;
        g_cnt[(1 * BB + b) * 4 + q] = c1;
    }
    // PDL: all dependent writes done
    cudaTriggerProgrammaticLaunchCompletion();
}

// ---------------- Kernel 2: q + u (CTAs 0..255)  +  M2T prep (CTAs 256..319) -
#define QU_SMEM_BYTES 66560

__global__ void __launch_bounds__(256) k_qu_prep(
    const float* __restrict__ cur, const float* __restrict__ depot,
    const float* __restrict__ Wq,  const float* __restrict__ Wk,
    const float* __restrict__ Wks, const float* __restrict__ Wo)
{
    extern __shared__ __align__(16) float sm[];
    int bx = blockIdx.x;
    int t = threadIdx.x;

    if (bx >= 256) {
        // ---- prep role: fully independent of k_nodes ------------------------
        float* a_sh = sm;            // 32 * 260
        float* b_sh = sm + 8320;     // 32 * 260
        int tile = bx - 256;
        int tj = tile & 7;   // d tile
        int ti = tile >> 3;  // e tile

        for (int i = t; i < 2048; i += 256) {
            int r = i >> 6, c4 = i & 63;
            float4 av = ((const float4*)(Wks + (size_t)(tj * 32 + r) * 256))[c4];
            float4 bv = ((const float4*)(Wo  + (size_t)(ti * 32 + r) * 256))[c4];
            *(float4*)(a_sh + r * 260 + c4 * 4) = av;
            *(float4*)(b_sh + r * 260 + c4 * 4) = bv;
        }
        __syncthreads();

        int el = t >> 3;
        int dl = (t & 7) * 4;
        float acc0 = 0.f, acc1 = 0.f, acc2 = 0.f, acc3 = 0.f;
        const float* br = b_sh + el * 260;
        const float* a0 = a_sh + (dl + 0) * 260;
        const float* a1 = a_sh + (dl + 1) * 260;
        const float* a2 = a_sh + (dl + 2) * 260;
        const float* a3 = a_sh + (dl + 3) * 260;
#pragma unroll 8
        for (int c = 0; c < 256; c++) {
            float bv = br[c];
            acc0 += a0[c] * bv;
            acc1 += a1[c] * bv;
            acc2 += a2[c] * bv;
            acc3 += a3[c] * bv;
        }
        *(float4*)(g_M2T + (size_t)(ti * 32 + el) * 256 + tj * 32 + dl) =
            make_float4(acc0, acc1, acc2, acc3);
        cudaTriggerProgrammaticLaunchCompletion();
        return;
    }

    // ---- qu role ------------------------------------------------------------
    float* ctx_base = sm;                       // 8 x 768
    float* qp_base  = sm + 6144;                // 8 x 8 x 32
    float* q_base   = sm + 6144 + 2048;         // 8 x 32
    float* den_s    = sm + 6144 + 2048 + 256;   // 8

    int cx = bx & 7;        // 0..7 : 32-col slice = 2 heads
    int by = bx >> 3;       // 0..31: 8 batches
    int lane = t & 31, w = t >> 5;

    // pre-sync prologue: fill cur/depot parts of ctx (inputs only)
    for (int i = t; i < 8 * 256; i += 256) {
        int bi = i >> 8, d = i & 255;
        int b = by * 8 + bi;
        ctx_base[bi * 768 + 256 + d] = cur[(size_t)b * DD + d];
        ctx_base[bi * 768 + 512 + d] = depot[(size_t)b * DD + d];
    }

    // wait for k_nodes' g_part/g_cnt
    cudaGridDependencySynchronize();

    if (t < 8) {
        int b = by * 8 + t;
        int c = g_cnt[b * 4 + 0] + g_cnt[b * 4 + 1] + g_cnt[b * 4 + 2] + g_cnt[b * 4 + 3];
        den_s[t] = fmaxf((float)c, 1.0f);
    }
    __syncthreads();

    for (int i = t; i < 8 * 256; i += 256) {
        int bi = i >> 8, d = i & 255;
        int b = by * 8 + bi;
        float s = g_part[(size_t)(b * 4 + 0) * 256 + d] + g_part[(size_t)(b * 4 + 1) * 256 + d]
                + g_part[(size_t)(b * 4 + 2) * 256 + d] + g_part[(size_t)(b * 4 + 3) * 256 + d];
        ctx_base[bi * 768 + d] = s / den_s[bi];
    }
    __syncthreads();

    {
        int c = cx * 32 + lane;
        float acc[8];
#pragma unroll
        for (int bi = 0; bi < 8; bi++) acc[bi] = 0.f;
        int k0 = w * 96;
        for (int k = k0; k < k0 + 96; k += 4) {
            float w0 = Wq[(size_t)(k + 0) * 256 + c];
            float w1 = Wq[(size_t)(k + 1) * 256 + c];
            float w2 = Wq[(size_t)(k + 2) * 256 + c];
            float w3 = Wq[(size_t)(k + 3) * 256 + c];
#pragma unroll
            for (int bi = 0; bi < 8; bi++) {
                const float* cb = ctx_base + bi * 768;
                acc[bi] += w0 * cb[k] + w1 * cb[k + 1]
                         + w2 * cb[k + 2] + w3 * cb[k + 3];
            }
        }
#pragma unroll
        for (int bi = 0; bi < 8; bi++) qp_base[(w * 8 + bi) * 32 + lane] = acc[bi];
    }
    __syncthreads();

    {
        int bi = w;
        float s = 0.f;
#pragma unroll
        for (int ww = 0; ww < 8; ww++) s += qp_base[(ww * 8 + bi) * 32 + lane];
        q_base[bi * 32 + lane] = s;
    }
    __syncthreads();

    int d = t;
    const float4* wk = (const float4*)(Wk + (size_t)d * 256 + cx * 32);
#pragma unroll
    for (int hl = 0; hl < 2; hl++) {
        float4 w0 = wk[hl * 4], w1 = wk[hl * 4 + 1], w2 = wk[hl * 4 + 2], w3 = wk[hl * 4 + 3];
#pragma unroll
        for (int bi = 0; bi < 8; bi++) {
            const float4* qv = (const float4*)(q_base + bi * 32 + hl * 16);
            float s = dot4(w0, qv[0]) + dot4(w1, qv[1]) + dot4(w2, qv[2]) + dot4(w3, qv[3]);
            g_u[(size_t)(by * 8 + bi) * (HH * DD) + (cx * 2 + hl) * 256 + d] = s;
        }
    }
    cudaTriggerProgrammaticLaunchCompletion();
}

// SMEM layout (bytes). Region A holds ce; its TAIL is reused after wsum for
// w/gl/tv/scr, preserving ce rows 0..73 for the logits phase.
#define OFF_A    0
#define A_BYTES  (C1 * DD * 4)                  // 103424
#define A_W      76544                          // 16 * 260 * 4 = 16640
#define A_GL     (A_W + 16640)                  // 93184
#define A_TV     (A_GL + 1024)                  // 94208
#define A_SCR    (A_TV + 1024)                  // 95232 (+8192 = 103424)
#define SM_J_LIM 74                             // ce rows [0,74) intact
#define OFF_ATT  A_BYTES                        // 16 * 104 * 4 = 6656
#define OFF_LG   (OFF_ATT + HH * AS * 4)
#define OFF_RED  (OFF_LG + 104 * 4)
#define OFF_VMI  (OFF_RED + 16)
#define OFF_SEL  (OFF_VMI + 104 * 4)
#define SMEM_BYTES (OFF_SEL + 16)               // 110944

// ---------------- Kernel 3: fused per-batch chain, occ 2 ---------------------
__global__ void __launch_bounds__(512, 2) k_main(
    const float* __restrict__ depot, const float* __restrict__ clus,
    const float* __restrict__ cur,   const void*  __restrict__ vmask,
    const void*  __restrict__ mask,
    const float* __restrict__ Wv,    float* __restrict__ out)
{
    extern __shared__ __align__(16) char smraw[];
    float* ce   = (float*)(smraw + OFF_A);
    float* w_s  = (float*)(smraw + A_W);
    float* gl   = (float*)(smraw + A_GL);
    float* tv   = (float*)(smraw + A_TV);
    float* scr  = (float*)(smraw + A_SCR);
    float* att  = (float*)(smraw + OFF_ATT);
    float* lg   = (float*)(smraw + OFF_LG);
    float* red  = (float*)(smraw + OFF_RED);
    int*   vmi  = (int*)(smraw + OFF_VMI);
    int*   seli = (int*)(smraw + OFF_SEL);

    int b = blockIdx.x, t = threadIdx.x;
    int lane = t & 31, warp = t >> 5;

    // pre-sync prologue: inputs only (ce tile, visited mask, mode)
    int mode = detect_mode(mask, t);
    {
        const float4* cg = (const float4*)(clus + (size_t)b * C1 * DD);
        float4* d4 = (float4*)ce;
        for (int i = t; i < C1 * DD / 4; i += 512) d4[i] = cg[i];
    }
    if (t < C1) vmi[t] = readb(vmask, b * C1 + t, mode) ? 1 : 0;
    __syncthreads();
    if (t == 0) {
        int all = 1;
        for (int j = 1; j < C1; j++) all &= vmi[j];
        vmi[0] = !all;
    }

    // wait for k_qu_prep's g_u / g_M2T (and k_nodes' g_part transitively)
    cudaGridDependencySynchronize();
    __syncthreads();

    const float4* ce4 = (const float4*)ce;
    int hg = warp & 3;       // head group: heads hg*4 .. hg*4+3
    int qq = warp >> 2;      // quarter index 0..3

    // ---- scores: warp = (hg, j-quarter); 4 heads in ONE pass -----------------
    {
        int jbeg = qq * 26;
        int jend = (qq == 3) ? C1 : jbeg + 26;
        const float4* up = (const float4*)(g_u + (size_t)b * (HH * DD));
        float4 ua[4], ub[4];
#pragma unroll
        for (int h = 0; h < 4; h++) {
            ua[h] = up[(hg * 4 + h) * 64 + lane * 2];
            ub[h] = up[(hg * 4 + h) * 64 + lane * 2 + 1];
        }
        for (int j = jbeg; j < jend; j++) {
            float4 c0 = ce4[j * 64 + lane * 2], c1 = ce4[j * 64 + lane * 2 + 1];
            float p0 = dot4(ua[0], c0) + dot4(ub[0], c1);
            float p1 = dot4(ua[1], c0) + dot4(ub[1], c1);
            float p2 = dot4(ua[2], c0) + dot4(ub[2], c1);
            float p3 = dot4(ua[3], c0) + dot4(ub[3], c1);
#pragma unroll
            for (int o = 16; o; o >>= 1) {
                p0 += __shfl_xor_sync(0xffffffffu, p0, o);
                p1 += __shfl_xor_sync(0xffffffffu, p1, o);
                p2 += __shfl_xor_sync(0xffffffffu, p2, o);
                p3 += __shfl_xor_sync(0xffffffffu, p3, o);
            }
            if (lane == 0) {
                int msk = vmi[j];
                att[(hg * 4 + 0) * AS + j] = msk ? NEGV : p0 * 0.25f;
                att[(hg * 4 + 1) * AS + j] = msk ? NEGV : p1 * 0.25f;
                att[(hg * 4 + 2) * AS + j] = msk ? NEGV : p2 * 0.25f;
                att[(hg * 4 + 3) * AS + j] = msk ? NEGV : p3 * 0.25f;
            }
        }
    }
    __syncthreads();

    // ---- softmax: warp = head ------------------------------------------------
    {
        int h = warp;
        float v[4];
#pragma unroll
        for (int k = 0; k < 4; k++) {
            int j = lane + 32 * k;
            v[k] = (j < C1) ? att[h * AS + j] : -3.0e38f;
        }
        float m = fmaxf(fmaxf(v[0], v[1]), fmaxf(v[2], v[3]));
#pragma unroll
        for (int o = 16; o; o >>= 1) m = fmaxf(m, __shfl_xor_sync(0xffffffffu, m, o));
        float e[4], s = 0.f;
#pragma unroll
        for (int k = 0; k < 4; k++) {
            int j = lane + 32 * k;
            e[k] = (j < C1) ? expf(v[k] - m) : 0.f;
            s += e[k];
        }
#pragma unroll
        for (int o = 16; o; o >>= 1) s += __shfl_xor_sync(0xffffffffu, s, o);
        float inv = 1.0f / s;
#pragma unroll
        for (int k = 0; k < 4; k++) {
            int j = lane + 32 * k;
            if (j < C1) att[h * AS + j] = e[k] * inv;
        }
    }
    __syncthreads();

    // ---- wsum: warp = (hg, d-quarter); accumulators in regs -------------------
    unsigned long long A0 = 0ull, A1 = 0ull, A2 = 0ull, A3 = 0ull;
    {
        const unsigned long long* ce2 = (const unsigned long long*)ce;
        const float* a0 = att + (hg * 4 + 0) * AS;
        const float* a1 = att + (hg * 4 + 1) * AS;
        const float* a2 = att + (hg * 4 + 2) * AS;
        const float* a3 = att + (hg * 4 + 3) * AS;
        int idx = qq * 32 + lane;
        for (int j = 0; j < C1; j++) {
            unsigned long long c = ce2[j * 128 + idx];
            fma2(A0, pack2(a0[j]), c);
            fma2(A1, pack2(a1[j]), c);
            fma2(A2, pack2(a2[j]), c);
            fma2(A3, pack2(a3[j]), c);
        }
    }
    __syncthreads();   // ce reads done; TAIL of region A reusable

    {
        int dbase = qq * 64 + lane * 2;
        U64F2 u0, u1, u2, u3;
        u0.u = A0; u1.u = A1; u2.u = A2; u3.u = A3;
        *(float2*)(w_s + (hg * 4 + 0) * WS + dbase) = u0.f;
        *(float2*)(w_s + (hg * 4 + 1) * WS + dbase) = u1.f;
        *(float2*)(w_s + (hg * 4 + 2) * WS + dbase) = u2.f;
        *(float2*)(w_s + (hg * 4 + 3) * WS + dbase) = u3.f;
    }
    __syncthreads();

    int c4 = t & 63, g = t >> 6;      // thread owns cols 4c4..4c4+3, d-group g
    int h4 = c4 >> 2;                 // head of those 4 columns

    // ---- gl[c] = sum_d Wv[d,c] * w[h(c)][d]  (coalesced float4 row loads) ----
    {
        const float4* wv4 = (const float4*)Wv;
        float4 acc = make_float4(0.f, 0.f, 0.f, 0.f);
        const float* wrow = w_s + h4 * WS;
        int d0 = g * 32;
#pragma unroll 8
        for (int i = 0; i < 32; i++) {
            int d = d0 + i;
            float4 wv = wv4[(size_t)d * 64 + c4];
            float wd = wrow[d];
            acc.x += wv.x * wd; acc.y += wv.y * wd;
            acc.z += wv.z * wd; acc.w += wv.w * wd;
        }
        ((float4*)scr)[g * 64 + c4] = acc;
    }
    __syncthreads();
    if (t < 256) {
        float s = 0.f;
#pragma unroll
        for (int gg = 0; gg < 8; gg++) s += scr[gg * 256 + t];
        gl[t] = s;
    }
    __syncthreads();

    // ---- tv[d] = sum_e M2T[e][d] * gl[e] ---------------------------------------
    {
        const float4* m4 = (const float4*)g_M2T;
        float4 acc = make_float4(0.f, 0.f, 0.f, 0.f);
        int e0 = g * 32;
#pragma unroll 8
        for (int i = 0; i < 32; i++) {
            int e = e0 + i;
            float4 wv = m4[(size_t)e * 64 + c4];
            float ge = gl[e];
            acc.x += wv.x * ge; acc.y += wv.y * ge;
            acc.z += wv.z * ge; acc.w += wv.w * ge;
        }
        ((float4*)scr)[g * 64 + c4] = acc;
    }
    __syncthreads();
    if (t < 256) {
        float s = 0.f;
#pragma unroll
        for (int gg = 0; gg < 8; gg++) s += scr[gg * 256 + t];
        tv[t] = s;
    }
    __syncthreads();

    // ---- logits: j<74 from SMEM ce, rest from gmem (L2) ------------------------
    {
        const float4* cg = (const float4*)(clus + (size_t)b * C1 * DD);
        const float4* tv4 = (const float4*)tv;
        float4 t0 = tv4[lane * 2], t1 = tv4[lane * 2 + 1];
        for (int j = warp; j < C1; j += 16) {
            const float4* src = (j < SM_J_LIM) ? ce4 : cg;
            float4 c0 = src[j * 64 + lane * 2], c1 = src[j * 64 + lane * 2 + 1];
            float s = dot4(t0, c0) + dot4(t1, c1);
#pragma unroll
            for (int o = 16; o; o >>= 1) s += __shfl_xor_sync(0xffffffffu, s, o);
            if (lane == 0) {
                float l = tanhf(s * (1.0f / 16.0f)) * 10.0f;
                lg[j] = vmi[j] ? NEGV : l;
            }
        }
    }
    __syncthreads();

    // ---- log_softmax + argmax (warp 0) ----------------------------------------
    if (warp == 0) {
        float m = -3.0e38f; int mi = 0x7fffffff;
        for (int j = lane; j < C1; j += 32) {
            float v = lg[j];
            if (v > m) { m = v; mi = j; }
        }
#pragma unroll
        for (int o = 16; o; o >>= 1) {
            float om = __shfl_xor_sync(0xffffffffu, m, o);
            int   oi = __shfl_xor_sync(0xffffffffu, mi, o);
            if (om > m || (om == m && oi < mi)) { m = om; mi = oi; }
        }
        float s = 0.f;
        for (int j = lane; j < C1; j += 32) s += expf(lg[j] - m);
#pragma unroll
        for (int o = 16; o; o >>= 1) s += __shfl_xor_sync(0xffffffffu, s, o);
        if (lane == 0) { red[0] = m + logf(s); seli[0] = mi; }
    }
    __syncthreads();

    // ---- outputs (uvc reduced inline from node partials) ----------------------
    int sel = seli[0];
    float lse = red[0];
    size_t oa = (size_t)b * 1024;
    if (t < 256) {
        float se = clus[(size_t)b * C1 * DD + (size_t)sel * 256 + t];
        int cb = (BB + b) * 4;
        float s = g_part[(size_t)(cb + 0) * 256 + t] + g_part[(size_t)(cb + 1) * 256 + t]
                + g_part[(size_t)(cb + 2) * 256 + t] + g_part[(size_t)(cb + 3) * 256 + t];
        float den = fmaxf((float)(g_cnt[cb] + g_cnt[cb + 1] + g_cnt[cb + 2] + g_cnt[cb + 3]), 1.0f);
        out[oa + t]       = s / den;
        out[oa + 512 + t] = se;
        out[262144 + (size_t)b * 256 + t] = se;
    } else {
        int d = t - 256;
        out[oa + 256 + d] = cur[(size_t)b * DD + d];
        out[oa + 768 + d] = depot[(size_t)b * DD + d];
    }
    if (t == 0) out[327680 + b] = (float)sel;
    if (t < C1) out[327936 + (size_t)b * C1 + t] = lg[t] - lse;
}

extern "C" void kernel_launch(void* const* d_in, const int* in_sizes, int n_in,
                              void* d_out, int out_size) {
    const float* depot = (const float*)d_in[0];
    const float* clus  = (const float*)d_in[1];
    const float* cur   = (const float*)d_in[2];
    const float* node  = (const float*)d_in[3];
    const void*  mask  = d_in[4];
    const void*  cmask = d_in[5];
    const void*  vmask = d_in[6];
    const float* Wq    = (const float*)d_in[7];
    const float* Wk    = (const float*)d_in[8];
    const float* Wv    = (const float*)d_in[9];
    const float* Wks   = (const float*)d_in[10];
    const float* Wo    = (const float*)d_in[11];
    float* out = (float*)d_out;

    cudaFuncSetAttribute(k_qu_prep, cudaFuncAttributeMaxDynamicSharedMemorySize, QU_SMEM_BYTES);
    cudaFuncSetAttribute(k_main, cudaFuncAttributeMaxDynamicSharedMemorySize, SMEM_BYTES);

    k_nodes_part<<<dim3(4, BB), 256>>>(node, mask, cmask);

    // PDL: overlap secondary prologue with primary tail
    cudaLaunchAttribute attr[1];
    attr[0].id = cudaLaunchAttributeProgrammaticStreamSerialization;
    attr[0].val.programmaticStreamSerializationAllowed = 1;

    {
        cudaLaunchConfig_t cfg = {};
        cfg.gridDim = dim3(320, 1, 1);
        cfg.blockDim = dim3(256, 1, 1);
        cfg.dynamicSmemBytes = QU_SMEM_BYTES;
        cfg.attrs = attr;
        cfg.numAttrs = 1;
        cudaLaunchKernelEx(&cfg, k_qu_prep, cur, depot, Wq, Wk, Wks, Wo);
    }
    {
        cudaLaunchConfig_t cfg = {};
        cfg.gridDim = dim3(BB, 1, 1);
        cfg.blockDim = dim3(512, 1, 1);
        cfg.dynamicSmemBytes = SMEM_BYTES;
        cfg.attrs = attr;
        cfg.numAttrs = 1;
        cudaLaunchKernelEx(&cfg, k_main, depot, clus, cur, vmask, mask, Wv, out);
    }
}

// round 15
// speedup vs baseline: 1.2687x; 1.0197x over previous
#include <cuda_runtime.h>
#include <math.h>
#include <stdint.h>

#define BB  256
#define NN  1024
#define C1  101
#define DD  256
#define HH  16
#define NEGV (-1000000000.0f)
#define AS  104          // att row stride (floats)
#define WS  260          // w_s row stride (floats)

__device__ __align__(16) float g_u[BB * HH * DD];     // u[b][h][d]
__device__ __align__(16) float g_M2T[DD * DD];        // M2T[e][d] = sum_c Wks[d,c]*Wo[e,c]
__device__ __align__(16) float g_part[2 * BB * 4 * DD];
__device__ int g_cnt[2 * BB * 4];

__device__ __forceinline__ bool readb(const void* p, int idx, int mode) {
    if (mode == 0) return ((const unsigned char*)p)[idx] != 0;
    if (mode == 1) return ((const int*)p)[idx] != 0;
    return ((const float*)p)[idx] != 0.0f;
}

__device__ __forceinline__ float dot4(float4 a, float4 b) {
    return a.x * b.x + a.y * b.y + a.z * b.z + a.w * b.w;
}

__device__ __forceinline__ unsigned long long pack2(float x) {
    unsigned long long r;
    asm("mov.b64 %0, {%1, %1};" : "=l"(r) : "f"(x));
    return r;
}
__device__ __forceinline__ void fma2(unsigned long long& acc, unsigned long long a,
                                     unsigned long long b) {
    asm("fma.rn.f32x2 %0, %1, %2, %0;" : "+l"(acc) : "l"(a), "l"(b));
}
union U64F2 { unsigned long long u; float2 f; };

// bool-dtype probe on first 4KB of `mask`. Call from ALL threads (sync-or).
__device__ __forceinline__ int detect_mode(const void* m, int t) {
    int f32 = 0, u8 = 0;
    if (t < 256) {
        uint4 v = ((const uint4*)m)[t];
        unsigned w[4] = {v.x, v.y, v.z, v.w};
#pragma unroll
        for (int i = 0; i < 4; i++) {
            unsigned x = w[i];
            if (((x >> 24) & 0xffu) == 0x3fu || ((x >> 16) & 0xffu) == 0x3fu ||
                ((x >> 8) & 0xffu) == 0x3fu || (x & 0xffu) == 0x3fu) f32 = 1;
            if (x & 0xffffff00u) u8 = 1;
        }
    }
    int a = __syncthreads_or(f32);
    int b = __syncthreads_or(u8);
    return a ? 2 : (b ? 0 : 1);
}

// ---------------- Kernel 1: node partial sums (1024 CTAs) --------------------
__global__ void __launch_bounds__(256) k_nodes_part(
    const float* __restrict__ node, const void* __restrict__ mask,
    const void* __restrict__ cmask)
{
    __shared__ int list0[256];    // n | (uvc-flag << 8)
    __shared__ int lcnt;
    __shared__ float4 part[2][4][64];

    int q = blockIdx.x, b = blockIdx.y, t = threadIdx.x;
    int mode = detect_mode(mask, t);

    if (t == 0) lcnt = 0;
    __syncthreads();

    int gidx = b * NN + q * 256 + t;
    bool m  = readb(mask,  gidx, mode);
    bool mc = m | readb(cmask, gidx, mode);
    if (!m) {
        int pos = atomicAdd(&lcnt, 1);
        list0[pos] = t | ((mc ? 0 : 1) << 8);
    }
    int c0 = __syncthreads_count(!m);
    int c1 = __syncthreads_count(!mc);

    int chunk = t >> 6, d4 = t & 63;
    const float4* np4 = (const float4*)(node + (size_t)(b * NN + q * 256) * DD);
    float4 s0 = make_float4(0.f, 0.f, 0.f, 0.f), s1 = s0;

    int cnt = c0;
    int len4 = (cnt + 3) >> 2;
    int begin = chunk * len4;
    int end = begin + len4; if (end > cnt) end = cnt;

    int i = begin;
    for (; i + 8 <= end; i += 8) {
        int e[8];
        float4 v[8];
#pragma unroll
        for (int k = 0; k < 8; k++) e[k] = list0[i + k];
#pragma unroll
        for (int k = 0; k < 8; k++) v[k] = __ldcs(&np4[(size_t)(e[k] & 255) * 64 + d4]);
#pragma unroll
        for (int k = 0; k < 8; k++) {
            s0.x += v[k].x; s0.y += v[k].y; s0.z += v[k].z; s0.w += v[k].w;
            if (e[k] & 256) {
                s1.x += v[k].x; s1.y += v[k].y; s1.z += v[k].z; s1.w += v[k].w;
            }
        }
    }
    for (; i < end; i++) {
        int e = list0[i];
        float4 v = __ldcs(&np4[(size_t)(e & 255) * 64 + d4]);
        s0.x += v.x; s0.y += v.y; s0.z += v.z; s0.w += v.w;
        if (e & 256) { s1.x += v.x; s1.y += v.y; s1.z += v.z; s1.w += v.w; }
    }

    part[0][chunk][d4] = s0;
    part[1][chunk][d4] = s1;
    __syncthreads();

    if (t < 128) {
        int which = t >> 6, d = t & 63;
        float4 r = make_float4(0.f, 0.f, 0.f, 0.f);
#pragma unroll
        for (int c = 0; c < 4; c++) {
            float4 a = part[which][c][d];
            r.x += a.x; r.y += a.y; r.z += a.z; r.w += a.w;
        }
        ((float4*)g_part)[((which * BB + b) * 4 + q) * 64 + d] = r;
    }
    if (t == 0) {
        g_cnt[(0 * BB + b) * 4 + q] = c0;
        g_cnt[(1 * BB + b) * 4 + q] = c1;
    }
    cudaTriggerProgrammaticLaunchCompletion();
}

// ---------------- Kernel 2: q + u (CTAs 0..255)  +  M2T prep (CTAs 256..319) -
#define QU_SMEM_BYTES 66560

__global__ void __launch_bounds__(256) k_qu_prep(
    const float* __restrict__ cur, const float* __restrict__ depot,
    const float* __restrict__ Wq,  const float* __restrict__ Wk,
    const float* __restrict__ Wks, const float* __restrict__ Wo)
{
    extern __shared__ __align__(16) float sm[];
    int bx = blockIdx.x;
    int t = threadIdx.x;

    if (bx >= 256) {
        // ---- prep role: fully independent of k_nodes ------------------------
        float* a_sh = sm;            // 32 * 260
        float* b_sh = sm + 8320;     // 32 * 260
        int tile = bx - 256;
        int tj = tile & 7;   // d tile
        int ti = tile >> 3;  // e tile

        for (int i = t; i < 2048; i += 256) {
            int r = i >> 6, c4 = i & 63;
            float4 av = ((const float4*)(Wks + (size_t)(tj * 32 + r) * 256))[c4];
            float4 bv = ((const float4*)(Wo  + (size_t)(ti * 32 + r) * 256))[c4];
            *(float4*)(a_sh + r * 260 + c4 * 4) = av;
            *(float4*)(b_sh + r * 260 + c4 * 4) = bv;
        }
        __syncthreads();

        int el = t >> 3;
        int dl = (t & 7) * 4;
        float acc0 = 0.f, acc1 = 0.f, acc2 = 0.f, acc3 = 0.f;
        const float* br = b_sh + el * 260;
        const float* a0 = a_sh + (dl + 0) * 260;
        const float* a1 = a_sh + (dl + 1) * 260;
        const float* a2 = a_sh + (dl + 2) * 260;
        const float* a3 = a_sh + (dl + 3) * 260;
#pragma unroll 8
        for (int c = 0; c < 256; c++) {
            float bv = br[c];
            acc0 += a0[c] * bv;
            acc1 += a1[c] * bv;
            acc2 += a2[c] * bv;
            acc3 += a3[c] * bv;
        }
        *(float4*)(g_M2T + (size_t)(ti * 32 + el) * 256 + tj * 32 + dl) =
            make_float4(acc0, acc1, acc2, acc3);
        cudaTriggerProgrammaticLaunchCompletion();
        return;
    }

    // ---- qu role ------------------------------------------------------------
    float* ctx_base = sm;                       // 8 x 768
    float* qp_base  = sm + 6144;                // 8 x 8 x 32
    float* q_base   = sm + 6144 + 2048;         // 8 x 32
    float* den_s    = sm + 6144 + 2048 + 256;   // 8

    int cx = bx & 7;        // 0..7 : 32-col slice = 2 heads
    int by = bx >> 3;       // 0..31: 8 batches
    int lane = t & 31, w = t >> 5;

    // pre-sync prologue: inputs only
    for (int i = t; i < 8 * 256; i += 256) {
        int bi = i >> 8, d = i & 255;
        int b = by * 8 + bi;
        ctx_base[bi * 768 + 256 + d] = cur[(size_t)b * DD + d];
        ctx_base[bi * 768 + 512 + d] = depot[(size_t)b * DD + d];
    }

    cudaGridDependencySynchronize();

    if (t < 8) {
        int b = by * 8 + t;
        int c = g_cnt[b * 4 + 0] + g_cnt[b * 4 + 1] + g_cnt[b * 4 + 2] + g_cnt[b * 4 + 3];
        den_s[t] = fmaxf((float)c, 1.0f);
    }
    __syncthreads();

    for (int i = t; i < 8 * 256; i += 256) {
        int bi = i >> 8, d = i & 255;
        int b = by * 8 + bi;
        float s = g_part[(size_t)(b * 4 + 0) * 256 + d] + g_part[(size_t)(b * 4 + 1) * 256 + d]
                + g_part[(size_t)(b * 4 + 2) * 256 + d] + g_part[(size_t)(b * 4 + 3) * 256 + d];
        ctx_base[bi * 768 + d] = s / den_s[bi];
    }
    __syncthreads();

    {
        int c = cx * 32 + lane;
        float acc[8];
#pragma unroll
        for (int bi = 0; bi < 8; bi++) acc[bi] = 0.f;
        int k0 = w * 96;
        for (int k = k0; k < k0 + 96; k += 4) {
            float w0 = Wq[(size_t)(k + 0) * 256 + c];
            float w1 = Wq[(size_t)(k + 1) * 256 + c];
            float w2 = Wq[(size_t)(k + 2) * 256 + c];
            float w3 = Wq[(size_t)(k + 3) * 256 + c];
#pragma unroll
            for (int bi = 0; bi < 8; bi++) {
                const float* cb = ctx_base + bi * 768;
                acc[bi] += w0 * cb[k] + w1 * cb[k + 1]
                         + w2 * cb[k + 2] + w3 * cb[k + 3];
            }
        }
#pragma unroll
        for (int bi = 0; bi < 8; bi++) qp_base[(w * 8 + bi) * 32 + lane] = acc[bi];
    }
    __syncthreads();

    {
        int bi = w;
        float s = 0.f;
#pragma unroll
        for (int ww = 0; ww < 8; ww++) s += qp_base[(ww * 8 + bi) * 32 + lane];
        q_base[bi * 32 + lane] = s;
    }
    __syncthreads();

    int d = t;
    const float4* wk = (const float4*)(Wk + (size_t)d * 256 + cx * 32);
#pragma unroll
    for (int hl = 0; hl < 2; hl++) {
        float4 w0 = wk[hl * 4], w1 = wk[hl * 4 + 1], w2 = wk[hl * 4 + 2], w3 = wk[hl * 4 + 3];
#pragma unroll
        for (int bi = 0; bi < 8; bi++) {
            const float4* qv = (const float4*)(q_base + bi * 32 + hl * 16);
            float s = dot4(w0, qv[0]) + dot4(w1, qv[1]) + dot4(w2, qv[2]) + dot4(w3, qv[3]);
            g_u[(size_t)(by * 8 + bi) * (HH * DD) + (cx * 2 + hl) * 256 + d] = s;
        }
    }
    cudaTriggerProgrammaticLaunchCompletion();
}

// SMEM layout (bytes). Region A holds ce; TAIL reused after wsum.
#define OFF_A    0
#define A_BYTES  (C1 * DD * 4)                  // 103424
#define A_W      76544                          // 16 * 260 * 4 = 16640
#define A_GL     (A_W + 16640)                  // 93184
#define A_TV     (A_GL + 1024)                  // 94208
#define A_SCR    (A_TV + 1024)                  // 95232 (+8192 = 103424)
#define SM_J_LIM 74                             // ce rows [0,74) intact
#define OFF_ATT  A_BYTES                        // 16 * 104 * 4 = 6656
#define OFF_LG   (OFF_ATT + HH * AS * 4)
#define OFF_RED  (OFF_LG + 104 * 4)
#define OFF_VMI  (OFF_RED + 16)
#define OFF_SEL  (OFF_VMI + 104 * 4)
#define OFF_JL   (OFF_SEL + 16)                 // unmasked-j list + count
#define SMEM_BYTES (OFF_JL + 104 * 4 + 16)      // ~111.4 KB, still occ 2

// ---------------- Kernel 3: fused per-batch chain, occ 2 ---------------------
__global__ void __launch_bounds__(512, 2) k_main(
    const float* __restrict__ depot, const float* __restrict__ clus,
    const float* __restrict__ cur,   const void*  __restrict__ vmask,
    const void*  __restrict__ mask,
    const float* __restrict__ Wv,    float* __restrict__ out)
{
    extern __shared__ __align__(16) char smraw[];
    float* ce   = (float*)(smraw + OFF_A);
    float* w_s  = (float*)(smraw + A_W);
    float* gl   = (float*)(smraw + A_GL);
    float* tv   = (float*)(smraw + A_TV);
    float* scr  = (float*)(smraw + A_SCR);
    float* att  = (float*)(smraw + OFF_ATT);
    float* lg   = (float*)(smraw + OFF_LG);
    float* red  = (float*)(smraw + OFF_RED);
    int*   vmi  = (int*)(smraw + OFF_VMI);
    int*   seli = (int*)(smraw + OFF_SEL);
    int*   jlst = (int*)(smraw + OFF_JL);
    int*   jcntp = jlst + 104;

    int b = blockIdx.x, t = threadIdx.x;
    int lane = t & 31, warp = t >> 5;

    // pre-sync prologue: inputs only
    int mode = detect_mode(mask, t);
    {
        const float4* cg = (const float4*)(clus + (size_t)b * C1 * DD);
        float4* d4 = (float4*)ce;
        for (int i = t; i < C1 * DD / 4; i += 512) d4[i] = cg[i];
    }
    if (t < C1) vmi[t] = readb(vmask, b * C1 + t, mode) ? 1 : 0;
    __syncthreads();
    if (t == 0) {
        int all = 1;
        for (int j = 1; j < C1; j++) all &= vmi[j];
        vmi[0] = !all;
        // deterministic compaction of unmasked j's
        int c = 0;
        for (int j = 0; j < C1; j++) if (!vmi[j]) jlst[c++] = j;
        *jcntp = c;
    }

    cudaGridDependencySynchronize();
    __syncthreads();

    int jcnt = *jcntp;
    const float4* ce4 = (const float4*)ce;
    int hg = warp & 3;       // head group: heads hg*4 .. hg*4+3
    int qq = warp >> 2;      // quarter index 0..3

    // pre-fill masked entries: att rows = NEGV, lg = NEGV
    if (t < C1 && vmi[t]) {
        lg[t] = NEGV;
#pragma unroll
        for (int h = 0; h < HH; h++) att[h * AS + t] = NEGV;
    }
    __syncthreads();

    // ---- scores: warp = (hg, j-quarter over COMPACTED list) ------------------
    {
        int jq = (jcnt + 3) >> 2;
        int jb = qq * jq;
        int je = jb + jq; if (je > jcnt) je = jcnt;
        const float4* up = (const float4*)(g_u + (size_t)b * (HH * DD));
        float4 ua[4], ub[4];
#pragma unroll
        for (int h = 0; h < 4; h++) {
            ua[h] = up[(hg * 4 + h) * 64 + lane * 2];
            ub[h] = up[(hg * 4 + h) * 64 + lane * 2 + 1];
        }
        for (int ji = jb; ji < je; ji++) {
            int j = jlst[ji];
            float4 c0 = ce4[j * 64 + lane * 2], c1 = ce4[j * 64 + lane * 2 + 1];
            float p0 = dot4(ua[0], c0) + dot4(ub[0], c1);
            float p1 = dot4(ua[1], c0) + dot4(ub[1], c1);
            float p2 = dot4(ua[2], c0) + dot4(ub[2], c1);
            float p3 = dot4(ua[3], c0) + dot4(ub[3], c1);
#pragma unroll
            for (int o = 16; o; o >>= 1) {
                p0 += __shfl_xor_sync(0xffffffffu, p0, o);
                p1 += __shfl_xor_sync(0xffffffffu, p1, o);
                p2 += __shfl_xor_sync(0xffffffffu, p2, o);
                p3 += __shfl_xor_sync(0xffffffffu, p3, o);
            }
            if (lane == 0) {
                att[(hg * 4 + 0) * AS + j] = p0 * 0.25f;
                att[(hg * 4 + 1) * AS + j] = p1 * 0.25f;
                att[(hg * 4 + 2) * AS + j] = p2 * 0.25f;
                att[(hg * 4 + 3) * AS + j] = p3 * 0.25f;
            }
        }
    }
    __syncthreads();

    // ---- softmax: warp = head ------------------------------------------------
    {
        int h = warp;
        float v[4];
#pragma unroll
        for (int k = 0; k < 4; k++) {
            int j = lane + 32 * k;
            v[k] = (j < C1) ? att[h * AS + j] : -3.0e38f;
        }
        float m = fmaxf(fmaxf(v[0], v[1]), fmaxf(v[2], v[3]));
#pragma unroll
        for (int o = 16; o; o >>= 1) m = fmaxf(m, __shfl_xor_sync(0xffffffffu, m, o));
        float e[4], s = 0.f;
#pragma unroll
        for (int k = 0; k < 4; k++) {
            int j = lane + 32 * k;
            e[k] = (j < C1) ? expf(v[k] - m) : 0.f;
            s += e[k];
        }
#pragma unroll
        for (int o = 16; o; o >>= 1) s += __shfl_xor_sync(0xffffffffu, s, o);
        float inv = 1.0f / s;
#pragma unroll
        for (int k = 0; k < 4; k++) {
            int j = lane + 32 * k;
            if (j < C1) att[h * AS + j] = e[k] * inv;
        }
    }
    __syncthreads();

    // ---- wsum over COMPACTED list (masked attn == +0.0 exactly) ---------------
    unsigned long long A0 = 0ull, A1 = 0ull, A2 = 0ull, A3 = 0ull;
    {
        const unsigned long long* ce2 = (const unsigned long long*)ce;
        const float* a0 = att + (hg * 4 + 0) * AS;
        const float* a1 = att + (hg * 4 + 1) * AS;
        const float* a2 = att + (hg * 4 + 2) * AS;
        const float* a3 = att + (hg * 4 + 3) * AS;
        int idx = qq * 32 + lane;
        for (int ji = 0; ji < jcnt; ji++) {
            int j = jlst[ji];
            unsigned long long c = ce2[j * 128 + idx];
            fma2(A0, pack2(a0[j]), c);
            fma2(A1, pack2(a1[j]), c);
            fma2(A2, pack2(a2[j]), c);
            fma2(A3, pack2(a3[j]), c);
        }
    }
    __syncthreads();   // ce reads done; TAIL of region A reusable

    {
        int dbase = qq * 64 + lane * 2;
        U64F2 u0, u1, u2, u3;
        u0.u = A0; u1.u = A1; u2.u = A2; u3.u = A3;
        *(float2*)(w_s + (hg * 4 + 0) * WS + dbase) = u0.f;
        *(float2*)(w_s + (hg * 4 + 1) * WS + dbase) = u1.f;
        *(float2*)(w_s + (hg * 4 + 2) * WS + dbase) = u2.f;
        *(float2*)(w_s + (hg * 4 + 3) * WS + dbase) = u3.f;
    }
    __syncthreads();

    int c4 = t & 63, g = t >> 6;      // thread owns cols 4c4..4c4+3, d-group g
    int h4 = c4 >> 2;                 // head of those 4 columns

    // ---- gl[c] = sum_d Wv[d,c] * w[h(c)][d] ------------------------------------
    {
        const float4* wv4 = (const float4*)Wv;
        float4 acc = make_float4(0.f, 0.f, 0.f, 0.f);
        const float* wrow = w_s + h4 * WS;
        int d0 = g * 32;
#pragma unroll 8
        for (int i = 0; i < 32; i++) {
            int d = d0 + i;
            float4 wv = wv4[(size_t)d * 64 + c4];
            float wd = wrow[d];
            acc.x += wv.x * wd; acc.y += wv.y * wd;
            acc.z += wv.z * wd; acc.w += wv.w * wd;
        }
        ((float4*)scr)[g * 64 + c4] = acc;
    }
    __syncthreads();
    if (t < 256) {
        float s = 0.f;
#pragma unroll
        for (int gg = 0; gg < 8; gg++) s += scr[gg * 256 + t];
        gl[t] = s;
    }
    __syncthreads();

    // ---- tv[d] = sum_e M2T[e][d] * gl[e] ---------------------------------------
    {
        const float4* m4 = (const float4*)g_M2T;
        float4 acc = make_float4(0.f, 0.f, 0.f, 0.f);
        int e0 = g * 32;
#pragma unroll 8
        for (int i = 0; i < 32; i++) {
            int e = e0 + i;
            float4 wv = m4[(size_t)e * 64 + c4];
            float ge = gl[e];
            acc.x += wv.x * ge; acc.y += wv.y * ge;
            acc.z += wv.z * ge; acc.w += wv.w * ge;
        }
        ((float4*)scr)[g * 64 + c4] = acc;
    }
    __syncthreads();
    if (t < 256) {
        float s = 0.f;
#pragma unroll
        for (int gg = 0; gg < 8; gg++) s += scr[gg * 256 + t];
        tv[t] = s;
    }
    __syncthreads();

    // ---- logits over COMPACTED list; masked lg already NEGV --------------------
    {
        const float4* cg = (const float4*)(clus + (size_t)b * C1 * DD);
        const float4* tv4 = (const float4*)tv;
        float4 t0 = tv4[lane * 2], t1 = tv4[lane * 2 + 1];
        for (int ji = warp; ji < jcnt; ji += 16) {
            int j = jlst[ji];
            const float4* src = (j < SM_J_LIM) ? ce4 : cg;
            float4 c0 = src[j * 64 + lane * 2], c1 = src[j * 64 + lane * 2 + 1];
            float s = dot4(t0, c0) + dot4(t1, c1);
#pragma unroll
            for (int o = 16; o; o >>= 1) s += __shfl_xor_sync(0xffffffffu, s, o);
            if (lane == 0) lg[j] = tanhf(s * (1.0f / 16.0f)) * 10.0f;
        }
    }
    __syncthreads();

    // ---- log_softmax + argmax (warp 0) ----------------------------------------
    if (warp == 0) {
        float m = -3.0e38f; int mi = 0x7fffffff;
        for (int j = lane; j < C1; j += 32) {
            float v = lg[j];
            if (v > m) { m = v; mi = j; }
        }
#pragma unroll
        for (int o = 16; o; o >>= 1) {
            float om = __shfl_xor_sync(0xffffffffu, m, o);
            int   oi = __shfl_xor_sync(0xffffffffu, mi, o);
            if (om > m || (om == m && oi < mi)) { m = om; mi = oi; }
        }
        float s = 0.f;
        for (int j = lane; j < C1; j += 32) s += expf(lg[j] - m);
#pragma unroll
        for (int o = 16; o; o >>= 1) s += __shfl_xor_sync(0xffffffffu, s, o);
        if (lane == 0) { red[0] = m + logf(s); seli[0] = mi; }
    }
    __syncthreads();

    // ---- outputs (uvc reduced inline from node partials) ----------------------
    int sel = seli[0];
    float lse = red[0];
    size_t oa = (size_t)b * 1024;
    if (t < 256) {
        float se = clus[(size_t)b * C1 * DD + (size_t)sel * 256 + t];
        int cb = (BB + b) * 4;
        float s = g_part[(size_t)(cb + 0) * 256 + t] + g_part[(size_t)(cb + 1) * 256 + t]
                + g_part[(size_t)(cb + 2) * 256 + t] + g_part[(size_t)(cb + 3) * 256 + t];
        float den = fmaxf((float)(g_cnt[cb] + g_cnt[cb + 1] + g_cnt[cb + 2] + g_cnt[cb + 3]), 1.0f);
        out[oa + t]       = s / den;
        out[oa + 512 + t] = se;
        out[262144 + (size_t)b * 256 + t] = se;
    } else {
        int d = t - 256;
        out[oa + 256 + d] = cur[(size_t)b * DD + d];
        out[oa + 768 + d] = depot[(size_t)b * DD + d];
    }
    if (t == 0) out[327680 + b] = (float)sel;
    if (t < C1) out[327936 + (size_t)b * C1 + t] = lg[t] - lse;
}

extern "C" void kernel_launch(void* const* d_in, const int* in_sizes, int n_in,
                              void* d_out, int out_size) {
    const float* depot = (const float*)d_in[0];
    const float* clus  = (const float*)d_in[1];
    const float* cur   = (const float*)d_in[2];
    const float* node  = (const float*)d_in[3];
    const void*  mask  = d_in[4];
    const void*  cmask = d_in[5];
    const void*  vmask = d_in[6];
    const float* Wq    = (const float*)d_in[7];
    const float* Wk    = (const float*)d_in[8];
    const float* Wv    = (const float*)d_in[9];
    const float* Wks   = (const float*)d_in[10];
    const float* Wo    = (const float*)d_in[11];
    float* out = (float*)d_out;

    cudaFuncSetAttribute(k_qu_prep, cudaFuncAttributeMaxDynamicSharedMemorySize, QU_SMEM_BYTES);
    cudaFuncSetAttribute(k_main, cudaFuncAttributeMaxDynamicSharedMemorySize, SMEM_BYTES);

    k_nodes_part<<<dim3(4, BB), 256>>>(node, mask, cmask);

    cudaLaunchAttribute attr[1];
    attr[0].id = cudaLaunchAttributeProgrammaticStreamSerialization;
    attr[0].val.programmaticStreamSerializationAllowed = 1;

    {
        cudaLaunchConfig_t cfg = {};
        cfg.gridDim = dim3(320, 1, 1);
        cfg.blockDim = dim3(256, 1, 1);
        cfg.dynamicSmemBytes = QU_SMEM_BYTES;
        cfg.attrs = attr;
        cfg.numAttrs = 1;
        cudaLaunchKernelEx(&cfg, k_qu_prep, cur, depot, Wq, Wk, Wks, Wo);
    }
    {
        cudaLaunchConfig_t cfg = {};
        cfg.gridDim = dim3(BB, 1, 1);
        cfg.blockDim = dim3(512, 1, 1);
        cfg.dynamicSmemBytes = SMEM_BYTES;
        cfg.attrs = attr;
        cfg.numAttrs = 1;
        cudaLaunchKernelEx(&cfg, k_main, depot, clus, cur, vmask, mask, Wv, out);
    }
}

// round 16
// speedup vs baseline: 1.2729x; 1.0033x over previous
#include <cuda_runtime.h>
#include <math.h>
#include <stdint.h>

#define BB  256
#define NN  1024
#define C1  101
#define DD  256
#define HH  16
#define NEGV (-1000000000.0f)
#define AS  104          // att row stride (floats)
#define WS  260          // w_s row stride (floats)

__device__ __align__(16) float g_u[BB * HH * DD];     // u[b][h][d]
__device__ __align__(16) float g_M2T[DD * DD];        // M2T[e][d] = sum_c Wks[d,c]*Wo[e,c]
__device__ __align__(16) float g_part[2 * BB * 4 * DD];
__device__ int g_cnt[2 * BB * 4];

__device__ __forceinline__ bool readb(const void* p, int idx, int mode) {
    if (mode == 0) return ((const unsigned char*)p)[idx] != 0;
    if (mode == 1) return ((const int*)p)[idx] != 0;
    return ((const float*)p)[idx] != 0.0f;
}

__device__ __forceinline__ float dot4(float4 a, float4 b) {
    return a.x * b.x + a.y * b.y + a.z * b.z + a.w * b.w;
}

__device__ __forceinline__ unsigned long long pack2(float x) {
    unsigned long long r;
    asm("mov.b64 %0, {%1, %1};" : "=l"(r) : "f"(x));
    return r;
}
__device__ __forceinline__ void fma2(unsigned long long& acc, unsigned long long a,
                                     unsigned long long b) {
    asm("fma.rn.f32x2 %0, %1, %2, %0;" : "+l"(acc) : "l"(a), "l"(b));
}
union U64F2 { unsigned long long u; float2 f; };

// bool-dtype probe on first 4KB of `mask`. Call from ALL threads (sync-or).
__device__ __forceinline__ int detect_mode(const void* m, int t) {
    int f32 = 0, u8 = 0;
    if (t < 256) {
        uint4 v = ((const uint4*)m)[t];
        unsigned w[4] = {v.x, v.y, v.z, v.w};
#pragma unroll
        for (int i = 0; i < 4; i++) {
            unsigned x = w[i];
            if (((x >> 24) & 0xffu) == 0x3fu || ((x >> 16) & 0xffu) == 0x3fu ||
                ((x >> 8) & 0xffu) == 0x3fu || (x & 0xffu) == 0x3fu) f32 = 1;
            if (x & 0xffffff00u) u8 = 1;
        }
    }
    int a = __syncthreads_or(f32);
    int b = __syncthreads_or(u8);
    return a ? 2 : (b ? 0 : 1);
}

// ---------------- Kernel 1: node partial sums (1024 CTAs) --------------------
__global__ void __launch_bounds__(256) k_nodes_part(
    const float* __restrict__ node, const void* __restrict__ mask,
    const void* __restrict__ cmask)
{
    __shared__ int list0[256];    // n | (uvc-flag << 8)
    __shared__ int lcnt;
    __shared__ float4 part[2][4][64];

    int q = blockIdx.x, b = blockIdx.y, t = threadIdx.x;
    int mode = detect_mode(mask, t);

    if (t == 0) lcnt = 0;
    __syncthreads();

    int gidx = b * NN + q * 256 + t;
    bool m  = readb(mask,  gidx, mode);
    bool mc = m | readb(cmask, gidx, mode);
    if (!m) {
        int pos = atomicAdd(&lcnt, 1);
        list0[pos] = t | ((mc ? 0 : 1) << 8);
    }
    int c0 = __syncthreads_count(!m);
    int c1 = __syncthreads_count(!mc);

    int chunk = t >> 6, d4 = t & 63;
    const float4* np4 = (const float4*)(node + (size_t)(b * NN + q * 256) * DD);
    float4 s0 = make_float4(0.f, 0.f, 0.f, 0.f), s1 = s0;

    int cnt = c0;
    int len4 = (cnt + 3) >> 2;
    int begin = chunk * len4;
    int end = begin + len4; if (end > cnt) end = cnt;

    int i = begin;
    for (; i + 8 <= end; i += 8) {
        int e[8];
        float4 v[8];
#pragma unroll
        for (int k = 0; k < 8; k++) e[k] = list0[i + k];
#pragma unroll
        for (int k = 0; k < 8; k++) v[k] = __ldcs(&np4[(size_t)(e[k] & 255) * 64 + d4]);
#pragma unroll
        for (int k = 0; k < 8; k++) {
            s0.x += v[k].x; s0.y += v[k].y; s0.z += v[k].z; s0.w += v[k].w;
            if (e[k] & 256) {
                s1.x += v[k].x; s1.y += v[k].y; s1.z += v[k].z; s1.w += v[k].w;
            }
        }
    }
    for (; i < end; i++) {
        int e = list0[i];
        float4 v = __ldcs(&np4[(size_t)(e & 255) * 64 + d4]);
        s0.x += v.x; s0.y += v.y; s0.z += v.z; s0.w += v.w;
        if (e & 256) { s1.x += v.x; s1.y += v.y; s1.z += v.z; s1.w += v.w; }
    }

    part[0][chunk][d4] = s0;
    part[1][chunk][d4] = s1;
    __syncthreads();

    if (t < 128) {
        int which = t >> 6, d = t & 63;
        float4 r = make_float4(0.f, 0.f, 0.f, 0.f);
#pragma unroll
        for (int c = 0; c < 4; c++) {
            float4 a = part[which][c][d];
            r.x += a.x; r.y += a.y; r.z += a.z; r.w += a.w;
        }
        ((float4*)g_part)[((which * BB + b) * 4 + q) * 64 + d] = r;
    }
    if (t == 0) {
        g_cnt[(0 * BB + b) * 4 + q] = c0;
        g_cnt[(1 * BB + b) * 4 + q] = c1;
    }
    cudaTriggerProgrammaticLaunchCompletion();
}

// ---------------- Kernel 2: q + u (CTAs 0..255)  +  M2T prep (CTAs 256..319) -
#define QU_SMEM_BYTES 66560

__global__ void __launch_bounds__(256) k_qu_prep(
    const float* __restrict__ cur, const float* __restrict__ depot,
    const float* __restrict__ Wq,  const float* __restrict__ Wk,
    const float* __restrict__ Wks, const float* __restrict__ Wo)
{
    extern __shared__ __align__(16) float sm[];
    int bx = blockIdx.x;
    int t = threadIdx.x;

    if (bx >= 256) {
        // ---- prep role: fully independent of k_nodes ------------------------
        float* a_sh = sm;            // 32 * 260
        float* b_sh = sm + 8320;     // 32 * 260
        int tile = bx - 256;
        int tj = tile & 7;   // d tile
        int ti = tile >> 3;  // e tile

        for (int i = t; i < 2048; i += 256) {
            int r = i >> 6, c4 = i & 63;
            float4 av = ((const float4*)(Wks + (size_t)(tj * 32 + r) * 256))[c4];
            float4 bv = ((const float4*)(Wo  + (size_t)(ti * 32 + r) * 256))[c4];
            *(float4*)(a_sh + r * 260 + c4 * 4) = av;
            *(float4*)(b_sh + r * 260 + c4 * 4) = bv;
        }
        __syncthreads();

        int el = t >> 3;
        int dl = (t & 7) * 4;
        float acc0 = 0.f, acc1 = 0.f, acc2 = 0.f, acc3 = 0.f;
        const float* br = b_sh + el * 260;
        const float* a0 = a_sh + (dl + 0) * 260;
        const float* a1 = a_sh + (dl + 1) * 260;
        const float* a2 = a_sh + (dl + 2) * 260;
        const float* a3 = a_sh + (dl + 3) * 260;
#pragma unroll 8
        for (int c = 0; c < 256; c++) {
            float bv = br[c];
            acc0 += a0[c] * bv;
            acc1 += a1[c] * bv;
            acc2 += a2[c] * bv;
            acc3 += a3[c] * bv;
        }
        *(float4*)(g_M2T + (size_t)(ti * 32 + el) * 256 + tj * 32 + dl) =
            make_float4(acc0, acc1, acc2, acc3);
        cudaTriggerProgrammaticLaunchCompletion();
        return;
    }

    // ---- qu role ------------------------------------------------------------
    float* ctx_base = sm;                       // 8 x 768
    float* qp_base  = sm + 6144;                // 8 x 8 x 32
    float* q_base   = sm + 6144 + 2048;         // 8 x 32
    float* den_s    = sm + 6144 + 2048 + 256;   // 8

    int cx = bx & 7;        // 0..7 : 32-col slice = 2 heads
    int by = bx >> 3;       // 0..31: 8 batches
    int lane = t & 31, w = t >> 5;

    // pre-sync: load cur/depot into ctx (inputs only)
    for (int i = t; i < 8 * 256; i += 256) {
        int bi = i >> 8, d = i & 255;
        int b = by * 8 + bi;
        ctx_base[bi * 768 + 256 + d] = cur[(size_t)b * DD + d];
        ctx_base[bi * 768 + 512 + d] = depot[(size_t)b * DD + d];
    }
    __syncthreads();

    // pre-sync: Wq partial over k in [256,768) — 2/3 of the matvec, overlapped
    // with k_nodes. Accumulators live in registers across the dependency sync.
    int c = cx * 32 + lane;
    float acc[8];
#pragma unroll
    for (int bi = 0; bi < 8; bi++) acc[bi] = 0.f;
    {
        int k0 = 256 + w * 64;
        for (int k = k0; k < k0 + 64; k += 4) {
            float w0 = Wq[(size_t)(k + 0) * 256 + c];
            float w1 = Wq[(size_t)(k + 1) * 256 + c];
            float w2 = Wq[(size_t)(k + 2) * 256 + c];
            float w3 = Wq[(size_t)(k + 3) * 256 + c];
#pragma unroll
            for (int bi = 0; bi < 8; bi++) {
                const float* cb = ctx_base + bi * 768;
                acc[bi] += w0 * cb[k] + w1 * cb[k + 1]
                         + w2 * cb[k + 2] + w3 * cb[k + 3];
            }
        }
    }

    // wait for k_nodes' g_part/g_cnt
    cudaGridDependencySynchronize();

    if (t < 8) {
        int b = by * 8 + t;
        int cc = g_cnt[b * 4 + 0] + g_cnt[b * 4 + 1] + g_cnt[b * 4 + 2] + g_cnt[b * 4 + 3];
        den_s[t] = fmaxf((float)cc, 1.0f);
    }
    __syncthreads();

    for (int i = t; i < 8 * 256; i += 256) {
        int bi = i >> 8, d = i & 255;
        int b = by * 8 + bi;
        float s = g_part[(size_t)(b * 4 + 0) * 256 + d] + g_part[(size_t)(b * 4 + 1) * 256 + d]
                + g_part[(size_t)(b * 4 + 2) * 256 + d] + g_part[(size_t)(b * 4 + 3) * 256 + d];
        ctx_base[bi * 768 + d] = s / den_s[bi];
    }
    __syncthreads();

    // post-sync: Wq over k in [0,256) — uv rows only
    {
        int k0 = w * 32;
        for (int k = k0; k < k0 + 32; k += 4) {
            float w0 = Wq[(size_t)(k + 0) * 256 + c];
            float w1 = Wq[(size_t)(k + 1) * 256 + c];
            float w2 = Wq[(size_t)(k + 2) * 256 + c];
            float w3 = Wq[(size_t)(k + 3) * 256 + c];
#pragma unroll
            for (int bi = 0; bi < 8; bi++) {
                const float* cb = ctx_base + bi * 768;
                acc[bi] += w0 * cb[k] + w1 * cb[k + 1]
                         + w2 * cb[k + 2] + w3 * cb[k + 3];
            }
        }
#pragma unroll
        for (int bi = 0; bi < 8; bi++) qp_base[(w * 8 + bi) * 32 + lane] = acc[bi];
    }
    __syncthreads();

    {
        int bi = w;
        float s = 0.f;
#pragma unroll
        for (int ww = 0; ww < 8; ww++) s += qp_base[(ww * 8 + bi) * 32 + lane];
        q_base[bi * 32 + lane] = s;
    }
    __syncthreads();

    int d = t;
    const float4* wk = (const float4*)(Wk + (size_t)d * 256 + cx * 32);
#pragma unroll
    for (int hl = 0; hl < 2; hl++) {
        float4 w0 = wk[hl * 4], w1 = wk[hl * 4 + 1], w2 = wk[hl * 4 + 2], w3 = wk[hl * 4 + 3];
#pragma unroll
        for (int bi = 0; bi < 8; bi++) {
            const float4* qv = (const float4*)(q_base + bi * 32 + hl * 16);
            float s = dot4(w0, qv[0]) + dot4(w1, qv[1]) + dot4(w2, qv[2]) + dot4(w3, qv[3]);
            g_u[(size_t)(by * 8 + bi) * (HH * DD) + (cx * 2 + hl) * 256 + d] = s;
        }
    }
    cudaTriggerProgrammaticLaunchCompletion();
}

// SMEM layout (bytes). Region A holds ce; TAIL reused after wsum.
#define OFF_A    0
#define A_BYTES  (C1 * DD * 4)                  // 103424
#define A_W      76544                          // 16 * 260 * 4 = 16640
#define A_GL     (A_W + 16640)                  // 93184
#define A_TV     (A_GL + 1024)                  // 94208
#define A_SCR    (A_TV + 1024)                  // 95232 (+8192 = 103424)
#define SM_J_LIM 74                             // ce rows [0,74) intact
#define OFF_ATT  A_BYTES                        // 16 * 104 * 4 = 6656
#define OFF_LG   (OFF_ATT + HH * AS * 4)
#define OFF_RED  (OFF_LG + 104 * 4)
#define OFF_VMI  (OFF_RED + 16)
#define OFF_SEL  (OFF_VMI + 104 * 4)
#define OFF_JL   (OFF_SEL + 16)                 // unmasked-j list + count
#define SMEM_BYTES (OFF_JL + 104 * 4 + 16)      // ~111.4 KB, still occ 2

// ---------------- Kernel 3: fused per-batch chain, occ 2 ---------------------
__global__ void __launch_bounds__(512, 2) k_main(
    const float* __restrict__ depot, const float* __restrict__ clus,
    const float* __restrict__ cur,   const void*  __restrict__ vmask,
    const void*  __restrict__ mask,
    const float* __restrict__ Wv,    float* __restrict__ out)
{
    extern __shared__ __align__(16) char smraw[];
    float* ce   = (float*)(smraw + OFF_A);
    float* w_s  = (float*)(smraw + A_W);
    float* gl   = (float*)(smraw + A_GL);
    float* tv   = (float*)(smraw + A_TV);
    float* scr  = (float*)(smraw + A_SCR);
    float* att  = (float*)(smraw + OFF_ATT);
    float* lg   = (float*)(smraw + OFF_LG);
    float* red  = (float*)(smraw + OFF_RED);
    int*   vmi  = (int*)(smraw + OFF_VMI);
    int*   seli = (int*)(smraw + OFF_SEL);
    int*   jlst = (int*)(smraw + OFF_JL);
    int*   jcntp = jlst + 104;

    int b = blockIdx.x, t = threadIdx.x;
    int lane = t & 31, warp = t >> 5;

    // pre-sync prologue: inputs only (ce tile, vmask, j-compaction, prefill)
    int mode = detect_mode(mask, t);
    {
        const float4* cg = (const float4*)(clus + (size_t)b * C1 * DD);
        float4* d4 = (float4*)ce;
        for (int i = t; i < C1 * DD / 4; i += 512) d4[i] = cg[i];
    }
    if (t < C1) vmi[t] = readb(vmask, b * C1 + t, mode) ? 1 : 0;
    __syncthreads();
    if (t == 0) {
        int all = 1;
        for (int j = 1; j < C1; j++) all &= vmi[j];
        vmi[0] = !all;
        int c = 0;
        for (int j = 0; j < C1; j++) if (!vmi[j]) jlst[c++] = j;
        *jcntp = c;
    }
    __syncthreads();
    // pre-fill masked entries (needs vmi only)
    if (t < C1 && vmi[t]) {
        lg[t] = NEGV;
#pragma unroll
        for (int h = 0; h < HH; h++) att[h * AS + t] = NEGV;
    }

    cudaGridDependencySynchronize();
    __syncthreads();

    int jcnt = *jcntp;
    const float4* ce4 = (const float4*)ce;
    int hg = warp & 3;       // head group: heads hg*4 .. hg*4+3
    int qq = warp >> 2;      // quarter index 0..3

    // ---- scores: warp = (hg, j-quarter over COMPACTED list) ------------------
    {
        int jq = (jcnt + 3) >> 2;
        int jb = qq * jq;
        int je = jb + jq; if (je > jcnt) je = jcnt;
        const float4* up = (const float4*)(g_u + (size_t)b * (HH * DD));
        float4 ua[4], ub[4];
#pragma unroll
        for (int h = 0; h < 4; h++) {
            ua[h] = up[(hg * 4 + h) * 64 + lane * 2];
            ub[h] = up[(hg * 4 + h) * 64 + lane * 2 + 1];
        }
        for (int ji = jb; ji < je; ji++) {
            int j = jlst[ji];
            float4 c0 = ce4[j * 64 + lane * 2], c1 = ce4[j * 64 + lane * 2 + 1];
            float p0 = dot4(ua[0], c0) + dot4(ub[0], c1);
            float p1 = dot4(ua[1], c0) + dot4(ub[1], c1);
            float p2 = dot4(ua[2], c0) + dot4(ub[2], c1);
            float p3 = dot4(ua[3], c0) + dot4(ub[3], c1);
#pragma unroll
            for (int o = 16; o; o >>= 1) {
                p0 += __shfl_xor_sync(0xffffffffu, p0, o);
                p1 += __shfl_xor_sync(0xffffffffu, p1, o);
                p2 += __shfl_xor_sync(0xffffffffu, p2, o);
                p3 += __shfl_xor_sync(0xffffffffu, p3, o);
            }
            if (lane == 0) {
                att[(hg * 4 + 0) * AS + j] = p0 * 0.25f;
                att[(hg * 4 + 1) * AS + j] = p1 * 0.25f;
                att[(hg * 4 + 2) * AS + j] = p2 * 0.25f;
                att[(hg * 4 + 3) * AS + j] = p3 * 0.25f;
            }
        }
    }
    __syncthreads();

    // ---- softmax: warp = head ------------------------------------------------
    {
        int h = warp;
        float v[4];
#pragma unroll
        for (int k = 0; k < 4; k++) {
            int j = lane + 32 * k;
            v[k] = (j < C1) ? att[h * AS + j] : -3.0e38f;
        }
        float m = fmaxf(fmaxf(v[0], v[1]), fmaxf(v[2], v[3]));
#pragma unroll
        for (int o = 16; o; o >>= 1) m = fmaxf(m, __shfl_xor_sync(0xffffffffu, m, o));
        float e[4], s = 0.f;
#pragma unroll
        for (int k = 0; k < 4; k++) {
            int j = lane + 32 * k;
            e[k] = (j < C1) ? expf(v[k] - m) : 0.f;
            s += e[k];
        }
#pragma unroll
        for (int o = 16; o; o >>= 1) s += __shfl_xor_sync(0xffffffffu, s, o);
        float inv = 1.0f / s;
#pragma unroll
        for (int k = 0; k < 4; k++) {
            int j = lane + 32 * k;
            if (j < C1) att[h * AS + j] = e[k] * inv;
        }
    }
    __syncthreads();

    // ---- wsum over COMPACTED list (masked attn == +0.0 exactly) ---------------
    unsigned long long A0 = 0ull, A1 = 0ull, A2 = 0ull, A3 = 0ull;
    {
        const unsigned long long* ce2 = (const unsigned long long*)ce;
        const float* a0 = att + (hg * 4 + 0) * AS;
        const float* a1 = att + (hg * 4 + 1) * AS;
        const float* a2 = att + (hg * 4 + 2) * AS;
        const float* a3 = att + (hg * 4 + 3) * AS;
        int idx = qq * 32 + lane;
        for (int ji = 0; ji < jcnt; ji++) {
            int j = jlst[ji];
            unsigned long long c = ce2[j * 128 + idx];
            fma2(A0, pack2(a0[j]), c);
            fma2(A1, pack2(a1[j]), c);
            fma2(A2, pack2(a2[j]), c);
            fma2(A3, pack2(a3[j]), c);
        }
    }
    __syncthreads();   // ce reads done; TAIL of region A reusable

    {
        int dbase = qq * 64 + lane * 2;
        U64F2 u0, u1, u2, u3;
        u0.u = A0; u1.u = A1; u2.u = A2; u3.u = A3;
        *(float2*)(w_s + (hg * 4 + 0) * WS + dbase) = u0.f;
        *(float2*)(w_s + (hg * 4 + 1) * WS + dbase) = u1.f;
        *(float2*)(w_s + (hg * 4 + 2) * WS + dbase) = u2.f;
        *(float2*)(w_s + (hg * 4 + 3) * WS + dbase) = u3.f;
    }
    __syncthreads();

    int c4 = t & 63, g = t >> 6;      // thread owns cols 4c4..4c4+3, d-group g
    int h4 = c4 >> 2;                 // head of those 4 columns

    // ---- gl[c] = sum_d Wv[d,c] * w[h(c)][d] ------------------------------------
    {
        const float4* wv4 = (const float4*)Wv;
        float4 acc = make_float4(0.f, 0.f, 0.f, 0.f);
        const float* wrow = w_s + h4 * WS;
        int d0 = g * 32;
#pragma unroll 8
        for (int i = 0; i < 32; i++) {
            int d = d0 + i;
            float4 wv = wv4[(size_t)d * 64 + c4];
            float wd = wrow[d];
            acc.x += wv.x * wd; acc.y += wv.y * wd;
            acc.z += wv.z * wd; acc.w += wv.w * wd;
        }
        ((float4*)scr)[g * 64 + c4] = acc;
    }
    __syncthreads();
    if (t < 256) {
        float s = 0.f;
#pragma unroll
        for (int gg = 0; gg < 8; gg++) s += scr[gg * 256 + t];
        gl[t] = s;
    }
    __syncthreads();

    // ---- tv[d] = sum_e M2T[e][d] * gl[e] ---------------------------------------
    {
        const float4* m4 = (const float4*)g_M2T;
        float4 acc = make_float4(0.f, 0.f, 0.f, 0.f);
        int e0 = g * 32;
#pragma unroll 8
        for (int i = 0; i < 32; i++) {
            int e = e0 + i;
            float4 wv = m4[(size_t)e * 64 + c4];
            float ge = gl[e];
            acc.x += wv.x * ge; acc.y += wv.y * ge;
            acc.z += wv.z * ge; acc.w += wv.w * ge;
        }
        ((float4*)scr)[g * 64 + c4] = acc;
    }
    __syncthreads();
    if (t < 256) {
        float s = 0.f;
#pragma unroll
        for (int gg = 0; gg < 8; gg++) s += scr[gg * 256 + t];
        tv[t] = s;
    }
    __syncthreads();

    // ---- logits over COMPACTED list; masked lg already NEGV --------------------
    {
        const float4* cg = (const float4*)(clus + (size_t)b * C1 * DD);
        const float4* tv4 = (const float4*)tv;
        float4 t0 = tv4[lane * 2], t1 = tv4[lane * 2 + 1];
        for (int ji = warp; ji < jcnt; ji += 16) {
            int j = jlst[ji];
            const float4* src = (j < SM_J_LIM) ? ce4 : cg;
            float4 c0 = src[j * 64 + lane * 2], c1 = src[j * 64 + lane * 2 + 1];
            float s = dot4(t0, c0) + dot4(t1, c1);
#pragma unroll
            for (int o = 16; o; o >>= 1) s += __shfl_xor_sync(0xffffffffu, s, o);
            if (lane == 0) lg[j] = tanhf(s * (1.0f / 16.0f)) * 10.0f;
        }
    }
    __syncthreads();

    // ---- log_softmax + argmax (warp 0) ----------------------------------------
    if (warp == 0) {
        float m = -3.0e38f; int mi = 0x7fffffff;
        for (int j = lane; j < C1; j += 32) {
            float v = lg[j];
            if (v > m) { m = v; mi = j; }
        }
#pragma unroll
        for (int o = 16; o; o >>= 1) {
            float om = __shfl_xor_sync(0xffffffffu, m, o);
            int   oi = __shfl_xor_sync(0xffffffffu, mi, o);
            if (om > m || (om == m && oi < mi)) { m = om; mi = oi; }
        }
        float s = 0.f;
        for (int j = lane; j < C1; j += 32) s += expf(lg[j] - m);
#pragma unroll
        for (int o = 16; o; o >>= 1) s += __shfl_xor_sync(0xffffffffu, s, o);
        if (lane == 0) { red[0] = m + logf(s); seli[0] = mi; }
    }
    __syncthreads();

    // ---- outputs (uvc reduced inline from node partials) ----------------------
    int sel = seli[0];
    float lse = red[0];
    size_t oa = (size_t)b * 1024;
    if (t < 256) {
        float se = clus[(size_t)b * C1 * DD + (size_t)sel * 256 + t];
        int cb = (BB + b) * 4;
        float s = g_part[(size_t)(cb + 0) * 256 + t] + g_part[(size_t)(cb + 1) * 256 + t]
                + g_part[(size_t)(cb + 2) * 256 + t] + g_part[(size_t)(cb + 3) * 256 + t];
        float den = fmaxf((float)(g_cnt[cb] + g_cnt[cb + 1] + g_cnt[cb + 2] + g_cnt[cb + 3]), 1.0f);
        out[oa + t]       = s / den;
        out[oa + 512 + t] = se;
        out[262144 + (size_t)b * 256 + t] = se;
    } else {
        int d = t - 256;
        out[oa + 256 + d] = cur[(size_t)b * DD + d];
        out[oa + 768 + d] = depot[(size_t)b * DD + d];
    }
    if (t == 0) out[327680 + b] = (float)sel;
    if (t < C1) out[327936 + (size_t)b * C1 + t] = lg[t] - lse;
}

extern "C" void kernel_launch(void* const* d_in, const int* in_sizes, int n_in,
                              void* d_out, int out_size) {
    const float* depot = (const float*)d_in[0];
    const float* clus  = (const float*)d_in[1];
    const float* cur   = (const float*)d_in[2];
    const float* node  = (const float*)d_in[3];
    const void*  mask  = d_in[4];
    const void*  cmask = d_in[5];
    const void*  vmask = d_in[6];
    const float* Wq    = (const float*)d_in[7];
    const float* Wk    = (const float*)d_in[8];
    const float* Wv    = (const float*)d_in[9];
    const float* Wks   = (const float*)d_in[10];
    const float* Wo    = (const float*)d_in[11];
    float* out = (float*)d_out;

    cudaFuncSetAttribute(k_qu_prep, cudaFuncAttributeMaxDynamicSharedMemorySize, QU_SMEM_BYTES);
    cudaFuncSetAttribute(k_main, cudaFuncAttributeMaxDynamicSharedMemorySize, SMEM_BYTES);

    k_nodes_part<<<dim3(4, BB), 256>>>(node, mask, cmask);

    cudaLaunchAttribute attr[1];
    attr[0].id = cudaLaunchAttributeProgrammaticStreamSerialization;
    attr[0].val.programmaticStreamSerializationAllowed = 1;

    {
        cudaLaunchConfig_t cfg = {};
        cfg.gridDim = dim3(320, 1, 1);
        cfg.blockDim = dim3(256, 1, 1);
        cfg.dynamicSmemBytes = QU_SMEM_BYTES;
        cfg.attrs = attr;
        cfg.numAttrs = 1;
        cudaLaunchKernelEx(&cfg, k_qu_prep, cur, depot, Wq, Wk, Wks, Wo);
    }
    {
        cudaLaunchConfig_t cfg = {};
        cfg.gridDim = dim3(BB, 1, 1);
        cfg.blockDim = dim3(512, 1, 1);
        cfg.dynamicSmemBytes = SMEM_BYTES;
        cfg.attrs = attr;
        cfg.numAttrs = 1;
        cudaLaunchKernelEx(&cfg, k_main, depot, clus, cur, vmask, mask, Wv, out);
    }
}

// round 17
// speedup vs baseline: 1.2848x; 1.0094x over previous
#include <cuda_runtime.h>
#include <math.h>
#include <stdint.h>

#define BB  256
#define NN  1024
#define C1  101
#define DD  256
#define HH  16
#define NEGV (-1000000000.0f)
#define AS  104
#define WS  260

__device__ __align__(16) float g_u[BB * HH * DD];
__device__ __align__(16) float g_M2T[DD * DD];
__device__ __align__(16) float g_part[2 * BB * 4 * DD];
__device__ int g_cnt[2 * BB * 4];
__device__ int g_syncA[32];
__device__ int g_syncB[32];

__device__ __forceinline__ bool readb(const void* p, int idx, int mode) {
    if (mode == 0) return ((const unsigned char*)p)[idx] != 0;
    if (mode == 1) return ((const int*)p)[idx] != 0;
    return ((const float*)p)[idx] != 0.0f;
}

__device__ __forceinline__ float dot4(float4 a, float4 b) {
    return a.x * b.x + a.y * b.y + a.z * b.z + a.w * b.w;
}

__device__ __forceinline__ unsigned long long pack2(float x) {
    unsigned long long r;
    asm("mov.b64 %0, {%1, %1};" : "=l"(r) : "f"(x));
    return r;
}
__device__ __forceinline__ void fma2(unsigned long long& acc, unsigned long long a,
                                     unsigned long long b) {
    asm("fma.rn.f32x2 %0, %1, %2, %0;" : "+l"(acc) : "l"(a), "l"(b));
}
union U64F2 { unsigned long long u; float2 f; };

// bool-dtype probe on first 4KB of `mask`. Call from ALL threads (sync-or).
__device__ __forceinline__ int detect_mode(const void* m, int t) {
    int f32 = 0, u8 = 0;
    if (t < 256) {
        uint4 v = ((const uint4*)m)[t];
        unsigned w[4] = {v.x, v.y, v.z, v.w};
#pragma unroll
        for (int i = 0; i < 4; i++) {
            unsigned x = w[i];
            if (((x >> 24) & 0xffu) == 0x3fu || ((x >> 16) & 0xffu) == 0x3fu ||
                ((x >> 8) & 0xffu) == 0x3fu || (x & 0xffu) == 0x3fu) f32 = 1;
            if (x & 0xffffff00u) u8 = 1;
        }
    }
    int a = __syncthreads_or(f32);
    int b = __syncthreads_or(u8);
    return a ? 2 : (b ? 0 : 1);
}

// ---------------- Front kernel: node CTAs [0,1024) + qu [1024,1280) + prep --
#define FRONT_SMEM 25664

__global__ void __launch_bounds__(256, 8) k_front(
    const float* __restrict__ node, const void* __restrict__ mask,
    const void* __restrict__ cmask,
    const float* __restrict__ cur,  const float* __restrict__ depot,
    const float* __restrict__ Wq,   const float* __restrict__ Wk,
    const float* __restrict__ Wks,  const float* __restrict__ Wo)
{
    extern __shared__ __align__(16) float sm[];
    int bx = blockIdx.x, t = threadIdx.x;
    int lane = t & 31, w = t >> 5;

    if (bx < 1024) {
        // ===================== node role =====================
        int* list0 = (int*)sm;                 // 256
        int* lcnt  = list0 + 256;
        float4* part = (float4*)(sm + 288);    // [2][4][64] = 512 float4

        int q = bx & 3, b = bx >> 2;
        int mode = detect_mode(mask, t);

        if (t == 0) *lcnt = 0;
        __syncthreads();

        int gidx = b * NN + q * 256 + t;
        bool m  = readb(mask,  gidx, mode);
        bool mc = m | readb(cmask, gidx, mode);
        if (!m) {
            int pos = atomicAdd(lcnt, 1);
            list0[pos] = t | ((mc ? 0 : 1) << 8);
        }
        int c0 = __syncthreads_count(!m);
        int c1 = __syncthreads_count(!mc);

        int chunk = t >> 6, d4 = t & 63;
        const float4* np4 = (const float4*)(node + (size_t)(b * NN + q * 256) * DD);
        float4 s0 = make_float4(0.f, 0.f, 0.f, 0.f), s1 = s0;

        int cnt = c0;
        int len4 = (cnt + 3) >> 2;
        int begin = chunk * len4;
        int end = begin + len4; if (end > cnt) end = cnt;

        int i = begin;
        for (; i + 8 <= end; i += 8) {
            int e[8];
            float4 v[8];
#pragma unroll
            for (int k = 0; k < 8; k++) e[k] = list0[i + k];
#pragma unroll
            for (int k = 0; k < 8; k++) v[k] = __ldcs(&np4[(size_t)(e[k] & 255) * 64 + d4]);
#pragma unroll
            for (int k = 0; k < 8; k++) {
                s0.x += v[k].x; s0.y += v[k].y; s0.z += v[k].z; s0.w += v[k].w;
                if (e[k] & 256) {
                    s1.x += v[k].x; s1.y += v[k].y; s1.z += v[k].z; s1.w += v[k].w;
                }
            }
        }
        for (; i < end; i++) {
            int e = list0[i];
            float4 v = __ldcs(&np4[(size_t)(e & 255) * 64 + d4]);
            s0.x += v.x; s0.y += v.y; s0.z += v.z; s0.w += v.w;
            if (e & 256) { s1.x += v.x; s1.y += v.y; s1.z += v.z; s1.w += v.w; }
        }

        part[(0 * 4 + chunk) * 64 + d4] = s0;
        part[(1 * 4 + chunk) * 64 + d4] = s1;
        __syncthreads();

        if (t < 128) {
            int which = t >> 6, d = t & 63;
            float4 r = make_float4(0.f, 0.f, 0.f, 0.f);
#pragma unroll
            for (int c = 0; c < 4; c++) {
                float4 a = part[(which * 4 + c) * 64 + d];
                r.x += a.x; r.y += a.y; r.z += a.z; r.w += a.w;
            }
            ((float4*)g_part)[((which * BB + b) * 4 + q) * 64 + d] = r;
        }
        if (t == 0) {
            g_cnt[(0 * BB + b) * 4 + q] = c0;
            g_cnt[(1 * BB + b) * 4 + q] = c1;
        }
        // publish to group counter (release: per-thread fence + barrier + atomic)
        __threadfence();
        __syncthreads();
        if (t == 0) atomicAdd(&g_syncA[bx >> 5], 1);
        cudaTriggerProgrammaticLaunchCompletion();
        return;
    }

    if (bx < 1280) {
        // ===================== qu role =====================
        int idx = bx - 1024;
        int cx = idx & 7;       // 32-col slice = 2 heads
        int by = idx >> 3;      // 8-batch group
        float* ctx = sm;                 // 8 x 768 floats
        float* q_s = sm + 6144;          // 8 x 32
        float* den = sm + 6400;          // 8
        float* qp  = sm;                 // alias (ctx dead when used)

        // pre-spin: load cur/depot rows of ctx
        for (int i = t; i < 2048; i += 256) {
            int bi = i >> 8, d = i & 255;
            int b = by * 8 + bi;
            ctx[bi * 768 + 256 + d] = cur[(size_t)b * DD + d];
            ctx[bi * 768 + 512 + d] = depot[(size_t)b * DD + d];
        }
        __syncthreads();

        int c = cx * 32 + lane;
        float acc[8];
#pragma unroll
        for (int bi = 0; bi < 8; bi++) acc[bi] = 0.f;
        {
            int k0 = 256 + w * 64;
            for (int k = k0; k < k0 + 64; k += 4) {
                float w0 = Wq[(size_t)(k + 0) * 256 + c];
                float w1 = Wq[(size_t)(k + 1) * 256 + c];
                float w2 = Wq[(size_t)(k + 2) * 256 + c];
                float w3 = Wq[(size_t)(k + 3) * 256 + c];
#pragma unroll
                for (int bi = 0; bi < 8; bi++) {
                    const float* cb = ctx + bi * 768;
                    acc[bi] += w0 * cb[k] + w1 * cb[k + 1]
                             + w2 * cb[k + 2] + w3 * cb[k + 3];
                }
            }
        }

        // spin until this group's 32 node CTAs have published
        if (t == 0) {
            while (atomicAdd(&g_syncA[by], 0) < 32) __nanosleep(64);
            __threadfence();   // acquire
        }
        __syncthreads();

        if (t < 8) {
            int b = by * 8 + t;
            int cc = g_cnt[b * 4 + 0] + g_cnt[b * 4 + 1] + g_cnt[b * 4 + 2] + g_cnt[b * 4 + 3];
            den[t] = fmaxf((float)cc, 1.0f);
        }
        __syncthreads();

        for (int i = t; i < 2048; i += 256) {
            int bi = i >> 8, d = i & 255;
            int b = by * 8 + bi;
            float s = g_part[(size_t)(b * 4 + 0) * 256 + d] + g_part[(size_t)(b * 4 + 1) * 256 + d]
                    + g_part[(size_t)(b * 4 + 2) * 256 + d] + g_part[(size_t)(b * 4 + 3) * 256 + d];
            ctx[bi * 768 + d] = s / den[bi];
        }
        __syncthreads();

        {
            int k1 = w * 32;
            for (int k = k1; k < k1 + 32; k += 4) {
                float w0 = Wq[(size_t)(k + 0) * 256 + c];
                float w1 = Wq[(size_t)(k + 1) * 256 + c];
                float w2 = Wq[(size_t)(k + 2) * 256 + c];
                float w3 = Wq[(size_t)(k + 3) * 256 + c];
#pragma unroll
                for (int bi = 0; bi < 8; bi++) {
                    const float* cb = ctx + bi * 768;
                    acc[bi] += w0 * cb[k] + w1 * cb[k + 1]
                             + w2 * cb[k + 2] + w3 * cb[k + 3];
                }
            }
        }
        __syncthreads();   // ctx reads done; qp may alias

#pragma unroll
        for (int bi = 0; bi < 8; bi++) qp[(w * 8 + bi) * 32 + lane] = acc[bi];
        __syncthreads();

        {
            int bi = w;
            float s = 0.f;
#pragma unroll
            for (int ww = 0; ww < 8; ww++) s += qp[(ww * 8 + bi) * 32 + lane];
            q_s[bi * 32 + lane] = s;
        }
        __syncthreads();

        int d = t;
        const float4* wk = (const float4*)(Wk + (size_t)d * 256 + cx * 32);
#pragma unroll
        for (int hl = 0; hl < 2; hl++) {
            float4 w0 = wk[hl * 4], w1 = wk[hl * 4 + 1], w2 = wk[hl * 4 + 2], w3 = wk[hl * 4 + 3];
#pragma unroll
            for (int bi = 0; bi < 8; bi++) {
                const float4* qv = (const float4*)(q_s + bi * 32 + hl * 16);
                float s = dot4(w0, qv[0]) + dot4(w1, qv[1]) + dot4(w2, qv[2]) + dot4(w3, qv[3]);
                g_u[(size_t)(by * 8 + bi) * (HH * DD) + (cx * 2 + hl) * 256 + d] = s;
            }
        }

        // group counter self-reset for graph replays (last of 8 qu CTAs)
        __syncthreads();
        if (t == 0) {
            if (atomicAdd(&g_syncB[by], 1) == 7) {
                g_syncA[by] = 0;
                g_syncB[by] = 0;
            }
        }
        cudaTriggerProgrammaticLaunchCompletion();
        return;
    }

    // ===================== prep role: M2T =====================
    {
        int tile = bx - 1280;
        int tj = tile & 7;    // d tile
        int ti = tile >> 3;   // e tile
        float* a_sh = sm;            // 32 x 65
        float* b_sh = sm + 2080;     // 32 x 65

        int el = t >> 3;
        int dl = (t & 7) * 4;
        float ac0 = 0.f, ac1 = 0.f, ac2 = 0.f, ac3 = 0.f;

        for (int kc = 0; kc < 4; kc++) {
            for (int i = t; i < 2048; i += 256) {
                int r = i >> 6, cc = i & 63;
                a_sh[r * 65 + cc] = Wks[(size_t)(tj * 32 + r) * 256 + kc * 64 + cc];
                b_sh[r * 65 + cc] = Wo [(size_t)(ti * 32 + r) * 256 + kc * 64 + cc];
            }
            __syncthreads();
            const float* br = b_sh + el * 65;
            const float* a0 = a_sh + (dl + 0) * 65;
            const float* a1 = a_sh + (dl + 1) * 65;
            const float* a2 = a_sh + (dl + 2) * 65;
            const float* a3 = a_sh + (dl + 3) * 65;
#pragma unroll 8
            for (int cc = 0; cc < 64; cc++) {
                float bv = br[cc];
                ac0 += a0[cc] * bv;
                ac1 += a1[cc] * bv;
                ac2 += a2[cc] * bv;
                ac3 += a3[cc] * bv;
            }
            __syncthreads();
        }
        *(float4*)(g_M2T + (size_t)(ti * 32 + el) * 256 + tj * 32 + dl) =
            make_float4(ac0, ac1, ac2, ac3);
        cudaTriggerProgrammaticLaunchCompletion();
    }
}

// SMEM layout (bytes). Region A holds ce; TAIL reused after wsum.
#define OFF_A    0
#define A_BYTES  (C1 * DD * 4)                  // 103424
#define A_W      76544
#define A_GL     (A_W + 16640)
#define A_TV     (A_GL + 1024)
#define A_SCR    (A_TV + 1024)
#define SM_J_LIM 74
#define OFF_ATT  A_BYTES
#define OFF_LG   (OFF_ATT + HH * AS * 4)
#define OFF_RED  (OFF_LG + 104 * 4)
#define OFF_VMI  (OFF_RED + 16)
#define OFF_SEL  (OFF_VMI + 104 * 4)
#define OFF_JL   (OFF_SEL + 16)
#define SMEM_BYTES (OFF_JL + 104 * 4 + 16)

// ---------------- Kernel 2: fused per-batch chain, occ 2 ---------------------
__global__ void __launch_bounds__(512, 2) k_main(
    const float* __restrict__ depot, const float* __restrict__ clus,
    const float* __restrict__ cur,   const void*  __restrict__ vmask,
    const void*  __restrict__ mask,
    const float* __restrict__ Wv,    float* __restrict__ out)
{
    extern __shared__ __align__(16) char smraw[];
    float* ce   = (float*)(smraw + OFF_A);
    float* w_s  = (float*)(smraw + A_W);
    float* gl   = (float*)(smraw + A_GL);
    float* tv   = (float*)(smraw + A_TV);
    float* scr  = (float*)(smraw + A_SCR);
    float* att  = (float*)(smraw + OFF_ATT);
    float* lg   = (float*)(smraw + OFF_LG);
    float* red  = (float*)(smraw + OFF_RED);
    int*   vmi  = (int*)(smraw + OFF_VMI);
    int*   seli = (int*)(smraw + OFF_SEL);
    int*   jlst = (int*)(smraw + OFF_JL);
    int*   jcntp = jlst + 104;

    int b = blockIdx.x, t = threadIdx.x;
    int lane = t & 31, warp = t >> 5;

    // pre-sync prologue: inputs only
    int mode = detect_mode(mask, t);
    {
        const float4* cg = (const float4*)(clus + (size_t)b * C1 * DD);
        float4* d4 = (float4*)ce;
        for (int i = t; i < C1 * DD / 4; i += 512) d4[i] = cg[i];
    }
    if (t < C1) vmi[t] = readb(vmask, b * C1 + t, mode) ? 1 : 0;
    __syncthreads();
    if (t == 0) {
        int all = 1;
        for (int j = 1; j < C1; j++) all &= vmi[j];
        vmi[0] = !all;
        int c = 0;
        for (int j = 0; j < C1; j++) if (!vmi[j]) jlst[c++] = j;
        *jcntp = c;
    }
    __syncthreads();
    if (t < C1 && vmi[t]) {
        lg[t] = NEGV;
#pragma unroll
        for (int h = 0; h < HH; h++) att[h * AS + t] = NEGV;
    }

    cudaGridDependencySynchronize();
    __syncthreads();

    int jcnt = *jcntp;
    const float4* ce4 = (const float4*)ce;
    int hg = warp & 3;
    int qq = warp >> 2;

    // ---- scores over compacted list -------------------------------------------
    {
        int jq = (jcnt + 3) >> 2;
        int jb = qq * jq;
        int je = jb + jq; if (je > jcnt) je = jcnt;
        const float4* up = (const float4*)(g_u + (size_t)b * (HH * DD));
        float4 ua[4], ub[4];
#pragma unroll
        for (int h = 0; h < 4; h++) {
            ua[h] = up[(hg * 4 + h) * 64 + lane * 2];
            ub[h] = up[(hg * 4 + h) * 64 + lane * 2 + 1];
        }
        for (int ji = jb; ji < je; ji++) {
            int j = jlst[ji];
            float4 c0 = ce4[j * 64 + lane * 2], c1 = ce4[j * 64 + lane * 2 + 1];
            float p0 = dot4(ua[0], c0) + dot4(ub[0], c1);
            float p1 = dot4(ua[1], c0) + dot4(ub[1], c1);
            float p2 = dot4(ua[2], c0) + dot4(ub[2], c1);
            float p3 = dot4(ua[3], c0) + dot4(ub[3], c1);
#pragma unroll
            for (int o = 16; o; o >>= 1) {
                p0 += __shfl_xor_sync(0xffffffffu, p0, o);
                p1 += __shfl_xor_sync(0xffffffffu, p1, o);
                p2 += __shfl_xor_sync(0xffffffffu, p2, o);
                p3 += __shfl_xor_sync(0xffffffffu, p3, o);
            }
            if (lane == 0) {
                att[(hg * 4 + 0) * AS + j] = p0 * 0.25f;
                att[(hg * 4 + 1) * AS + j] = p1 * 0.25f;
                att[(hg * 4 + 2) * AS + j] = p2 * 0.25f;
                att[(hg * 4 + 3) * AS + j] = p3 * 0.25f;
            }
        }
    }
    __syncthreads();

    // ---- softmax: warp = head ---------------------------------------------------
    {
        int h = warp;
        float v[4];
#pragma unroll
        for (int k = 0; k < 4; k++) {
            int j = lane + 32 * k;
            v[k] = (j < C1) ? att[h * AS + j] : -3.0e38f;
        }
        float m = fmaxf(fmaxf(v[0], v[1]), fmaxf(v[2], v[3]));
#pragma unroll
        for (int o = 16; o; o >>= 1) m = fmaxf(m, __shfl_xor_sync(0xffffffffu, m, o));
        float e[4], s = 0.f;
#pragma unroll
        for (int k = 0; k < 4; k++) {
            int j = lane + 32 * k;
            e[k] = (j < C1) ? expf(v[k] - m) : 0.f;
            s += e[k];
        }
#pragma unroll
        for (int o = 16; o; o >>= 1) s += __shfl_xor_sync(0xffffffffu, s, o);
        float inv = 1.0f / s;
#pragma unroll
        for (int k = 0; k < 4; k++) {
            int j = lane + 32 * k;
            if (j < C1) att[h * AS + j] = e[k] * inv;
        }
    }
    __syncthreads();

    // ---- wsum over compacted list ----------------------------------------------
    unsigned long long A0 = 0ull, A1 = 0ull, A2 = 0ull, A3 = 0ull;
    {
        const unsigned long long* ce2 = (const unsigned long long*)ce;
        const float* a0 = att + (hg * 4 + 0) * AS;
        const float* a1 = att + (hg * 4 + 1) * AS;
        const float* a2 = att + (hg * 4 + 2) * AS;
        const float* a3 = att + (hg * 4 + 3) * AS;
        int idx = qq * 32 + lane;
        for (int ji = 0; ji < jcnt; ji++) {
            int j = jlst[ji];
            unsigned long long c = ce2[j * 128 + idx];
            fma2(A0, pack2(a0[j]), c);
            fma2(A1, pack2(a1[j]), c);
            fma2(A2, pack2(a2[j]), c);
            fma2(A3, pack2(a3[j]), c);
        }
    }
    __syncthreads();

    {
        int dbase = qq * 64 + lane * 2;
        U64F2 u0, u1, u2, u3;
        u0.u = A0; u1.u = A1; u2.u = A2; u3.u = A3;
        *(float2*)(w_s + (hg * 4 + 0) * WS + dbase) = u0.f;
        *(float2*)(w_s + (hg * 4 + 1) * WS + dbase) = u1.f;
        *(float2*)(w_s + (hg * 4 + 2) * WS + dbase) = u2.f;
        *(float2*)(w_s + (hg * 4 + 3) * WS + dbase) = u3.f;
    }
    __syncthreads();

    int c4 = t & 63, g = t >> 6;
    int h4 = c4 >> 2;

    // ---- gl ----------------------------------------------------------------------
    {
        const float4* wv4 = (const float4*)Wv;
        float4 acc = make_float4(0.f, 0.f, 0.f, 0.f);
        const float* wrow = w_s + h4 * WS;
        int d0 = g * 32;
#pragma unroll 8
        for (int i = 0; i < 32; i++) {
            int d = d0 + i;
            float4 wv = wv4[(size_t)d * 64 + c4];
            float wd = wrow[d];
            acc.x += wv.x * wd; acc.y += wv.y * wd;
            acc.z += wv.z * wd; acc.w += wv.w * wd;
        }
        ((float4*)scr)[g * 64 + c4] = acc;
    }
    __syncthreads();
    if (t < 256) {
        float s = 0.f;
#pragma unroll
        for (int gg = 0; gg < 8; gg++) s += scr[gg * 256 + t];
        gl[t] = s;
    }
    __syncthreads();

    // ---- tv ----------------------------------------------------------------------
    {
        const float4* m4 = (const float4*)g_M2T;
        float4 acc = make_float4(0.f, 0.f, 0.f, 0.f);
        int e0 = g * 32;
#pragma unroll 8
        for (int i = 0; i < 32; i++) {
            int e = e0 + i;
            float4 wv = m4[(size_t)e * 64 + c4];
            float ge = gl[e];
            acc.x += wv.x * ge; acc.y += wv.y * ge;
            acc.z += wv.z * ge; acc.w += wv.w * ge;
        }
        ((float4*)scr)[g * 64 + c4] = acc;
    }
    __syncthreads();
    if (t < 256) {
        float s = 0.f;
#pragma unroll
        for (int gg = 0; gg < 8; gg++) s += scr[gg * 256 + t];
        tv[t] = s;
    }
    __syncthreads();

    // ---- logits over compacted list -----------------------------------------------
    {
        const float4* cg = (const float4*)(clus + (size_t)b * C1 * DD);
        const float4* tv4 = (const float4*)tv;
        float4 t0 = tv4[lane * 2], t1 = tv4[lane * 2 + 1];
        for (int ji = warp; ji < jcnt; ji += 16) {
            int j = jlst[ji];
            const float4* src = (j < SM_J_LIM) ? ce4 : cg;
            float4 c0 = src[j * 64 + lane * 2], c1 = src[j * 64 + lane * 2 + 1];
            float s = dot4(t0, c0) + dot4(t1, c1);
#pragma unroll
            for (int o = 16; o; o >>= 1) s += __shfl_xor_sync(0xffffffffu, s, o);
            if (lane == 0) lg[j] = tanhf(s * (1.0f / 16.0f)) * 10.0f;
        }
    }
    __syncthreads();

    // ---- log_softmax + argmax (warp 0) ---------------------------------------------
    if (warp == 0) {
        float m = -3.0e38f; int mi = 0x7fffffff;
        for (int j = lane; j < C1; j += 32) {
            float v = lg[j];
            if (v > m) { m = v; mi = j; }
        }
#pragma unroll
        for (int o = 16; o; o >>= 1) {
            float om = __shfl_xor_sync(0xffffffffu, m, o);
            int   oi = __shfl_xor_sync(0xffffffffu, mi, o);
            if (om > m || (om == m && oi < mi)) { m = om; mi = oi; }
        }
        float s = 0.f;
        for (int j = lane; j < C1; j += 32) s += expf(lg[j] - m);
#pragma unroll
        for (int o = 16; o; o >>= 1) s += __shfl_xor_sync(0xffffffffu, s, o);
        if (lane == 0) { red[0] = m + logf(s); seli[0] = mi; }
    }
    __syncthreads();

    // ---- outputs ---------------------------------------------------------------------
    int sel = seli[0];
    float lse = red[0];
    size_t oa = (size_t)b * 1024;
    if (t < 256) {
        float se = clus[(size_t)b * C1 * DD + (size_t)sel * 256 + t];
        int cb = (BB + b) * 4;
        float s = g_part[(size_t)(cb + 0) * 256 + t] + g_part[(size_t)(cb + 1) * 256 + t]
                + g_part[(size_t)(cb + 2) * 256 + t] + g_part[(size_t)(cb + 3) * 256 + t];
        float den = fmaxf((float)(g_cnt[cb] + g_cnt[cb + 1] + g_cnt[cb + 2] + g_cnt[cb + 3]), 1.0f);
        out[oa + t]       = s / den;
        out[oa + 512 + t] = se;
        out[262144 + (size_t)b * 256 + t] = se;
    } else {
        int d = t - 256;
        out[oa + 256 + d] = cur[(size_t)b * DD + d];
        out[oa + 768 + d] = depot[(size_t)b * DD + d];
    }
    if (t == 0) out[327680 + b] = (float)sel;
    if (t < C1) out[327936 + (size_t)b * C1 + t] = lg[t] - lse;
}

extern "C" void kernel_launch(void* const* d_in, const int* in_sizes, int n_in,
                              void* d_out, int out_size) {
    const float* depot = (const float*)d_in[0];
    const float* clus  = (const float*)d_in[1];
    const float* cur   = (const float*)d_in[2];
    const float* node  = (const float*)d_in[3];
    const void*  mask  = d_in[4];
    const void*  cmask = d_in[5];
    const void*  vmask = d_in[6];
    const float* Wq    = (const float*)d_in[7];
    const float* Wk    = (const float*)d_in[8];
    const float* Wv    = (const float*)d_in[9];
    const float* Wks   = (const float*)d_in[10];
    const float* Wo    = (const float*)d_in[11];
    float* out = (float*)d_out;

    cudaFuncSetAttribute(k_main, cudaFuncAttributeMaxDynamicSharedMemorySize, SMEM_BYTES);

    k_front<<<1344, 256, FRONT_SMEM>>>(node, mask, cmask, cur, depot, Wq, Wk, Wks, Wo);

    cudaLaunchAttribute attr[1];
    attr[0].id = cudaLaunchAttributeProgrammaticStreamSerialization;
    attr[0].val.programmaticStreamSerializationAllowed = 1;
    {
        cudaLaunchConfig_t cfg = {};
        cfg.gridDim = dim3(BB, 1, 1);
        cfg.blockDim = dim3(512, 1, 1);
        cfg.dynamicSmemBytes = SMEM_BYTES;
        cfg.attrs = attr;
        cfg.numAttrs = 1;
        cudaLaunchKernelEx(&cfg, k_main, depot, clus, cur, vmask, mask, Wv, out);
    }
}